// round 5
// baseline (speedup 1.0000x reference)
#include <cuda_runtime.h>
#include <cstdint>
#include <math.h>

#define S_   2048
#define H_   1024
#define NH_  16
#define KVH_ 4
#define HD_  64
#define E_   8
#define I_   4096

// ---------------- accurate math helpers ------------------
#ifdef __FAST_MATH__
__device__ __forceinline__ float acc_expf(float x) { return (float)exp((double)x); }
__device__ __forceinline__ float acc_cosf(float x) { return (float)cos((double)x); }
__device__ __forceinline__ float acc_sinf(float x) { return (float)sin((double)x); }
__device__ __forceinline__ float acc_powf(float a, float b) { return (float)pow((double)a, (double)b); }
#else
__device__ __forceinline__ float acc_expf(float x) { return expf(x); }
__device__ __forceinline__ float acc_cosf(float x) { return cosf(x); }
__device__ __forceinline__ float acc_sinf(float x) { return sinf(x); }
__device__ __forceinline__ float acc_powf(float a, float b) { return powf(a, b); }
#endif

__device__ __forceinline__ float tf32r(float x) {
    uint32_t u;
    asm("cvt.rna.tf32.f32 %0, %1;" : "=r"(u) : "f"(x));
    return __uint_as_float(u);
}
__device__ __forceinline__ uint32_t tf32u(float x) {
    uint32_t u;
    asm("cvt.rna.tf32.f32 %0, %1;" : "=r"(u) : "f"(x));
    return u;
}
__device__ __forceinline__ float4 tf32r4(float4 v) {
    v.x = tf32r(v.x); v.y = tf32r(v.y); v.z = tf32r(v.z); v.w = tf32r(v.w);
    return v;
}
__device__ __forceinline__ float silu_f(float v) {
    return __fdiv_rn(v, 1.0f + acc_expf(-v));
}

__device__ __forceinline__ uint32_t s2u(const void* p) {
    return (uint32_t)__cvta_generic_to_shared(p);
}
__device__ __forceinline__ void cp16(uint32_t dst, const float* src) {
    asm volatile("cp.async.ca.shared.global [%0], [%1], 16;\n" :: "r"(dst), "l"(src));
}
__device__ __forceinline__ void cp_commit() {
    asm volatile("cp.async.commit_group;\n" ::);
}
__device__ __forceinline__ void cp_wait1() {
    asm volatile("cp.async.wait_group 1;\n" ::);
}

// ---------------- scratch ----------------
__device__ float g_x1[S_*H_];
__device__ float g_q[S_*H_];
__device__ float g_k[S_*KVH_*HD_];
__device__ float g_v[S_*KVH_*HD_];
__device__ float g_att[S_*H_];
__device__ float g_hidden[S_*H_];
__device__ float g_x2[S_*H_];
__device__ float g_hs[S_*I_];
__device__ float g_hcol[(S_*2)*I_];
__device__ float g_eo[(S_*2)*H_];
__device__ float g_sc[(size_t)NH_*S_*S_];  // score/e cache: [(h*16+qt)][j][qlocal]
__device__ int   g_cnt[E_];
__device__ int   g_list[E_*S_];
__device__ float g_wts[S_*2];

// ---------------- TF32 tensor-core GEMM, 3-stage cp.async ----------------
#define BM  128
#define BN  128
#define BKT 16
#define NST 3
#define ASTR 20
#define BSTR 136
#define SMEM_GEMM ((NST*BM*ASTR + NST*BKT*BSTR) * 4)

template<int EPI, int GATHER, int SHIFT, int QKV>
__global__ void __launch_bounds__(256, 2) mma_gemm_k(
    const float* __restrict__ A, const float* __restrict__ B,
    float* __restrict__ C, const float* __restrict__ R,
    const int* __restrict__ list, const int* __restrict__ cnt,
    const float* __restrict__ B2, const float* __restrict__ B3,
    float* __restrict__ C2, float* __restrict__ C3,
    int N, int K)
{
    extern __shared__ float dsm[];
    float* As = dsm;
    float* Bs = dsm + NST * BM * ASTR;

    int n_rows = S_;
    const float* Bz = B;
    float* Cz = C;
    int zoff = 0;
    int Nl = N;
    int n0 = blockIdx.x * BN;
    if (GATHER) {
        const int z = blockIdx.z;
        n_rows = cnt[z];
        if ((int)blockIdx.y * BM >= n_rows) return;
        zoff = z * S_;
        Bz = B + (size_t)z * K * N;
    }
    if (QKV) {
        const int bx = blockIdx.x;
        if (bx < 8)       { Bz = B;  Cz = C;  Nl = 1024; n0 = bx * BN; }
        else if (bx < 10) { Bz = B2; Cz = C2; Nl = 256;  n0 = (bx - 8) * BN; }
        else              { Bz = B3; Cz = C3; Nl = 256;  n0 = (bx - 10) * BN; }
    }

    const int tid  = threadIdx.x;
    const int lane = tid & 31;
    const int wid  = tid >> 5;
    const int wm   = (wid & 1) * 64;
    const int wn   = (wid >> 1) * 32;
    const int m0   = blockIdx.y * BM;

    const int aIdx0 = tid, aIdx1 = tid + 256;
    const int r0 = m0 + (aIdx0 >> 2), r1 = m0 + (aIdx1 >> 2);
    int gar0 = r0, gar1 = r1;
    if (GATHER) {
        gar0 = (r0 < n_rows) ? (list[zoff + r0] >> SHIFT) : 0;
        gar1 = (r1 < n_rows) ? (list[zoff + r1] >> SHIFT) : 0;
    }
    const float* Ag0 = A + (size_t)gar0 * K + (aIdx0 & 3) * 4;
    const float* Ag1 = A + (size_t)gar1 * K + (aIdx1 & 3) * 4;
    const float* Bg0 = Bz + (size_t)(tid >> 5) * Nl + n0 + (tid & 31) * 4;
    const float* Bg1 = Bg0 + (size_t)8 * Nl;

    const uint32_t sa0 = s2u(&As[(size_t)(aIdx0 >> 2) * ASTR + (aIdx0 & 3) * 4]);
    const uint32_t sa1 = s2u(&As[(size_t)(aIdx1 >> 2) * ASTR + (aIdx1 & 3) * 4]);
    const uint32_t sb0 = s2u(&Bs[(size_t)(tid >> 5) * BSTR + (tid & 31) * 4]);
    const uint32_t sb1 = s2u(&Bs[(size_t)((tid >> 5) + 8) * BSTR + (tid & 31) * 4]);
    const uint32_t aStgB = BM * ASTR * 4;
    const uint32_t bStgB = BKT * BSTR * 4;

    float acc[4][4][4] = {};
    const int nk = K / BKT;

    auto load_stage = [&](int sbuf, int c) {
        const int k0 = c * BKT;
        cp16(sa0 + sbuf * aStgB, Ag0 + k0);
        cp16(sa1 + sbuf * aStgB, Ag1 + k0);
        cp16(sb0 + sbuf * bStgB, Bg0 + (size_t)k0 * Nl);
        cp16(sb1 + sbuf * bStgB, Bg1 + (size_t)k0 * Nl);
        cp_commit();
    };

    load_stage(0, 0);
    load_stage(1, 1);

    for (int c = 0; c < nk; c++) {
        cp_wait1();
        __syncthreads();
        const int buf = c % NST;
        if (c + NST - 1 < nk) load_stage((c + NST - 1) % NST, c + NST - 1);

        const float* Ab = As + (size_t)buf * BM * ASTR;
        const float* Bb = Bs + (size_t)buf * BKT * BSTR;
        #pragma unroll
        for (int ks = 0; ks < 2; ks++) {
            const int kk = ks * 8 + (lane & 3);
            uint32_t a[4][4], b[4][2];
            #pragma unroll
            for (int mt = 0; mt < 4; mt++) {
                const int m = wm + mt * 16 + (lane >> 2);
                a[mt][0] = tf32u(Ab[(size_t)m * ASTR + kk]);
                a[mt][1] = tf32u(Ab[(size_t)(m + 8) * ASTR + kk]);
                a[mt][2] = tf32u(Ab[(size_t)m * ASTR + kk + 4]);
                a[mt][3] = tf32u(Ab[(size_t)(m + 8) * ASTR + kk + 4]);
            }
            #pragma unroll
            for (int nt = 0; nt < 4; nt++) {
                const int nn = wn + nt * 8 + (lane >> 2);
                b[nt][0] = tf32u(Bb[(size_t)kk * BSTR + nn]);
                b[nt][1] = tf32u(Bb[(size_t)(kk + 4) * BSTR + nn]);
            }
            #pragma unroll
            for (int mt = 0; mt < 4; mt++)
                #pragma unroll
                for (int nt = 0; nt < 4; nt++)
                    asm volatile(
                        "mma.sync.aligned.m16n8k8.row.col.f32.tf32.tf32.f32 "
                        "{%0,%1,%2,%3}, {%4,%5,%6,%7}, {%8,%9}, {%0,%1,%2,%3};"
                        : "+f"(acc[mt][nt][0]), "+f"(acc[mt][nt][1]),
                          "+f"(acc[mt][nt][2]), "+f"(acc[mt][nt][3])
                        : "r"(a[mt][0]), "r"(a[mt][1]), "r"(a[mt][2]), "r"(a[mt][3]),
                          "r"(b[nt][0]), "r"(b[nt][1]));
        }
    }

    #pragma unroll
    for (int mt = 0; mt < 4; mt++) {
        #pragma unroll
        for (int half = 0; half < 2; half++) {
            const int r = m0 + wm + mt * 16 + (lane >> 2) + half * 8;
            if (GATHER && r >= n_rows) continue;
            size_t crow_idx = r;
            if (GATHER) crow_idx = (size_t)list[zoff + r];
            float* crow = Cz + crow_idx * Nl;
            #pragma unroll
            for (int nt = 0; nt < 4; nt++) {
                const int col = n0 + wn + nt * 8 + (lane & 3) * 2;
                float2 v;
                v.x = acc[mt][nt][half * 2 + 0];
                v.y = acc[mt][nt][half * 2 + 1];
                if (EPI == 1) {
                    v.x = silu_f(v.x); v.y = silu_f(v.y);
                } else if (EPI == 2) {
                    const float2 rr = *(const float2*)(R + crow_idx * Nl + col);
                    v.x += rr.x; v.y += rr.y;
                }
                *(float2*)(crow + col) = v;
            }
        }
    }
}

// ---------------- RMSNorm ----------------
__global__ void rmsnorm_k(const float* __restrict__ x, const float* __restrict__ w,
                          float* __restrict__ o)
{
    const int t = blockIdx.x;
    const int tid = threadIdx.x;
    const float* xr = x + (size_t)t * H_;
    float s = 0.f;
    for (int i = tid; i < H_; i += 256) { float v = xr[i]; s = __fmaf_rn(v, v, s); }
    for (int off = 16; off; off >>= 1) s += __shfl_down_sync(0xffffffffu, s, off);
    __shared__ float red[8];
    const int wid = tid >> 5, lane = tid & 31;
    if (!lane) red[wid] = s;
    __syncthreads();
    if (tid == 0) {
        float tot = 0.f;
        #pragma unroll
        for (int i = 0; i < 8; i++) tot += red[i];
        red[0] = rsqrtf(tot * (1.0f / H_) + 1e-6f);
    }
    __syncthreads();
    const float r = red[0];
    float* orow = o + (size_t)t * H_;
    for (int i = tid; i < H_; i += 256) orow[i] = w[i] * (xr[i] * r);
}

// ---------------- RoPE ----------------
__global__ void rope_k(float* __restrict__ q, float* __restrict__ k)
{
    const int idx = blockIdx.x * blockDim.x + threadIdx.x;
    const int half = idx & 31;
    const int rest = idx >> 5;
    const int head = rest % (NH_ + KVH_);
    const int t = rest / (NH_ + KVH_);
    const float inv_freq = __fdiv_rn(1.0f, acc_powf(10000.0f, (float)half * 0.03125f));
    const float ang = __fmul_rn((float)t, inv_freq);
    const float c = acc_cosf(ang);
    const float sn = acc_sinf(ang);
    float* base = (head < NH_) ? (q + (size_t)t * H_ + head * HD_)
                               : (k + (size_t)t * (KVH_ * HD_) + (head - NH_) * HD_);
    const float x1 = base[half];
    const float x2 = base[half + 32];
    base[half]      = __fadd_rn(__fmul_rn(x1, c), -__fmul_rn(x2, sn));
    base[half + 32] = __fadd_rn(__fmul_rn(x2, c),  __fmul_rn(x1, sn));
}

// ---------------- Attention: 3-phase MMA (two-pass softmax preserved) ---------
#define AQ 128
#define AK 64
#define QSTR 68
// dyn smem: Qs[128*68] KV[64*68] SP[128*68] mbuf[256] lbuf[256] mfin[128] lfin[128]
#define SMEM_ATTN ((AQ*QSTR + AK*QSTR + AQ*QSTR + 256 + 256 + AQ + AQ) * 4)

__global__ void __launch_bounds__(256, 2) attn_mma_k(
    const float* __restrict__ q, const float* __restrict__ k,
    const float* __restrict__ v, float* __restrict__ o,
    float* __restrict__ sc)
{
    extern __shared__ float sm[];
    float* Qs   = sm;
    float* KV   = Qs + AQ * QSTR;
    float* SP   = KV + AK * QSTR;
    float* mbuf = SP + AQ * QSTR;
    float* lbuf = mbuf + 256;
    float* mfin = lbuf + 256;
    float* lfin = mfin + AQ;

    const int h  = blockIdx.y;
    const int qt = (int)gridDim.x - 1 - (int)blockIdx.x;   // heavy tiles first
    const int q0 = qt * AQ;
    const int tid = threadIdx.x;
    const int lane = tid & 31, wid = tid >> 5;
    const int kvh = h >> 2;
    float* scB = sc + (size_t)(h * 16 + qt) * S_ * 128;    // [j][qlocal]

    const int myq = tid & 127, jh = tid >> 7;
    const int qi = q0 + myq;
    const int ntiles = (q0 + AQ) / AK;

    // load Q tile (tf32)
    for (int i = tid; i < AQ * (HD_ / 4); i += 256) {
        const int qq = i >> 4, d4 = (i & 15) * 4;
        *(float4*)&Qs[qq * QSTR + d4] =
            tf32r4(*(const float4*)(q + (size_t)(q0 + qq) * H_ + h * HD_ + d4));
    }

    const int wmS = (wid & 3) * 32, wnS = (wid >> 2) * 32;
    float mreg = -1e30f;

    // ---- phase A: S = Q K^T via MMA, cache scores, row max ----
    for (int t = 0; t < ntiles; t++) {
        const int k0 = t * AK;
        __syncthreads();
        for (int i = tid; i < AK * (HD_ / 4); i += 256) {
            const int j = i >> 4, d4 = (i & 15) * 4;
            *(float4*)&KV[j * QSTR + d4] =
                tf32r4(*(const float4*)(k + (size_t)(k0 + j) * (KVH_ * HD_) + kvh * HD_ + d4));
        }
        __syncthreads();

        float accS[2][4][4] = {};
        #pragma unroll
        for (int ks = 0; ks < 8; ks++) {
            const int kk = ks * 8 + (lane & 3);
            uint32_t a[2][4], b[4][2];
            #pragma unroll
            for (int mt = 0; mt < 2; mt++) {
                const int r = wmS + mt * 16 + (lane >> 2);
                a[mt][0] = __float_as_uint(Qs[r * QSTR + kk]);
                a[mt][1] = __float_as_uint(Qs[(r + 8) * QSTR + kk]);
                a[mt][2] = __float_as_uint(Qs[r * QSTR + kk + 4]);
                a[mt][3] = __float_as_uint(Qs[(r + 8) * QSTR + kk + 4]);
            }
            #pragma unroll
            for (int nt = 0; nt < 4; nt++) {
                const int j = wnS + nt * 8 + (lane >> 2);
                b[nt][0] = __float_as_uint(KV[j * QSTR + kk]);
                b[nt][1] = __float_as_uint(KV[j * QSTR + kk + 4]);
            }
            #pragma unroll
            for (int mt = 0; mt < 2; mt++)
                #pragma unroll
                for (int nt = 0; nt < 4; nt++)
                    asm volatile(
                        "mma.sync.aligned.m16n8k8.row.col.f32.tf32.tf32.f32 "
                        "{%0,%1,%2,%3}, {%4,%5,%6,%7}, {%8,%9}, {%0,%1,%2,%3};"
                        : "+f"(accS[mt][nt][0]), "+f"(accS[mt][nt][1]),
                          "+f"(accS[mt][nt][2]), "+f"(accS[mt][nt][3])
                        : "r"(a[mt][0]), "r"(a[mt][1]), "r"(a[mt][2]), "r"(a[mt][3]),
                          "r"(b[nt][0]), "r"(b[nt][1]));
        }
        // scaled scores -> SP [q][j]
        #pragma unroll
        for (int mt = 0; mt < 2; mt++)
            #pragma unroll
            for (int half = 0; half < 2; half++) {
                const int row = wmS + mt * 16 + (lane >> 2) + half * 8;
                #pragma unroll
                for (int nt = 0; nt < 4; nt++) {
                    const int col = wnS + nt * 8 + (lane & 3) * 2;
                    SP[row * QSTR + col]     = accS[mt][nt][half * 2 + 0] * 0.125f;
                    SP[row * QSTR + col + 1] = accS[mt][nt][half * 2 + 1] * 0.125f;
                }
            }
        __syncthreads();
        // copy to gmem cache (coalesced) + per-half row max
        for (int i = tid; i < AK * AQ; i += 256) {
            const int j = i >> 7, qq = i & 127;
            scB[(size_t)(k0 + j) * 128 + qq] = SP[qq * QSTR + j];
        }
        float mp = -1e30f;
        const int jlim = min(AK, qi - k0 + 1);
        const int jend = min(jlim, jh * 32 + 32);
        for (int jj = jh * 32; jj < jend; jj++)
            mp = fmaxf(mp, SP[myq * QSTR + jj]);
        mbuf[tid] = mp;
        __syncthreads();
        if (tid < 128) mreg = fmaxf(mreg, fmaxf(mbuf[tid], mbuf[tid + 128]));
    }

    // ---- phase B: e = exp(s - m), l = sum e, write e back ----
    if (tid < 128) mfin[tid] = mreg;
    __syncthreads();
    {
        const float mq = mfin[myq];
        float lp = 0.f;
        for (int t = 0; t < ntiles; t++) {
            const int k0 = t * AK;
            const int jlim = min(AK, qi - k0 + 1);
            const int jend = min(jlim, jh * 32 + 32);
            for (int jj = jh * 32; jj < jend; jj++) {
                const size_t idx = (size_t)(k0 + jj) * 128 + myq;
                const float e = acc_expf(scB[idx] - mq);
                lp += e;
                scB[idx] = e;
            }
        }
        lbuf[tid] = lp;
    }
    __syncthreads();
    if (tid < 128) lfin[tid] = lbuf[tid] + lbuf[tid + 128];

    // ---- phase C: p = tf32(e / l); O += P V via MMA ----
    float accO[2][4][4] = {};
    const int wmO = (wid & 3) * 32, wnO = (wid >> 2) * 32;
    for (int t = 0; t < ntiles; t++) {
        const int k0 = t * AK;
        __syncthreads();
        for (int i = tid; i < AK * (HD_ / 4); i += 256) {
            const int j = i >> 4, d4 = (i & 15) * 4;
            *(float4*)&KV[j * QSTR + d4] =
                tf32r4(*(const float4*)(v + (size_t)(k0 + j) * (KVH_ * HD_) + kvh * HD_ + d4));
        }
        for (int i = tid; i < AK * AQ; i += 256) {
            const int j = i >> 7, qq = i & 127;
            float p = 0.f;
            if (k0 + j <= q0 + qq)
                p = tf32r(__fdiv_rn(scB[(size_t)(k0 + j) * 128 + qq], lfin[qq]));
            SP[qq * QSTR + j] = p;
        }
        __syncthreads();
        #pragma unroll
        for (int ks = 0; ks < 8; ks++) {
            const int kk = ks * 8 + (lane & 3);
            uint32_t a[2][4], b[4][2];
            #pragma unroll
            for (int mt = 0; mt < 2; mt++) {
                const int r = wmO + mt * 16 + (lane >> 2);
                a[mt][0] = __float_as_uint(SP[r * QSTR + kk]);
                a[mt][1] = __float_as_uint(SP[(r + 8) * QSTR + kk]);
                a[mt][2] = __float_as_uint(SP[r * QSTR + kk + 4]);
                a[mt][3] = __float_as_uint(SP[(r + 8) * QSTR + kk + 4]);
            }
            #pragma unroll
            for (int nt = 0; nt < 4; nt++) {
                const int d = wnO + nt * 8 + (lane >> 2);
                b[nt][0] = __float_as_uint(KV[kk * QSTR + d]);
                b[nt][1] = __float_as_uint(KV[(kk + 4) * QSTR + d]);
            }
            #pragma unroll
            for (int mt = 0; mt < 2; mt++)
                #pragma unroll
                for (int nt = 0; nt < 4; nt++)
                    asm volatile(
                        "mma.sync.aligned.m16n8k8.row.col.f32.tf32.tf32.f32 "
                        "{%0,%1,%2,%3}, {%4,%5,%6,%7}, {%8,%9}, {%0,%1,%2,%3};"
                        : "+f"(accO[mt][nt][0]), "+f"(accO[mt][nt][1]),
                          "+f"(accO[mt][nt][2]), "+f"(accO[mt][nt][3])
                        : "r"(a[mt][0]), "r"(a[mt][1]), "r"(a[mt][2]), "r"(a[mt][3]),
                          "r"(b[nt][0]), "r"(b[nt][1]));
        }
    }

    // write O
    #pragma unroll
    for (int mt = 0; mt < 2; mt++)
        #pragma unroll
        for (int half = 0; half < 2; half++) {
            const int row = q0 + wmO + mt * 16 + (lane >> 2) + half * 8;
            #pragma unroll
            for (int nt = 0; nt < 4; nt++) {
                const int col = wnO + nt * 8 + (lane & 3) * 2;
                float2 r2;
                r2.x = accO[mt][nt][half * 2 + 0];
                r2.y = accO[mt][nt][half * 2 + 1];
                *(float2*)(o + (size_t)row * H_ + h * HD_ + col) = r2;
            }
        }
}

// ---------------- router ----------------
__global__ void zero_k(int* __restrict__ c)
{
    if (threadIdx.x < E_) c[threadIdx.x] = 0;
}

__global__ void router_k(const float* __restrict__ x, const float* __restrict__ rw,
                         int* __restrict__ cnt, int* __restrict__ list,
                         float* __restrict__ wout)
{
    const int t = blockIdx.x;
    const int tid = threadIdx.x;
    const int e = tid >> 5, lane = tid & 31;
    const float* xr = x + (size_t)t * H_;
    float s = 0.f;
    for (int i = lane; i < H_; i += 32)
        s = __fmaf_rn(tf32r(xr[i]), tf32r(rw[i * E_ + e]), s);
    for (int off = 16; off; off >>= 1) s += __shfl_down_sync(0xffffffffu, s, off);
    __shared__ float logit[E_];
    if (!lane) logit[e] = s;
    __syncthreads();
    if (tid == 0) {
        float mx = logit[0];
        #pragma unroll
        for (int i = 1; i < E_; i++) mx = fmaxf(mx, logit[i]);
        float p[E_];
        #pragma unroll
        for (int i = 0; i < E_; i++) p[i] = acc_expf(logit[i] - mx);
        int i0 = 0;
        #pragma unroll
        for (int i = 1; i < E_; i++) if (p[i] > p[i0]) i0 = i;
        int i1 = (i0 == 0) ? 1 : 0;
        #pragma unroll
        for (int i = 0; i < E_; i++) if (i != i0 && p[i] > p[i1]) i1 = i;
        const float denom = p[i0] + p[i1];
        wout[2 * t + 0] = __fdiv_rn(p[i0], denom);
        wout[2 * t + 1] = __fdiv_rn(p[i1], denom);
        int pos = atomicAdd(&cnt[i0], 1);
        list[i0 * S_ + pos] = 2 * t;
        pos = atomicAdd(&cnt[i1], 1);
        list[i1 * S_ + pos] = 2 * t + 1;
    }
}

// ---------------- combine ----------------
__global__ void combine_k(float* __restrict__ out, const float* __restrict__ eo,
                          const float* __restrict__ w)
{
    const int t = blockIdx.x;
    const float w0 = w[2 * t], w1 = w[2 * t + 1];
    const float* e0 = eo + (size_t)(2 * t) * H_;
    const float* e1 = eo + (size_t)(2 * t + 1) * H_;
    float* orow = out + (size_t)t * H_;
    for (int i = threadIdx.x; i < H_; i += 256)
        orow[i] += __fmaf_rn(w0, e0[i], __fmul_rn(w1, e1[i]));
}

// ---------------- host launch --------------------------------------------------
extern "C" void kernel_launch(void* const* d_in, const int* in_sizes, int n_in,
                              void* d_out, int out_size)
{
    const float* hs  = (const float*)d_in[0];
    const float* ln1 = (const float*)d_in[1];
    const float* wq  = (const float*)d_in[2];
    const float* wk  = (const float*)d_in[3];
    const float* wv  = (const float*)d_in[4];
    const float* wo  = (const float*)d_in[5];
    const float* ln2 = (const float*)d_in[6];
    const float* sw1 = (const float*)d_in[7];
    const float* sw2 = (const float*)d_in[8];
    const float* ew1 = (const float*)d_in[9];
    const float* ew2 = (const float*)d_in[10];
    const float* rw  = (const float*)d_in[11];
    float* out = (float*)d_out;

    float *x1, *q, *k, *v, *att, *hid, *x2, *hsv, *hcol, *eo, *wts, *sc;
    int *cnt, *list;
    cudaGetSymbolAddress((void**)&x1,   g_x1);
    cudaGetSymbolAddress((void**)&q,    g_q);
    cudaGetSymbolAddress((void**)&k,    g_k);
    cudaGetSymbolAddress((void**)&v,    g_v);
    cudaGetSymbolAddress((void**)&att,  g_att);
    cudaGetSymbolAddress((void**)&hid,  g_hidden);
    cudaGetSymbolAddress((void**)&x2,   g_x2);
    cudaGetSymbolAddress((void**)&hsv,  g_hs);
    cudaGetSymbolAddress((void**)&hcol, g_hcol);
    cudaGetSymbolAddress((void**)&eo,   g_eo);
    cudaGetSymbolAddress((void**)&wts,  g_wts);
    cudaGetSymbolAddress((void**)&sc,   g_sc);
    cudaGetSymbolAddress((void**)&cnt,  g_cnt);
    cudaGetSymbolAddress((void**)&list, g_list);

    cudaFuncSetAttribute(mma_gemm_k<0,0,0,1>, cudaFuncAttributeMaxDynamicSharedMemorySize, SMEM_GEMM);
    cudaFuncSetAttribute(mma_gemm_k<2,0,0,0>, cudaFuncAttributeMaxDynamicSharedMemorySize, SMEM_GEMM);
    cudaFuncSetAttribute(mma_gemm_k<1,0,0,0>, cudaFuncAttributeMaxDynamicSharedMemorySize, SMEM_GEMM);
    cudaFuncSetAttribute(mma_gemm_k<1,1,1,0>, cudaFuncAttributeMaxDynamicSharedMemorySize, SMEM_GEMM);
    cudaFuncSetAttribute(mma_gemm_k<0,1,0,0>, cudaFuncAttributeMaxDynamicSharedMemorySize, SMEM_GEMM);
    cudaFuncSetAttribute(attn_mma_k, cudaFuncAttributeMaxDynamicSharedMemorySize, SMEM_ATTN);

    // 1. rmsnorm1
    rmsnorm_k<<<S_, 256>>>(hs, ln1, x1);
    // 2. fused QKV projection
    mma_gemm_k<0,0,0,1><<<dim3(12, S_ / BM), 256, SMEM_GEMM>>>(
        x1, wq, q, nullptr, nullptr, nullptr, wk, wv, k, v, H_, H_);
    // 3. RoPE
    rope_k<<<(S_ * (NH_ + KVH_) * 32) / 256, 256>>>(q, k);
    // 4. attention (3-phase MMA)
    attn_mma_k<<<dim3(S_ / AQ, NH_), 256, SMEM_ATTN>>>(q, k, v, att, sc);
    // 5. O-proj + residual
    mma_gemm_k<2,0,0,0><<<dim3(H_ / BN, S_ / BM), 256, SMEM_GEMM>>>(
        att, wo, hid, hs, nullptr, nullptr, nullptr, nullptr, nullptr, nullptr, H_, H_);
    // 6. rmsnorm2
    rmsnorm_k<<<S_, 256>>>(hid, ln2, x2);
    // 7. router
    zero_k<<<1, 32>>>(cnt);
    router_k<<<S_, 256>>>(x2, rw, cnt, list, wts);
    // 8. shared MLP
    mma_gemm_k<1,0,0,0><<<dim3(I_ / BN, S_ / BM), 256, SMEM_GEMM>>>(
        x2, sw1, hsv, nullptr, nullptr, nullptr, nullptr, nullptr, nullptr, nullptr, I_, H_);
    mma_gemm_k<2,0,0,0><<<dim3(H_ / BN, S_ / BM), 256, SMEM_GEMM>>>(
        hsv, sw2, out, hid, nullptr, nullptr, nullptr, nullptr, nullptr, nullptr, H_, I_);
    // 9. gathered expert MLPs (top-2 only)
    mma_gemm_k<1,1,1,0><<<dim3(I_ / BN, S_ / BM, E_), 256, SMEM_GEMM>>>(
        x2, ew1, hcol, nullptr, list, cnt, nullptr, nullptr, nullptr, nullptr, I_, H_);
    mma_gemm_k<0,1,0,0><<<dim3(H_ / BN, S_ / BM, E_), 256, SMEM_GEMM>>>(
        hcol, ew2, eo, nullptr, list, cnt, nullptr, nullptr, nullptr, nullptr, H_, I_);
    // 10. combine
    combine_k<<<S_, 256>>>(out, eo, wts);
}

// round 6
// speedup vs baseline: 1.5670x; 1.5670x over previous
#include <cuda_runtime.h>
#include <cstdint>
#include <math.h>

#define S_   2048
#define H_   1024
#define NH_  16
#define KVH_ 4
#define HD_  64
#define E_   8
#define I_   4096

// ---------------- accurate math helpers ------------------
#ifdef __FAST_MATH__
__device__ __forceinline__ float acc_expf(float x) { return (float)exp((double)x); }
__device__ __forceinline__ float acc_cosf(float x) { return (float)cos((double)x); }
__device__ __forceinline__ float acc_sinf(float x) { return (float)sin((double)x); }
__device__ __forceinline__ float acc_powf(float a, float b) { return (float)pow((double)a, (double)b); }
#else
__device__ __forceinline__ float acc_expf(float x) { return expf(x); }
__device__ __forceinline__ float acc_cosf(float x) { return cosf(x); }
__device__ __forceinline__ float acc_sinf(float x) { return sinf(x); }
__device__ __forceinline__ float acc_powf(float a, float b) { return powf(a, b); }
#endif

__device__ __forceinline__ float tf32r(float x) {
    uint32_t u;
    asm("cvt.rna.tf32.f32 %0, %1;" : "=r"(u) : "f"(x));
    return __uint_as_float(u);
}
__device__ __forceinline__ uint32_t tf32u(float x) {
    uint32_t u;
    asm("cvt.rna.tf32.f32 %0, %1;" : "=r"(u) : "f"(x));
    return u;
}
__device__ __forceinline__ float4 tf32r4(float4 v) {
    v.x = tf32r(v.x); v.y = tf32r(v.y); v.z = tf32r(v.z); v.w = tf32r(v.w);
    return v;
}
__device__ __forceinline__ float silu_f(float v) {
    return __fdiv_rn(v, 1.0f + acc_expf(-v));
}

__device__ __forceinline__ uint32_t s2u(const void* p) {
    return (uint32_t)__cvta_generic_to_shared(p);
}
__device__ __forceinline__ void cp16(uint32_t dst, const float* src) {
    asm volatile("cp.async.ca.shared.global [%0], [%1], 16;\n" :: "r"(dst), "l"(src));
}
__device__ __forceinline__ void cp_commit() {
    asm volatile("cp.async.commit_group;\n" ::);
}
__device__ __forceinline__ void cp_wait1() {
    asm volatile("cp.async.wait_group 1;\n" ::);
}

// ---------------- scratch ----------------
__device__ float g_x1[S_*H_];
__device__ float g_q[S_*H_];
__device__ float g_k[S_*KVH_*HD_];
__device__ float g_v[S_*KVH_*HD_];
__device__ float g_att[S_*H_];
__device__ float g_hidden[S_*H_];
__device__ float g_x2[S_*H_];
__device__ float g_hs[S_*I_];
__device__ float g_hcol[(S_*2)*I_];
__device__ float g_eo[(S_*2)*H_];
__device__ int   g_cnt[E_];
__device__ int   g_list[E_*S_];
__device__ float g_wts[S_*2];

// ---------------- TF32 tensor-core GEMM, 3-stage cp.async ----------------
#define BM  128
#define BN  128
#define BKT 16
#define NST 3
#define ASTR 20
#define BSTR 136
#define SMEM_GEMM ((NST*BM*ASTR + NST*BKT*BSTR) * 4)

template<int EPI, int GATHER, int SHIFT, int QKV>
__global__ void __launch_bounds__(256, 2) mma_gemm_k(
    const float* __restrict__ A, const float* __restrict__ B,
    float* __restrict__ C, const float* __restrict__ R,
    const int* __restrict__ list, const int* __restrict__ cnt,
    const float* __restrict__ B2, const float* __restrict__ B3,
    float* __restrict__ C2, float* __restrict__ C3,
    int N, int K)
{
    extern __shared__ float dsm[];
    float* As = dsm;
    float* Bs = dsm + NST * BM * ASTR;

    int n_rows = S_;
    const float* Bz = B;
    float* Cz = C;
    int zoff = 0;
    int Nl = N;
    int n0 = blockIdx.x * BN;
    if (GATHER) {
        const int z = blockIdx.z;
        n_rows = cnt[z];
        if ((int)blockIdx.y * BM >= n_rows) return;
        zoff = z * S_;
        Bz = B + (size_t)z * K * N;
    }
    if (QKV) {
        const int bx = blockIdx.x;
        if (bx < 8)       { Bz = B;  Cz = C;  Nl = 1024; n0 = bx * BN; }
        else if (bx < 10) { Bz = B2; Cz = C2; Nl = 256;  n0 = (bx - 8) * BN; }
        else              { Bz = B3; Cz = C3; Nl = 256;  n0 = (bx - 10) * BN; }
    }

    const int tid  = threadIdx.x;
    const int lane = tid & 31;
    const int wid  = tid >> 5;
    const int wm   = (wid & 1) * 64;
    const int wn   = (wid >> 1) * 32;
    const int m0   = blockIdx.y * BM;

    const int aIdx0 = tid, aIdx1 = tid + 256;
    const int r0 = m0 + (aIdx0 >> 2), r1 = m0 + (aIdx1 >> 2);
    int gar0 = r0, gar1 = r1;
    if (GATHER) {
        gar0 = (r0 < n_rows) ? (list[zoff + r0] >> SHIFT) : 0;
        gar1 = (r1 < n_rows) ? (list[zoff + r1] >> SHIFT) : 0;
    }
    const float* Ag0 = A + (size_t)gar0 * K + (aIdx0 & 3) * 4;
    const float* Ag1 = A + (size_t)gar1 * K + (aIdx1 & 3) * 4;
    const float* Bg0 = Bz + (size_t)(tid >> 5) * Nl + n0 + (tid & 31) * 4;
    const float* Bg1 = Bg0 + (size_t)8 * Nl;

    const uint32_t sa0 = s2u(&As[(size_t)(aIdx0 >> 2) * ASTR + (aIdx0 & 3) * 4]);
    const uint32_t sa1 = s2u(&As[(size_t)(aIdx1 >> 2) * ASTR + (aIdx1 & 3) * 4]);
    const uint32_t sb0 = s2u(&Bs[(size_t)(tid >> 5) * BSTR + (tid & 31) * 4]);
    const uint32_t sb1 = s2u(&Bs[(size_t)((tid >> 5) + 8) * BSTR + (tid & 31) * 4]);
    const uint32_t aStgB = BM * ASTR * 4;
    const uint32_t bStgB = BKT * BSTR * 4;

    float acc[4][4][4] = {};
    const int nk = K / BKT;

    auto load_stage = [&](int sbuf, int c) {
        const int k0 = c * BKT;
        cp16(sa0 + sbuf * aStgB, Ag0 + k0);
        cp16(sa1 + sbuf * aStgB, Ag1 + k0);
        cp16(sb0 + sbuf * bStgB, Bg0 + (size_t)k0 * Nl);
        cp16(sb1 + sbuf * bStgB, Bg1 + (size_t)k0 * Nl);
        cp_commit();
    };

    load_stage(0, 0);
    load_stage(1, 1);

    for (int c = 0; c < nk; c++) {
        cp_wait1();
        __syncthreads();
        const int buf = c % NST;
        if (c + NST - 1 < nk) load_stage((c + NST - 1) % NST, c + NST - 1);

        const float* Ab = As + (size_t)buf * BM * ASTR;
        const float* Bb = Bs + (size_t)buf * BKT * BSTR;
        #pragma unroll
        for (int ks = 0; ks < 2; ks++) {
            const int kk = ks * 8 + (lane & 3);
            uint32_t a[4][4], b[4][2];
            #pragma unroll
            for (int mt = 0; mt < 4; mt++) {
                const int m = wm + mt * 16 + (lane >> 2);
                a[mt][0] = tf32u(Ab[(size_t)m * ASTR + kk]);
                a[mt][1] = tf32u(Ab[(size_t)(m + 8) * ASTR + kk]);
                a[mt][2] = tf32u(Ab[(size_t)m * ASTR + kk + 4]);
                a[mt][3] = tf32u(Ab[(size_t)(m + 8) * ASTR + kk + 4]);
            }
            #pragma unroll
            for (int nt = 0; nt < 4; nt++) {
                const int nn = wn + nt * 8 + (lane >> 2);
                b[nt][0] = tf32u(Bb[(size_t)kk * BSTR + nn]);
                b[nt][1] = tf32u(Bb[(size_t)(kk + 4) * BSTR + nn]);
            }
            #pragma unroll
            for (int mt = 0; mt < 4; mt++)
                #pragma unroll
                for (int nt = 0; nt < 4; nt++)
                    asm volatile(
                        "mma.sync.aligned.m16n8k8.row.col.f32.tf32.tf32.f32 "
                        "{%0,%1,%2,%3}, {%4,%5,%6,%7}, {%8,%9}, {%0,%1,%2,%3};"
                        : "+f"(acc[mt][nt][0]), "+f"(acc[mt][nt][1]),
                          "+f"(acc[mt][nt][2]), "+f"(acc[mt][nt][3])
                        : "r"(a[mt][0]), "r"(a[mt][1]), "r"(a[mt][2]), "r"(a[mt][3]),
                          "r"(b[nt][0]), "r"(b[nt][1]));
        }
    }

    #pragma unroll
    for (int mt = 0; mt < 4; mt++) {
        #pragma unroll
        for (int half = 0; half < 2; half++) {
            const int r = m0 + wm + mt * 16 + (lane >> 2) + half * 8;
            if (GATHER && r >= n_rows) continue;
            size_t crow_idx = r;
            if (GATHER) crow_idx = (size_t)list[zoff + r];
            float* crow = Cz + crow_idx * Nl;
            #pragma unroll
            for (int nt = 0; nt < 4; nt++) {
                const int col = n0 + wn + nt * 8 + (lane & 3) * 2;
                float2 v;
                v.x = acc[mt][nt][half * 2 + 0];
                v.y = acc[mt][nt][half * 2 + 1];
                if (EPI == 1) {
                    v.x = silu_f(v.x); v.y = silu_f(v.y);
                } else if (EPI == 2) {
                    const float2 rr = *(const float2*)(R + crow_idx * Nl + col);
                    v.x += rr.x; v.y += rr.y;
                }
                *(float2*)(crow + col) = v;
            }
        }
    }
}

// ---------------- RMSNorm ----------------
__global__ void rmsnorm_k(const float* __restrict__ x, const float* __restrict__ w,
                          float* __restrict__ o)
{
    const int t = blockIdx.x;
    const int tid = threadIdx.x;
    const float* xr = x + (size_t)t * H_;
    float s = 0.f;
    for (int i = tid; i < H_; i += 256) { float v = xr[i]; s = __fmaf_rn(v, v, s); }
    for (int off = 16; off; off >>= 1) s += __shfl_down_sync(0xffffffffu, s, off);
    __shared__ float red[8];
    const int wid = tid >> 5, lane = tid & 31;
    if (!lane) red[wid] = s;
    __syncthreads();
    if (tid == 0) {
        float tot = 0.f;
        #pragma unroll
        for (int i = 0; i < 8; i++) tot += red[i];
        red[0] = rsqrtf(tot * (1.0f / H_) + 1e-6f);
    }
    __syncthreads();
    const float r = red[0];
    float* orow = o + (size_t)t * H_;
    for (int i = tid; i < H_; i += 256) orow[i] = w[i] * (xr[i] * r);
}

// ---------------- RoPE ----------------
__global__ void rope_k(float* __restrict__ q, float* __restrict__ k)
{
    const int idx = blockIdx.x * blockDim.x + threadIdx.x;
    const int half = idx & 31;
    const int rest = idx >> 5;
    const int head = rest % (NH_ + KVH_);
    const int t = rest / (NH_ + KVH_);
    const float inv_freq = __fdiv_rn(1.0f, acc_powf(10000.0f, (float)half * 0.03125f));
    const float ang = __fmul_rn((float)t, inv_freq);
    const float c = acc_cosf(ang);
    const float sn = acc_sinf(ang);
    float* base = (head < NH_) ? (q + (size_t)t * H_ + head * HD_)
                               : (k + (size_t)t * (KVH_ * HD_) + (head - NH_) * HD_);
    const float x1 = base[half];
    const float x2 = base[half + 32];
    base[half]      = __fadd_rn(__fmul_rn(x1, c), -__fmul_rn(x2, sn));
    base[half + 32] = __fadd_rn(__fmul_rn(x2, c),  __fmul_rn(x1, sn));
}

// ------------- Attention: MMA, two-pass softmax, smem-only (no gmem cache) ----
#define AQ 128
#define AK 64
#define QSTR 68
// dyn smem: Qs[128*68] KV[64*68] SP[128*68] mbuf[256] lbuf[256] mfin[128] lfin[128]
#define SMEM_ATTN ((AQ*QSTR + AK*QSTR + AQ*QSTR + 256 + 256 + AQ + AQ) * 4)

__global__ void __launch_bounds__(256, 2) attn_mma_k(
    const float* __restrict__ q, const float* __restrict__ k,
    const float* __restrict__ v, float* __restrict__ o)
{
    extern __shared__ float sm[];
    float* Qs   = sm;
    float* KV   = Qs + AQ * QSTR;
    float* SP   = KV + AK * QSTR;
    float* mbuf = SP + AQ * QSTR;
    float* lbuf = mbuf + 256;
    float* mfin = lbuf + 256;
    float* lfin = mfin + AQ;

    const int h  = blockIdx.y;
    const int qt = (int)gridDim.x - 1 - (int)blockIdx.x;   // heavy tiles first
    const int q0 = qt * AQ;
    const int tid = threadIdx.x;
    const int lane = tid & 31, wid = tid >> 5;
    const int kvh = h >> 2;

    const int myq = tid & 127, jh = tid >> 7;
    const int qi = q0 + myq;
    const int ntiles = (q0 + AQ) / AK;

    // load Q tile (tf32)
    for (int i = tid; i < AQ * (HD_ / 4); i += 256) {
        const int qq = i >> 4, d4 = (i & 15) * 4;
        *(float4*)&Qs[qq * QSTR + d4] =
            tf32r4(*(const float4*)(q + (size_t)(q0 + qq) * H_ + h * HD_ + d4));
    }

    const int wm = (wid & 3) * 32, wn = (wid >> 2) * 32;

    // S = Q K^T MMA for one K tile (KV holds tf32 K tile) -> accS
    auto mma_scores = [&](float accS[2][4][4]) {
        #pragma unroll
        for (int ks = 0; ks < 8; ks++) {
            const int kk = ks * 8 + (lane & 3);
            uint32_t a[2][4], b[4][2];
            #pragma unroll
            for (int mt = 0; mt < 2; mt++) {
                const int r = wm + mt * 16 + (lane >> 2);
                a[mt][0] = __float_as_uint(Qs[r * QSTR + kk]);
                a[mt][1] = __float_as_uint(Qs[(r + 8) * QSTR + kk]);
                a[mt][2] = __float_as_uint(Qs[r * QSTR + kk + 4]);
                a[mt][3] = __float_as_uint(Qs[(r + 8) * QSTR + kk + 4]);
            }
            #pragma unroll
            for (int nt = 0; nt < 4; nt++) {
                const int j = wn + nt * 8 + (lane >> 2);
                b[nt][0] = __float_as_uint(KV[j * QSTR + kk]);
                b[nt][1] = __float_as_uint(KV[j * QSTR + kk + 4]);
            }
            #pragma unroll
            for (int mt = 0; mt < 2; mt++)
                #pragma unroll
                for (int nt = 0; nt < 4; nt++)
                    asm volatile(
                        "mma.sync.aligned.m16n8k8.row.col.f32.tf32.tf32.f32 "
                        "{%0,%1,%2,%3}, {%4,%5,%6,%7}, {%8,%9}, {%0,%1,%2,%3};"
                        : "+f"(accS[mt][nt][0]), "+f"(accS[mt][nt][1]),
                          "+f"(accS[mt][nt][2]), "+f"(accS[mt][nt][3])
                        : "r"(a[mt][0]), "r"(a[mt][1]), "r"(a[mt][2]), "r"(a[mt][3]),
                          "r"(b[nt][0]), "r"(b[nt][1]));
        }
    };

    auto load_k_tile = [&](int k0) {
        for (int i = tid; i < AK * (HD_ / 4); i += 256) {
            const int j = i >> 4, d4 = (i & 15) * 4;
            *(float4*)&KV[j * QSTR + d4] =
                tf32r4(*(const float4*)(k + (size_t)(k0 + j) * (KVH_ * HD_) + kvh * HD_ + d4));
        }
    };

    float m_old = -1e30f, l_old = 0.f;

    // ---- phase A: running row max m and denominator l ----
    for (int t = 0; t < ntiles; t++) {
        const int k0 = t * AK;
        __syncthreads();
        load_k_tile(k0);
        __syncthreads();
        float accS[2][4][4] = {};
        mma_scores(accS);
        // scaled scores -> SP [q][j]
        #pragma unroll
        for (int mt = 0; mt < 2; mt++)
            #pragma unroll
            for (int half = 0; half < 2; half++) {
                const int row = wm + mt * 16 + (lane >> 2) + half * 8;
                #pragma unroll
                for (int nt = 0; nt < 4; nt++) {
                    const int col = wn + nt * 8 + (lane & 3) * 2;
                    SP[row * QSTR + col]     = accS[mt][nt][half * 2 + 0] * 0.125f;
                    SP[row * QSTR + col + 1] = accS[mt][nt][half * 2 + 1] * 0.125f;
                }
            }
        __syncthreads();
        // per-row tile max (2 threads/row)
        const int jlim = min(AK, qi - k0 + 1);
        const int jend = min(jlim, jh * 32 + 32);
        float mp = -1e30f;
        for (int jj = jh * 32; jj < jend; jj++)
            mp = fmaxf(mp, SP[myq * QSTR + jj]);
        mbuf[tid] = mp;
        __syncthreads();
        if (tid < 128)
            mfin[tid] = fmaxf(m_old, fmaxf(mbuf[tid], mbuf[tid + 128]));
        __syncthreads();
        const float mn = mfin[myq];
        float lp = 0.f;
        for (int jj = jh * 32; jj < jend; jj++)
            lp += acc_expf(SP[myq * QSTR + jj] - mn);
        lbuf[tid] = lp;
        __syncthreads();
        if (tid < 128) {
            l_old = __fmaf_rn(l_old, acc_expf(m_old - mn), lbuf[tid] + lbuf[tid + 128]);
            m_old = mn;
        }
    }
    __syncthreads();
    if (tid < 128) lfin[tid] = l_old;   // mfin already holds final m
    __syncthreads();

    // ---- phase C: recompute S (bit-identical), p = tf32(e/l), O += P V -------
    float accO[2][4][4] = {};
    for (int t = 0; t < ntiles; t++) {
        const int k0 = t * AK;
        __syncthreads();
        load_k_tile(k0);
        __syncthreads();
        float accS[2][4][4] = {};
        mma_scores(accS);
        // convert fragments to probabilities in SP
        #pragma unroll
        for (int mt = 0; mt < 2; mt++)
            #pragma unroll
            for (int half = 0; half < 2; half++) {
                const int row = wm + mt * 16 + (lane >> 2) + half * 8;
                const float mq = mfin[row];
                const float lq = lfin[row];
                #pragma unroll
                for (int nt = 0; nt < 4; nt++) {
                    #pragma unroll
                    for (int e2 = 0; e2 < 2; e2++) {
                        const int col = wn + nt * 8 + (lane & 3) * 2 + e2;
                        float p = 0.f;
                        if (k0 + col <= q0 + row) {
                            const float s = accS[mt][nt][half * 2 + e2] * 0.125f;
                            p = tf32r(__fdiv_rn(acc_expf(s - mq), lq));
                        }
                        SP[row * QSTR + col] = p;
                    }
                }
            }
        __syncthreads();
        // V tile overwrites KV
        for (int i = tid; i < AK * (HD_ / 4); i += 256) {
            const int j = i >> 4, d4 = (i & 15) * 4;
            *(float4*)&KV[j * QSTR + d4] =
                tf32r4(*(const float4*)(v + (size_t)(k0 + j) * (KVH_ * HD_) + kvh * HD_ + d4));
        }
        __syncthreads();
        // O += P V
        #pragma unroll
        for (int ks = 0; ks < 8; ks++) {
            const int kk = ks * 8 + (lane & 3);
            uint32_t a[2][4], b[4][2];
            #pragma unroll
            for (int mt = 0; mt < 2; mt++) {
                const int r = wm + mt * 16 + (lane >> 2);
                a[mt][0] = __float_as_uint(SP[r * QSTR + kk]);
                a[mt][1] = __float_as_uint(SP[(r + 8) * QSTR + kk]);
                a[mt][2] = __float_as_uint(SP[r * QSTR + kk + 4]);
                a[mt][3] = __float_as_uint(SP[(r + 8) * QSTR + kk + 4]);
            }
            #pragma unroll
            for (int nt = 0; nt < 4; nt++) {
                const int d = wn + nt * 8 + (lane >> 2);
                b[nt][0] = __float_as_uint(KV[kk * QSTR + d]);
                b[nt][1] = __float_as_uint(KV[(kk + 4) * QSTR + d]);
            }
            #pragma unroll
            for (int mt = 0; mt < 2; mt++)
                #pragma unroll
                for (int nt = 0; nt < 4; nt++)
                    asm volatile(
                        "mma.sync.aligned.m16n8k8.row.col.f32.tf32.tf32.f32 "
                        "{%0,%1,%2,%3}, {%4,%5,%6,%7}, {%8,%9}, {%0,%1,%2,%3};"
                        : "+f"(accO[mt][nt][0]), "+f"(accO[mt][nt][1]),
                          "+f"(accO[mt][nt][2]), "+f"(accO[mt][nt][3])
                        : "r"(a[mt][0]), "r"(a[mt][1]), "r"(a[mt][2]), "r"(a[mt][3]),
                          "r"(b[nt][0]), "r"(b[nt][1]));
        }
    }

    // write O
    #pragma unroll
    for (int mt = 0; mt < 2; mt++)
        #pragma unroll
        for (int half = 0; half < 2; half++) {
            const int row = q0 + wm + mt * 16 + (lane >> 2) + half * 8;
            #pragma unroll
            for (int nt = 0; nt < 4; nt++) {
                const int col = wn + nt * 8 + (lane & 3) * 2;
                float2 r2;
                r2.x = accO[mt][nt][half * 2 + 0];
                r2.y = accO[mt][nt][half * 2 + 1];
                *(float2*)(o + (size_t)row * H_ + h * HD_ + col) = r2;
            }
        }
}

// ---------------- router ----------------
__global__ void zero_k(int* __restrict__ c)
{
    if (threadIdx.x < E_) c[threadIdx.x] = 0;
}

__global__ void router_k(const float* __restrict__ x, const float* __restrict__ rw,
                         int* __restrict__ cnt, int* __restrict__ list,
                         float* __restrict__ wout)
{
    const int t = blockIdx.x;
    const int tid = threadIdx.x;
    const int e = tid >> 5, lane = tid & 31;
    const float* xr = x + (size_t)t * H_;
    float s = 0.f;
    for (int i = lane; i < H_; i += 32)
        s = __fmaf_rn(tf32r(xr[i]), tf32r(rw[i * E_ + e]), s);
    for (int off = 16; off; off >>= 1) s += __shfl_down_sync(0xffffffffu, s, off);
    __shared__ float logit[E_];
    if (!lane) logit[e] = s;
    __syncthreads();
    if (tid == 0) {
        float mx = logit[0];
        #pragma unroll
        for (int i = 1; i < E_; i++) mx = fmaxf(mx, logit[i]);
        float p[E_];
        #pragma unroll
        for (int i = 0; i < E_; i++) p[i] = acc_expf(logit[i] - mx);
        int i0 = 0;
        #pragma unroll
        for (int i = 1; i < E_; i++) if (p[i] > p[i0]) i0 = i;
        int i1 = (i0 == 0) ? 1 : 0;
        #pragma unroll
        for (int i = 0; i < E_; i++) if (i != i0 && p[i] > p[i1]) i1 = i;
        const float denom = p[i0] + p[i1];
        wout[2 * t + 0] = __fdiv_rn(p[i0], denom);
        wout[2 * t + 1] = __fdiv_rn(p[i1], denom);
        int pos = atomicAdd(&cnt[i0], 1);
        list[i0 * S_ + pos] = 2 * t;
        pos = atomicAdd(&cnt[i1], 1);
        list[i1 * S_ + pos] = 2 * t + 1;
    }
}

// ---------------- combine ----------------
__global__ void combine_k(float* __restrict__ out, const float* __restrict__ eo,
                          const float* __restrict__ w)
{
    const int t = blockIdx.x;
    const float w0 = w[2 * t], w1 = w[2 * t + 1];
    const float* e0 = eo + (size_t)(2 * t) * H_;
    const float* e1 = eo + (size_t)(2 * t + 1) * H_;
    float* orow = out + (size_t)t * H_;
    for (int i = threadIdx.x; i < H_; i += 256)
        orow[i] += __fmaf_rn(w0, e0[i], __fmul_rn(w1, e1[i]));
}

// ---------------- host launch --------------------------------------------------
extern "C" void kernel_launch(void* const* d_in, const int* in_sizes, int n_in,
                              void* d_out, int out_size)
{
    const float* hs  = (const float*)d_in[0];
    const float* ln1 = (const float*)d_in[1];
    const float* wq  = (const float*)d_in[2];
    const float* wk  = (const float*)d_in[3];
    const float* wv  = (const float*)d_in[4];
    const float* wo  = (const float*)d_in[5];
    const float* ln2 = (const float*)d_in[6];
    const float* sw1 = (const float*)d_in[7];
    const float* sw2 = (const float*)d_in[8];
    const float* ew1 = (const float*)d_in[9];
    const float* ew2 = (const float*)d_in[10];
    const float* rw  = (const float*)d_in[11];
    float* out = (float*)d_out;

    float *x1, *q, *k, *v, *att, *hid, *x2, *hsv, *hcol, *eo, *wts;
    int *cnt, *list;
    cudaGetSymbolAddress((void**)&x1,   g_x1);
    cudaGetSymbolAddress((void**)&q,    g_q);
    cudaGetSymbolAddress((void**)&k,    g_k);
    cudaGetSymbolAddress((void**)&v,    g_v);
    cudaGetSymbolAddress((void**)&att,  g_att);
    cudaGetSymbolAddress((void**)&hid,  g_hidden);
    cudaGetSymbolAddress((void**)&x2,   g_x2);
    cudaGetSymbolAddress((void**)&hsv,  g_hs);
    cudaGetSymbolAddress((void**)&hcol, g_hcol);
    cudaGetSymbolAddress((void**)&eo,   g_eo);
    cudaGetSymbolAddress((void**)&wts,  g_wts);
    cudaGetSymbolAddress((void**)&cnt,  g_cnt);
    cudaGetSymbolAddress((void**)&list, g_list);

    cudaFuncSetAttribute(mma_gemm_k<0,0,0,1>, cudaFuncAttributeMaxDynamicSharedMemorySize, SMEM_GEMM);
    cudaFuncSetAttribute(mma_gemm_k<2,0,0,0>, cudaFuncAttributeMaxDynamicSharedMemorySize, SMEM_GEMM);
    cudaFuncSetAttribute(mma_gemm_k<1,0,0,0>, cudaFuncAttributeMaxDynamicSharedMemorySize, SMEM_GEMM);
    cudaFuncSetAttribute(mma_gemm_k<1,1,1,0>, cudaFuncAttributeMaxDynamicSharedMemorySize, SMEM_GEMM);
    cudaFuncSetAttribute(mma_gemm_k<0,1,0,0>, cudaFuncAttributeMaxDynamicSharedMemorySize, SMEM_GEMM);
    cudaFuncSetAttribute(attn_mma_k, cudaFuncAttributeMaxDynamicSharedMemorySize, SMEM_ATTN);

    // 1. rmsnorm1
    rmsnorm_k<<<S_, 256>>>(hs, ln1, x1);
    // 2. fused QKV projection
    mma_gemm_k<0,0,0,1><<<dim3(12, S_ / BM), 256, SMEM_GEMM>>>(
        x1, wq, q, nullptr, nullptr, nullptr, wk, wv, k, v, H_, H_);
    // 3. RoPE
    rope_k<<<(S_ * (NH_ + KVH_) * 32) / 256, 256>>>(q, k);
    // 4. attention (MMA, smem-only two-pass)
    attn_mma_k<<<dim3(S_ / AQ, NH_), 256, SMEM_ATTN>>>(q, k, v, att);
    // 5. O-proj + residual
    mma_gemm_k<2,0,0,0><<<dim3(H_ / BN, S_ / BM), 256, SMEM_GEMM>>>(
        att, wo, hid, hs, nullptr, nullptr, nullptr, nullptr, nullptr, nullptr, H_, H_);
    // 6. rmsnorm2
    rmsnorm_k<<<S_, 256>>>(hid, ln2, x2);
    // 7. router
    zero_k<<<1, 32>>>(cnt);
    router_k<<<S_, 256>>>(x2, rw, cnt, list, wts);
    // 8. shared MLP
    mma_gemm_k<1,0,0,0><<<dim3(I_ / BN, S_ / BM), 256, SMEM_GEMM>>>(
        x2, sw1, hsv, nullptr, nullptr, nullptr, nullptr, nullptr, nullptr, nullptr, I_, H_);
    mma_gemm_k<2,0,0,0><<<dim3(H_ / BN, S_ / BM), 256, SMEM_GEMM>>>(
        hsv, sw2, out, hid, nullptr, nullptr, nullptr, nullptr, nullptr, nullptr, H_, I_);
    // 9. gathered expert MLPs (top-2 only)
    mma_gemm_k<1,1,1,0><<<dim3(I_ / BN, S_ / BM, E_), 256, SMEM_GEMM>>>(
        x2, ew1, hcol, nullptr, list, cnt, nullptr, nullptr, nullptr, nullptr, I_, H_);
    mma_gemm_k<0,1,0,0><<<dim3(H_ / BN, S_ / BM, E_), 256, SMEM_GEMM>>>(
        hcol, ew2, eo, nullptr, list, cnt, nullptr, nullptr, nullptr, nullptr, H_, I_);
    // 10. combine
    combine_k<<<S_, 256>>>(out, eo, wts);
}

// round 7
// speedup vs baseline: 1.6694x; 1.0654x over previous
#include <cuda_runtime.h>
#include <cstdint>
#include <math.h>

#define S_   2048
#define H_   1024
#define NH_  16
#define KVH_ 4
#define HD_  64
#define E_   8
#define I_   4096

// ---------------- accurate math helpers ------------------
#ifdef __FAST_MATH__
__device__ __forceinline__ float acc_expf(float x) { return (float)exp((double)x); }
__device__ __forceinline__ float acc_cosf(float x) { return (float)cos((double)x); }
__device__ __forceinline__ float acc_sinf(float x) { return (float)sin((double)x); }
__device__ __forceinline__ float acc_powf(float a, float b) { return (float)pow((double)a, (double)b); }
#else
__device__ __forceinline__ float acc_expf(float x) { return expf(x); }
__device__ __forceinline__ float acc_cosf(float x) { return cosf(x); }
__device__ __forceinline__ float acc_sinf(float x) { return sinf(x); }
__device__ __forceinline__ float acc_powf(float a, float b) { return powf(a, b); }
#endif

__device__ __forceinline__ float tf32r(float x) {
    uint32_t u;
    asm("cvt.rna.tf32.f32 %0, %1;" : "=r"(u) : "f"(x));
    return __uint_as_float(u);
}
__device__ __forceinline__ uint32_t tf32u(float x) {
    uint32_t u;
    asm("cvt.rna.tf32.f32 %0, %1;" : "=r"(u) : "f"(x));
    return u;
}
__device__ __forceinline__ float4 tf32r4(float4 v) {
    v.x = tf32r(v.x); v.y = tf32r(v.y); v.z = tf32r(v.z); v.w = tf32r(v.w);
    return v;
}
__device__ __forceinline__ float silu_f(float v) {
    return __fdiv_rn(v, 1.0f + acc_expf(-v));
}

__device__ __forceinline__ uint32_t s2u(const void* p) {
    return (uint32_t)__cvta_generic_to_shared(p);
}
__device__ __forceinline__ void cp16(uint32_t dst, const float* src) {
    asm volatile("cp.async.ca.shared.global [%0], [%1], 16;\n" :: "r"(dst), "l"(src));
}
__device__ __forceinline__ void cp_commit() {
    asm volatile("cp.async.commit_group;\n" ::);
}
__device__ __forceinline__ void cp_wait1() {
    asm volatile("cp.async.wait_group 1;\n" ::);
}
__device__ __forceinline__ void cp_wait0() {
    asm volatile("cp.async.wait_group 0;\n" ::);
}

// ---------------- scratch ----------------
__device__ float g_x1[S_*H_];
__device__ float g_q[S_*H_];
__device__ float g_k[S_*KVH_*HD_];
__device__ float g_v[S_*KVH_*HD_];
__device__ float g_att[S_*H_];
__device__ float g_hidden[S_*H_];
__device__ float g_x2[S_*H_];
__device__ float g_hs[S_*I_];
__device__ float g_hcol[(S_*2)*I_];
__device__ float g_eo[(S_*2)*H_];
__device__ int   g_cnt[E_];
__device__ int   g_list[E_*S_];
__device__ float g_wts[S_*2];

// ---------------- TF32 tensor-core GEMM, 3-stage cp.async ----------------
// MODE: 0 plain, 1 gather, 2 fused (z==0: shared path via B2/B3/C2, z>0: gather expert)
#define BM  128
#define BN  128
#define BKT 16
#define NST 3
#define ASTR 20
#define BSTR 136
#define SMEM_GEMM ((NST*BM*ASTR + NST*BKT*BSTR) * 4)

template<int EPI, int MODE, int SHIFT, int QKV, int EPI2>
__global__ void __launch_bounds__(256, 2) mma_gemm_k(
    const float* __restrict__ A, const float* __restrict__ B,
    float* __restrict__ C, const float* __restrict__ R,
    const int* __restrict__ list, const int* __restrict__ cnt,
    const float* __restrict__ B2, const float* __restrict__ B3,
    float* __restrict__ C2, float* __restrict__ C3,
    int N, int K)
{
    extern __shared__ float dsm[];
    float* As = dsm;
    float* Bs = dsm + NST * BM * ASTR;

    int n_rows = S_;
    const float* Az = A;
    const float* Bz = B;
    float* Cz = C;
    bool gat = (MODE == 1);
    int zoff = 0;
    int Nl = N;
    int n0 = blockIdx.x * BN;
    if (MODE == 1) {
        const int z = blockIdx.z;
        n_rows = cnt[z];
        if ((int)blockIdx.y * BM >= n_rows) return;
        zoff = z * S_;
        Bz = B + (size_t)z * K * N;
    }
    if (MODE == 2) {
        const int z = blockIdx.z;
        if (z == 0) {
            Az = B3; Bz = B2; Cz = C2; gat = false;
        } else {
            const int e = z - 1;
            n_rows = cnt[e];
            if ((int)blockIdx.y * BM >= n_rows) return;
            zoff = e * S_;
            Bz = B + (size_t)e * K * N;
            gat = true;
        }
    }
    if (QKV) {
        const int bx = blockIdx.x;
        if (bx < 8)       { Bz = B;  Cz = C;  Nl = 1024; n0 = bx * BN; }
        else if (bx < 10) { Bz = B2; Cz = C2; Nl = 256;  n0 = (bx - 8) * BN; }
        else              { Bz = B3; Cz = C3; Nl = 256;  n0 = (bx - 10) * BN; }
    }

    const int tid  = threadIdx.x;
    const int lane = tid & 31;
    const int wid  = tid >> 5;
    const int wm   = (wid & 1) * 64;
    const int wn   = (wid >> 1) * 32;
    const int m0   = blockIdx.y * BM;

    const int aIdx0 = tid, aIdx1 = tid + 256;
    const int r0 = m0 + (aIdx0 >> 2), r1 = m0 + (aIdx1 >> 2);
    int gar0 = r0, gar1 = r1;
    if (gat) {
        gar0 = (r0 < n_rows) ? (list[zoff + r0] >> SHIFT) : 0;
        gar1 = (r1 < n_rows) ? (list[zoff + r1] >> SHIFT) : 0;
    }
    const float* Ag0 = Az + (size_t)gar0 * K + (aIdx0 & 3) * 4;
    const float* Ag1 = Az + (size_t)gar1 * K + (aIdx1 & 3) * 4;
    const float* Bg0 = Bz + (size_t)(tid >> 5) * Nl + n0 + (tid & 31) * 4;
    const float* Bg1 = Bg0 + (size_t)8 * Nl;

    const uint32_t sa0 = s2u(&As[(size_t)(aIdx0 >> 2) * ASTR + (aIdx0 & 3) * 4]);
    const uint32_t sa1 = s2u(&As[(size_t)(aIdx1 >> 2) * ASTR + (aIdx1 & 3) * 4]);
    const uint32_t sb0 = s2u(&Bs[(size_t)(tid >> 5) * BSTR + (tid & 31) * 4]);
    const uint32_t sb1 = s2u(&Bs[(size_t)((tid >> 5) + 8) * BSTR + (tid & 31) * 4]);
    const uint32_t aStgB = BM * ASTR * 4;
    const uint32_t bStgB = BKT * BSTR * 4;

    float acc[4][4][4] = {};
    const int nk = K / BKT;

    auto load_stage = [&](int sbuf, int c) {
        const int k0 = c * BKT;
        cp16(sa0 + sbuf * aStgB, Ag0 + k0);
        cp16(sa1 + sbuf * aStgB, Ag1 + k0);
        cp16(sb0 + sbuf * bStgB, Bg0 + (size_t)k0 * Nl);
        cp16(sb1 + sbuf * bStgB, Bg1 + (size_t)k0 * Nl);
        cp_commit();
    };

    load_stage(0, 0);
    load_stage(1, 1);

    for (int c = 0; c < nk; c++) {
        cp_wait1();
        __syncthreads();
        const int buf = c % NST;
        if (c + NST - 1 < nk) load_stage((c + NST - 1) % NST, c + NST - 1);

        const float* Ab = As + (size_t)buf * BM * ASTR;
        const float* Bb = Bs + (size_t)buf * BKT * BSTR;
        #pragma unroll
        for (int ks = 0; ks < 2; ks++) {
            const int kk = ks * 8 + (lane & 3);
            uint32_t a[4][4], b[4][2];
            #pragma unroll
            for (int mt = 0; mt < 4; mt++) {
                const int m = wm + mt * 16 + (lane >> 2);
                a[mt][0] = tf32u(Ab[(size_t)m * ASTR + kk]);
                a[mt][1] = tf32u(Ab[(size_t)(m + 8) * ASTR + kk]);
                a[mt][2] = tf32u(Ab[(size_t)m * ASTR + kk + 4]);
                a[mt][3] = tf32u(Ab[(size_t)(m + 8) * ASTR + kk + 4]);
            }
            #pragma unroll
            for (int nt = 0; nt < 4; nt++) {
                const int nn = wn + nt * 8 + (lane >> 2);
                b[nt][0] = tf32u(Bb[(size_t)kk * BSTR + nn]);
                b[nt][1] = tf32u(Bb[(size_t)(kk + 4) * BSTR + nn]);
            }
            #pragma unroll
            for (int mt = 0; mt < 4; mt++)
                #pragma unroll
                for (int nt = 0; nt < 4; nt++)
                    asm volatile(
                        "mma.sync.aligned.m16n8k8.row.col.f32.tf32.tf32.f32 "
                        "{%0,%1,%2,%3}, {%4,%5,%6,%7}, {%8,%9}, {%0,%1,%2,%3};"
                        : "+f"(acc[mt][nt][0]), "+f"(acc[mt][nt][1]),
                          "+f"(acc[mt][nt][2]), "+f"(acc[mt][nt][3])
                        : "r"(a[mt][0]), "r"(a[mt][1]), "r"(a[mt][2]), "r"(a[mt][3]),
                          "r"(b[nt][0]), "r"(b[nt][1]));
        }
    }

    const bool sharedSide = (MODE == 2) && (blockIdx.z == 0);
    #pragma unroll
    for (int mt = 0; mt < 4; mt++) {
        #pragma unroll
        for (int half = 0; half < 2; half++) {
            const int r = m0 + wm + mt * 16 + (lane >> 2) + half * 8;
            if (gat && r >= n_rows) continue;
            size_t crow_idx = r;
            if (gat) crow_idx = (size_t)list[zoff + r];
            float* crow = Cz + crow_idx * Nl;
            const int epi = sharedSide ? EPI2 : EPI;
            #pragma unroll
            for (int nt = 0; nt < 4; nt++) {
                const int col = n0 + wn + nt * 8 + (lane & 3) * 2;
                float2 v;
                v.x = acc[mt][nt][half * 2 + 0];
                v.y = acc[mt][nt][half * 2 + 1];
                if (epi == 1) {
                    v.x = silu_f(v.x); v.y = silu_f(v.y);
                } else if (epi == 2) {
                    const float2 rr = *(const float2*)(R + crow_idx * Nl + col);
                    v.x += rr.x; v.y += rr.y;
                }
                *(float2*)(crow + col) = v;
            }
        }
    }
}

// ---------------- RMSNorm ----------------
__global__ void rmsnorm_k(const float* __restrict__ x, const float* __restrict__ w,
                          float* __restrict__ o)
{
    const int t = blockIdx.x;
    const int tid = threadIdx.x;
    const float* xr = x + (size_t)t * H_;
    float s = 0.f;
    for (int i = tid; i < H_; i += 256) { float v = xr[i]; s = __fmaf_rn(v, v, s); }
    for (int off = 16; off; off >>= 1) s += __shfl_down_sync(0xffffffffu, s, off);
    __shared__ float red[8];
    const int wid = tid >> 5, lane = tid & 31;
    if (!lane) red[wid] = s;
    __syncthreads();
    if (tid == 0) {
        float tot = 0.f;
        #pragma unroll
        for (int i = 0; i < 8; i++) tot += red[i];
        red[0] = rsqrtf(tot * (1.0f / H_) + 1e-6f);
    }
    __syncthreads();
    const float r = red[0];
    float* orow = o + (size_t)t * H_;
    for (int i = tid; i < H_; i += 256) orow[i] = w[i] * (xr[i] * r);
}

// ---------------- RoPE ----------------
__global__ void rope_k(float* __restrict__ q, float* __restrict__ k)
{
    const int idx = blockIdx.x * blockDim.x + threadIdx.x;
    const int half = idx & 31;
    const int rest = idx >> 5;
    const int head = rest % (NH_ + KVH_);
    const int t = rest / (NH_ + KVH_);
    const float inv_freq = __fdiv_rn(1.0f, acc_powf(10000.0f, (float)half * 0.03125f));
    const float ang = __fmul_rn((float)t, inv_freq);
    const float c = acc_cosf(ang);
    const float sn = acc_sinf(ang);
    float* base = (head < NH_) ? (q + (size_t)t * H_ + head * HD_)
                               : (k + (size_t)t * (KVH_ * HD_) + (head - NH_) * HD_);
    const float x1 = base[half];
    const float x2 = base[half + 32];
    base[half]      = __fadd_rn(__fmul_rn(x1, c), -__fmul_rn(x2, sn));
    base[half + 32] = __fadd_rn(__fmul_rn(x2, c),  __fmul_rn(x1, sn));
}

// ---- Attention: MMA two-pass, in-register softmax stats, cp.async K/V -------
#define AQ 128
#define AK 64
#define QSTR 68
// smem: Qs[128*68] SP[128*68] KVa[64*68] KVb[64*68] partM[256] partL[256] mfin[128] lfin[128]
#define SMEM_ATTN ((AQ*QSTR*2 + AK*QSTR*2 + 256 + 256 + AQ + AQ) * 4)

__global__ void __launch_bounds__(256, 2) attn_mma_k(
    const float* __restrict__ q, const float* __restrict__ k,
    const float* __restrict__ v, float* __restrict__ o)
{
    extern __shared__ float sm[];
    float* Qs    = sm;
    float* SP    = Qs + AQ * QSTR;
    float* KVa   = SP + AQ * QSTR;
    float* KVb   = KVa + AK * QSTR;
    float* partM = KVb + AK * QSTR;   // [128][2]
    float* partL = partM + 256;
    float* mfin  = partL + 256;
    float* lfin  = mfin + AQ;

    const int h  = blockIdx.y;
    const int qt = (int)gridDim.x - 1 - (int)blockIdx.x;   // heavy tiles first
    const int q0 = qt * AQ;
    const int tid = threadIdx.x;
    const int lane = tid & 31, wid = tid >> 5;
    const int kvh = h >> 2;
    const int ntiles = (q0 + AQ) / AK;
    const int wm = (wid & 3) * 32, wn = (wid >> 2) * 32;

    // async copy of one 64x64 K/V tile: 4 cp16 per thread
    auto issue_tile = [&](const float* gbase, float* sbuf) {
        #pragma unroll
        for (int s = 0; s < 4; s++) {
            const int i = tid + s * 256;
            const int j = i >> 4, d4 = (i & 15) * 4;
            cp16(s2u(&sbuf[j * QSTR + d4]), gbase + (size_t)j * (KVH_ * HD_) + d4);
        }
        cp_commit();
    };
    auto kbase = [&](int k0) { return k + (size_t)k0 * (KVH_ * HD_) + kvh * HD_; };
    auto vbase = [&](int k0) { return v + (size_t)k0 * (KVH_ * HD_) + kvh * HD_; };

    // S = Q K^T MMA (K buffer raw; tf32 at read)
    auto mma_scores = [&](const float* KB, float accS[2][4][4]) {
        #pragma unroll
        for (int ks = 0; ks < 8; ks++) {
            const int kk = ks * 8 + (lane & 3);
            uint32_t a[2][4], b[4][2];
            #pragma unroll
            for (int mt = 0; mt < 2; mt++) {
                const int r = wm + mt * 16 + (lane >> 2);
                a[mt][0] = __float_as_uint(Qs[r * QSTR + kk]);
                a[mt][1] = __float_as_uint(Qs[(r + 8) * QSTR + kk]);
                a[mt][2] = __float_as_uint(Qs[r * QSTR + kk + 4]);
                a[mt][3] = __float_as_uint(Qs[(r + 8) * QSTR + kk + 4]);
            }
            #pragma unroll
            for (int nt = 0; nt < 4; nt++) {
                const int j = wn + nt * 8 + (lane >> 2);
                b[nt][0] = tf32u(KB[j * QSTR + kk]);
                b[nt][1] = tf32u(KB[j * QSTR + kk + 4]);
            }
            #pragma unroll
            for (int mt = 0; mt < 2; mt++)
                #pragma unroll
                for (int nt = 0; nt < 4; nt++)
                    asm volatile(
                        "mma.sync.aligned.m16n8k8.row.col.f32.tf32.tf32.f32 "
                        "{%0,%1,%2,%3}, {%4,%5,%6,%7}, {%8,%9}, {%0,%1,%2,%3};"
                        : "+f"(accS[mt][nt][0]), "+f"(accS[mt][nt][1]),
                          "+f"(accS[mt][nt][2]), "+f"(accS[mt][nt][3])
                        : "r"(a[mt][0]), "r"(a[mt][1]), "r"(a[mt][2]), "r"(a[mt][3]),
                          "r"(b[nt][0]), "r"(b[nt][1]));
        }
    };

    // ---- phase A: running (m, l) via in-register fragment reduction ----
    issue_tile(kbase(0), KVa);
    // load Q tile (tf32-rounded once)
    for (int i = tid; i < AQ * (HD_ / 4); i += 256) {
        const int qq = i >> 4, d4 = (i & 15) * 4;
        *(float4*)&Qs[qq * QSTR + d4] =
            tf32r4(*(const float4*)(q + (size_t)(q0 + qq) * H_ + h * HD_ + d4));
    }

    float m_old = -1e30f, l_old = 0.f;
    for (int t = 0; t < ntiles; t++) {
        const int k0 = t * AK;
        float* bufX = (t & 1) ? KVb : KVa;
        float* bufY = (t & 1) ? KVa : KVb;
        if (t + 1 < ntiles) { issue_tile(kbase(k0 + AK), bufY); cp_wait1(); }
        else                { cp_wait0(); }
        __syncthreads();                          // K_t visible; partM free for reuse

        float accS[2][4][4] = {};
        mma_scores(bufX, accS);

        #pragma unroll
        for (int mt = 0; mt < 2; mt++)
            #pragma unroll
            for (int half = 0; half < 2; half++) {
                const int row = wm + mt * 16 + (lane >> 2) + half * 8;
                const int qi_r = q0 + row;
                float sv[8];
                float pm = -1e30f;
                #pragma unroll
                for (int nt = 0; nt < 4; nt++)
                    #pragma unroll
                    for (int e2 = 0; e2 < 2; e2++) {
                        const int col = wn + nt * 8 + (lane & 3) * 2 + e2;
                        const float s = accS[mt][nt][half * 2 + e2] * 0.125f;
                        sv[nt * 2 + e2] = (k0 + col <= qi_r) ? s : -1e30f;
                        pm = fmaxf(pm, sv[nt * 2 + e2]);
                    }
                float pl = 0.f;
                #pragma unroll
                for (int x = 0; x < 8; x++)
                    if (sv[x] > -1e29f) pl += acc_expf(sv[x] - pm);
                // merge across the 4 lanes sharing this row
                #pragma unroll
                for (int mm = 1; mm <= 2; mm <<= 1) {
                    const float om = __shfl_xor_sync(0xffffffffu, pm, mm);
                    const float ol = __shfl_xor_sync(0xffffffffu, pl, mm);
                    const float nm = fmaxf(pm, om);
                    pl = pl * acc_expf(pm - nm) + ol * acc_expf(om - nm);
                    pm = nm;
                }
                if ((lane & 3) == 0) {
                    partM[row * 2 + (wn >> 5)] = pm;
                    partL[row * 2 + (wn >> 5)] = pl;
                }
            }
        __syncthreads();
        if (tid < 128) {
            const float mA = partM[tid * 2], mB = partM[tid * 2 + 1];
            const float mt2 = fmaxf(mA, mB);
            const float lt = partL[tid * 2] * acc_expf(mA - mt2)
                           + partL[tid * 2 + 1] * acc_expf(mB - mt2);
            const float mn = fmaxf(m_old, mt2);
            l_old = l_old * acc_expf(m_old - mn) + lt * acc_expf(mt2 - mn);
            m_old = mn;
        }
    }
    if (tid < 128) { mfin[tid] = m_old; lfin[tid] = l_old; }

    // ---- phase C: recompute S (bit-identical), p = tf32(e/l), O += P V ------
    float accO[2][4][4] = {};
    issue_tile(kbase(0), KVa);
    for (int t = 0; t < ntiles; t++) {
        const int k0 = t * AK;
        float* bufX = (t & 1) ? KVb : KVa;
        float* bufY = (t & 1) ? KVa : KVb;
        __syncthreads();                          // prev PV done; mfin visible (t=0)
        if (t + 1 < ntiles) { issue_tile(kbase(k0 + AK), bufY); cp_wait1(); }
        else                { cp_wait0(); }
        __syncthreads();                          // K_t visible

        float accS[2][4][4] = {};
        mma_scores(bufX, accS);
        // fragment -> probabilities in SP
        #pragma unroll
        for (int mt = 0; mt < 2; mt++)
            #pragma unroll
            for (int half = 0; half < 2; half++) {
                const int row = wm + mt * 16 + (lane >> 2) + half * 8;
                const float mq = mfin[row];
                const float lq = lfin[row];
                #pragma unroll
                for (int nt = 0; nt < 4; nt++)
                    #pragma unroll
                    for (int e2 = 0; e2 < 2; e2++) {
                        const int col = wn + nt * 8 + (lane & 3) * 2 + e2;
                        float p = 0.f;
                        if (k0 + col <= q0 + row) {
                            const float s = accS[mt][nt][half * 2 + e2] * 0.125f;
                            p = tf32r(__fdiv_rn(acc_expf(s - mq), lq));
                        }
                        SP[row * QSTR + col] = p;
                    }
            }
        __syncthreads();                          // SP ready; bufX K reads done
        issue_tile(vbase(k0), bufX);              // V_t overwrites bufX
        cp_wait0();
        __syncthreads();                          // V_t visible
        // O += P V
        #pragma unroll
        for (int ks = 0; ks < 8; ks++) {
            const int kk = ks * 8 + (lane & 3);
            uint32_t a[2][4], b[4][2];
            #pragma unroll
            for (int mt = 0; mt < 2; mt++) {
                const int r = wm + mt * 16 + (lane >> 2);
                a[mt][0] = __float_as_uint(SP[r * QSTR + kk]);
                a[mt][1] = __float_as_uint(SP[(r + 8) * QSTR + kk]);
                a[mt][2] = __float_as_uint(SP[r * QSTR + kk + 4]);
                a[mt][3] = __float_as_uint(SP[(r + 8) * QSTR + kk + 4]);
            }
            #pragma unroll
            for (int nt = 0; nt < 4; nt++) {
                const int d = wn + nt * 8 + (lane >> 2);
                b[nt][0] = tf32u(bufX[kk * QSTR + d]);
                b[nt][1] = tf32u(bufX[(kk + 4) * QSTR + d]);
            }
            #pragma unroll
            for (int mt = 0; mt < 2; mt++)
                #pragma unroll
                for (int nt = 0; nt < 4; nt++)
                    asm volatile(
                        "mma.sync.aligned.m16n8k8.row.col.f32.tf32.tf32.f32 "
                        "{%0,%1,%2,%3}, {%4,%5,%6,%7}, {%8,%9}, {%0,%1,%2,%3};"
                        : "+f"(accO[mt][nt][0]), "+f"(accO[mt][nt][1]),
                          "+f"(accO[mt][nt][2]), "+f"(accO[mt][nt][3])
                        : "r"(a[mt][0]), "r"(a[mt][1]), "r"(a[mt][2]), "r"(a[mt][3]),
                          "r"(b[nt][0]), "r"(b[nt][1]));
        }
    }

    // write O
    #pragma unroll
    for (int mt = 0; mt < 2; mt++)
        #pragma unroll
        for (int half = 0; half < 2; half++) {
            const int row = q0 + wm + mt * 16 + (lane >> 2) + half * 8;
            #pragma unroll
            for (int nt = 0; nt < 4; nt++) {
                const int col = wn + nt * 8 + (lane & 3) * 2;
                float2 r2;
                r2.x = accO[mt][nt][half * 2 + 0];
                r2.y = accO[mt][nt][half * 2 + 1];
                *(float2*)(o + (size_t)row * H_ + h * HD_ + col) = r2;
            }
        }
}

// ---------------- router ----------------
__global__ void zero_k(int* __restrict__ c)
{
    if (threadIdx.x < E_) c[threadIdx.x] = 0;
}

__global__ void router_k(const float* __restrict__ x, const float* __restrict__ rw,
                         int* __restrict__ cnt, int* __restrict__ list,
                         float* __restrict__ wout)
{
    const int t = blockIdx.x;
    const int tid = threadIdx.x;
    const int e = tid >> 5, lane = tid & 31;
    const float* xr = x + (size_t)t * H_;
    float s = 0.f;
    for (int i = lane; i < H_; i += 32)
        s = __fmaf_rn(tf32r(xr[i]), tf32r(rw[i * E_ + e]), s);
    for (int off = 16; off; off >>= 1) s += __shfl_down_sync(0xffffffffu, s, off);
    __shared__ float logit[E_];
    if (!lane) logit[e] = s;
    __syncthreads();
    if (tid == 0) {
        float mx = logit[0];
        #pragma unroll
        for (int i = 1; i < E_; i++) mx = fmaxf(mx, logit[i]);
        float p[E_];
        #pragma unroll
        for (int i = 0; i < E_; i++) p[i] = acc_expf(logit[i] - mx);
        int i0 = 0;
        #pragma unroll
        for (int i = 1; i < E_; i++) if (p[i] > p[i0]) i0 = i;
        int i1 = (i0 == 0) ? 1 : 0;
        #pragma unroll
        for (int i = 0; i < E_; i++) if (i != i0 && p[i] > p[i1]) i1 = i;
        const float denom = p[i0] + p[i1];
        wout[2 * t + 0] = __fdiv_rn(p[i0], denom);
        wout[2 * t + 1] = __fdiv_rn(p[i1], denom);
        int pos = atomicAdd(&cnt[i0], 1);
        list[i0 * S_ + pos] = 2 * t;
        pos = atomicAdd(&cnt[i1], 1);
        list[i1 * S_ + pos] = 2 * t + 1;
    }
}

// ---------------- combine ----------------
__global__ void combine_k(float* __restrict__ out, const float* __restrict__ eo,
                          const float* __restrict__ w)
{
    const int t = blockIdx.x;
    const float w0 = w[2 * t], w1 = w[2 * t + 1];
    const float* e0 = eo + (size_t)(2 * t) * H_;
    const float* e1 = eo + (size_t)(2 * t + 1) * H_;
    float* orow = out + (size_t)t * H_;
    for (int i = threadIdx.x; i < H_; i += 256)
        orow[i] += __fmaf_rn(w0, e0[i], __fmul_rn(w1, e1[i]));
}

// ---------------- host launch --------------------------------------------------
extern "C" void kernel_launch(void* const* d_in, const int* in_sizes, int n_in,
                              void* d_out, int out_size)
{
    const float* hs  = (const float*)d_in[0];
    const float* ln1 = (const float*)d_in[1];
    const float* wq  = (const float*)d_in[2];
    const float* wk  = (const float*)d_in[3];
    const float* wv  = (const float*)d_in[4];
    const float* wo  = (const float*)d_in[5];
    const float* ln2 = (const float*)d_in[6];
    const float* sw1 = (const float*)d_in[7];
    const float* sw2 = (const float*)d_in[8];
    const float* ew1 = (const float*)d_in[9];
    const float* ew2 = (const float*)d_in[10];
    const float* rw  = (const float*)d_in[11];
    float* out = (float*)d_out;

    float *x1, *q, *k, *v, *att, *hid, *x2, *hsv, *hcol, *eo, *wts;
    int *cnt, *list;
    cudaGetSymbolAddress((void**)&x1,   g_x1);
    cudaGetSymbolAddress((void**)&q,    g_q);
    cudaGetSymbolAddress((void**)&k,    g_k);
    cudaGetSymbolAddress((void**)&v,    g_v);
    cudaGetSymbolAddress((void**)&att,  g_att);
    cudaGetSymbolAddress((void**)&hid,  g_hidden);
    cudaGetSymbolAddress((void**)&x2,   g_x2);
    cudaGetSymbolAddress((void**)&hsv,  g_hs);
    cudaGetSymbolAddress((void**)&hcol, g_hcol);
    cudaGetSymbolAddress((void**)&eo,   g_eo);
    cudaGetSymbolAddress((void**)&wts,  g_wts);
    cudaGetSymbolAddress((void**)&cnt,  g_cnt);
    cudaGetSymbolAddress((void**)&list, g_list);

    cudaFuncSetAttribute(mma_gemm_k<0,0,0,1,0>, cudaFuncAttributeMaxDynamicSharedMemorySize, SMEM_GEMM);
    cudaFuncSetAttribute(mma_gemm_k<2,0,0,0,0>, cudaFuncAttributeMaxDynamicSharedMemorySize, SMEM_GEMM);
    cudaFuncSetAttribute(mma_gemm_k<1,2,1,0,1>, cudaFuncAttributeMaxDynamicSharedMemorySize, SMEM_GEMM);
    cudaFuncSetAttribute(mma_gemm_k<0,2,0,0,2>, cudaFuncAttributeMaxDynamicSharedMemorySize, SMEM_GEMM);
    cudaFuncSetAttribute(attn_mma_k, cudaFuncAttributeMaxDynamicSharedMemorySize, SMEM_ATTN);

    // 1. rmsnorm1
    rmsnorm_k<<<S_, 256>>>(hs, ln1, x1);
    // 2. fused QKV projection
    mma_gemm_k<0,0,0,1,0><<<dim3(12, S_ / BM), 256, SMEM_GEMM>>>(
        x1, wq, q, nullptr, nullptr, nullptr, wk, wv, k, v, H_, H_);
    // 3. RoPE
    rope_k<<<(S_ * (NH_ + KVH_) * 32) / 256, 256>>>(q, k);
    // 4. attention
    attn_mma_k<<<dim3(S_ / AQ, NH_), 256, SMEM_ATTN>>>(q, k, v, att);
    // 5. O-proj + residual
    mma_gemm_k<2,0,0,0,0><<<dim3(H_ / BN, S_ / BM), 256, SMEM_GEMM>>>(
        att, wo, hid, hs, nullptr, nullptr, nullptr, nullptr, nullptr, nullptr, H_, H_);
    // 6. rmsnorm2
    rmsnorm_k<<<S_, 256>>>(hid, ln2, x2);
    // 7. router
    zero_k<<<1, 32>>>(cnt);
    router_k<<<S_, 256>>>(x2, rw, cnt, list, wts);
    // 8. fused shared-MLP-1 + expert-1 (z=0 shared, z=1..8 experts)
    mma_gemm_k<1,2,1,0,1><<<dim3(I_ / BN, S_ / BM, E_ + 1), 256, SMEM_GEMM>>>(
        x2, ew1, hcol, nullptr, list, cnt, sw1, x2, hsv, nullptr, I_, H_);
    // 9. fused shared-MLP-2 (+residual) + expert-2
    mma_gemm_k<0,2,0,0,2><<<dim3(H_ / BN, S_ / BM, E_ + 1), 256, SMEM_GEMM>>>(
        hcol, ew2, eo, hid, list, cnt, sw2, hsv, out, nullptr, H_, I_);
    // 10. combine
    combine_k<<<S_, 256>>>(out, eo, wts);
}

// round 11
// speedup vs baseline: 1.8110x; 1.0848x over previous
#include <cuda_runtime.h>
#include <cstdint>
#include <math.h>

#define S_   2048
#define H_   1024
#define NH_  16
#define KVH_ 4
#define HD_  64
#define E_   8
#define I_   4096

// ---------------- accurate math helpers ------------------
#ifdef __FAST_MATH__
__device__ __forceinline__ float acc_expf(float x) { return (float)exp((double)x); }
__device__ __forceinline__ float acc_cosf(float x) { return (float)cos((double)x); }
__device__ __forceinline__ float acc_sinf(float x) { return (float)sin((double)x); }
__device__ __forceinline__ float acc_powf(float a, float b) { return (float)pow((double)a, (double)b); }
#else
__device__ __forceinline__ float acc_expf(float x) { return expf(x); }
__device__ __forceinline__ float acc_cosf(float x) { return cosf(x); }
__device__ __forceinline__ float acc_sinf(float x) { return sinf(x); }
__device__ __forceinline__ float acc_powf(float a, float b) { return powf(a, b); }
#endif

__device__ __forceinline__ float tf32r(float x) {
    uint32_t u;
    asm("cvt.rna.tf32.f32 %0, %1;" : "=r"(u) : "f"(x));
    return __uint_as_float(u);
}
__device__ __forceinline__ uint32_t tf32u(float x) {
    uint32_t u;
    asm("cvt.rna.tf32.f32 %0, %1;" : "=r"(u) : "f"(x));
    return u;
}
__device__ __forceinline__ float4 tf32r4(float4 v) {
    v.x = tf32r(v.x); v.y = tf32r(v.y); v.z = tf32r(v.z); v.w = tf32r(v.w);
    return v;
}
__device__ __forceinline__ float silu_f(float v) {
    return __fdiv_rn(v, 1.0f + acc_expf(-v));
}

__device__ __forceinline__ uint32_t s2u(const void* p) {
    return (uint32_t)__cvta_generic_to_shared(p);
}
__device__ __forceinline__ void cp16(uint32_t dst, const float* src) {
    asm volatile("cp.async.ca.shared.global [%0], [%1], 16;\n" :: "r"(dst), "l"(src));
}
__device__ __forceinline__ void cp_commit() {
    asm volatile("cp.async.commit_group;\n" ::);
}
__device__ __forceinline__ void cp_wait1() {
    asm volatile("cp.async.wait_group 1;\n" ::);
}
__device__ __forceinline__ void cp_wait0() {
    asm volatile("cp.async.wait_group 0;\n" ::);
}

// ---------------- scratch ----------------
__device__ float g_x1[S_*H_];
__device__ float g_q[S_*H_];
__device__ float g_k[S_*KVH_*HD_];
__device__ float g_v[S_*KVH_*HD_];
__device__ float g_att[S_*H_];
__device__ float g_attP[S_*H_];
__device__ float g_ml[NH_*16*2*256];   // [h][qt][s][{m:0-127, l:128-255}]
__device__ float g_hidden[S_*H_];
__device__ float g_x2[S_*H_];
__device__ float g_hs[S_*I_];
__device__ float g_hcol[(S_*2)*I_];
__device__ float g_eo[(S_*2)*H_];
__device__ int   g_cnt[E_];
__device__ int   g_list[E_*S_];
__device__ float g_wts[S_*2];

// ---------------- TF32 tensor-core GEMM, 3-stage cp.async ----------------
#define BM  128
#define BN  128
#define BKT 16
#define NST 3
#define ASTR 20
#define BSTR 136
#define SMEM_GEMM ((NST*BM*ASTR + NST*BKT*BSTR) * 4)

template<int EPI, int MODE, int SHIFT, int QKV, int EPI2>
__global__ void __launch_bounds__(256, 2) mma_gemm_k(
    const float* __restrict__ A, const float* __restrict__ B,
    float* __restrict__ C, const float* __restrict__ R,
    const int* __restrict__ list, const int* __restrict__ cnt,
    const float* __restrict__ B2, const float* __restrict__ B3,
    float* __restrict__ C2, float* __restrict__ C3,
    int N, int K)
{
    extern __shared__ float dsm[];
    float* As = dsm;
    float* Bs = dsm + NST * BM * ASTR;

    int n_rows = S_;
    const float* Az = A;
    const float* Bz = B;
    float* Cz = C;
    bool gat = (MODE == 1);
    int zoff = 0;
    int Nl = N;
    int n0 = blockIdx.x * BN;
    if (MODE == 1) {
        const int z = blockIdx.z;
        n_rows = cnt[z];
        if ((int)blockIdx.y * BM >= n_rows) return;
        zoff = z * S_;
        Bz = B + (size_t)z * K * N;
    }
    if (MODE == 2) {
        const int z = blockIdx.z;
        if (z == 0) {
            Az = B3; Bz = B2; Cz = C2; gat = false;
        } else {
            const int e = z - 1;
            n_rows = cnt[e];
            if ((int)blockIdx.y * BM >= n_rows) return;
            zoff = e * S_;
            Bz = B + (size_t)e * K * N;
            gat = true;
        }
    }
    if (QKV) {
        const int bx = blockIdx.x;
        if (bx < 8)       { Bz = B;  Cz = C;  Nl = 1024; n0 = bx * BN; }
        else if (bx < 10) { Bz = B2; Cz = C2; Nl = 256;  n0 = (bx - 8) * BN; }
        else              { Bz = B3; Cz = C3; Nl = 256;  n0 = (bx - 10) * BN; }
    }

    const int tid  = threadIdx.x;
    const int lane = tid & 31;
    const int wid  = tid >> 5;
    const int wm   = (wid & 1) * 64;
    const int wn   = (wid >> 1) * 32;
    const int m0   = blockIdx.y * BM;

    const int aIdx0 = tid, aIdx1 = tid + 256;
    const int r0 = m0 + (aIdx0 >> 2), r1 = m0 + (aIdx1 >> 2);
    int gar0 = r0, gar1 = r1;
    if (gat) {
        gar0 = (r0 < n_rows) ? (list[zoff + r0] >> SHIFT) : 0;
        gar1 = (r1 < n_rows) ? (list[zoff + r1] >> SHIFT) : 0;
    }
    const float* Ag0 = Az + (size_t)gar0 * K + (aIdx0 & 3) * 4;
    const float* Ag1 = Az + (size_t)gar1 * K + (aIdx1 & 3) * 4;
    const float* Bg0 = Bz + (size_t)(tid >> 5) * Nl + n0 + (tid & 31) * 4;
    const float* Bg1 = Bg0 + (size_t)8 * Nl;

    const uint32_t sa0 = s2u(&As[(size_t)(aIdx0 >> 2) * ASTR + (aIdx0 & 3) * 4]);
    const uint32_t sa1 = s2u(&As[(size_t)(aIdx1 >> 2) * ASTR + (aIdx1 & 3) * 4]);
    const uint32_t sb0 = s2u(&Bs[(size_t)(tid >> 5) * BSTR + (tid & 31) * 4]);
    const uint32_t sb1 = s2u(&Bs[(size_t)((tid >> 5) + 8) * BSTR + (tid & 31) * 4]);
    const uint32_t aStgB = BM * ASTR * 4;
    const uint32_t bStgB = BKT * BSTR * 4;

    float acc[4][4][4] = {};
    const int nk = K / BKT;

    auto load_stage = [&](int sbuf, int c) {
        const int k0 = c * BKT;
        cp16(sa0 + sbuf * aStgB, Ag0 + k0);
        cp16(sa1 + sbuf * aStgB, Ag1 + k0);
        cp16(sb0 + sbuf * bStgB, Bg0 + (size_t)k0 * Nl);
        cp16(sb1 + sbuf * bStgB, Bg1 + (size_t)k0 * Nl);
        cp_commit();
    };

    load_stage(0, 0);
    load_stage(1, 1);

    for (int c = 0; c < nk; c++) {
        cp_wait1();
        __syncthreads();
        const int buf = c % NST;
        if (c + NST - 1 < nk) load_stage((c + NST - 1) % NST, c + NST - 1);

        const float* Ab = As + (size_t)buf * BM * ASTR;
        const float* Bb = Bs + (size_t)buf * BKT * BSTR;
        #pragma unroll
        for (int ks = 0; ks < 2; ks++) {
            const int kk = ks * 8 + (lane & 3);
            uint32_t a[4][4], b[4][2];
            #pragma unroll
            for (int mt = 0; mt < 4; mt++) {
                const int m = wm + mt * 16 + (lane >> 2);
                a[mt][0] = tf32u(Ab[(size_t)m * ASTR + kk]);
                a[mt][1] = tf32u(Ab[(size_t)(m + 8) * ASTR + kk]);
                a[mt][2] = tf32u(Ab[(size_t)m * ASTR + kk + 4]);
                a[mt][3] = tf32u(Ab[(size_t)(m + 8) * ASTR + kk + 4]);
            }
            #pragma unroll
            for (int nt = 0; nt < 4; nt++) {
                const int nn = wn + nt * 8 + (lane >> 2);
                b[nt][0] = tf32u(Bb[(size_t)kk * BSTR + nn]);
                b[nt][1] = tf32u(Bb[(size_t)(kk + 4) * BSTR + nn]);
            }
            #pragma unroll
            for (int mt = 0; mt < 4; mt++)
                #pragma unroll
                for (int nt = 0; nt < 4; nt++)
                    asm volatile(
                        "mma.sync.aligned.m16n8k8.row.col.f32.tf32.tf32.f32 "
                        "{%0,%1,%2,%3}, {%4,%5,%6,%7}, {%8,%9}, {%0,%1,%2,%3};"
                        : "+f"(acc[mt][nt][0]), "+f"(acc[mt][nt][1]),
                          "+f"(acc[mt][nt][2]), "+f"(acc[mt][nt][3])
                        : "r"(a[mt][0]), "r"(a[mt][1]), "r"(a[mt][2]), "r"(a[mt][3]),
                          "r"(b[nt][0]), "r"(b[nt][1]));
        }
    }

    const bool sharedSide = (MODE == 2) && (blockIdx.z == 0);
    #pragma unroll
    for (int mt = 0; mt < 4; mt++) {
        #pragma unroll
        for (int half = 0; half < 2; half++) {
            const int r = m0 + wm + mt * 16 + (lane >> 2) + half * 8;
            if (gat && r >= n_rows) continue;
            size_t crow_idx = r;
            if (gat) crow_idx = (size_t)list[zoff + r];
            float* crow = Cz + crow_idx * Nl;
            const int epi = sharedSide ? EPI2 : EPI;
            #pragma unroll
            for (int nt = 0; nt < 4; nt++) {
                const int col = n0 + wn + nt * 8 + (lane & 3) * 2;
                float2 v;
                v.x = acc[mt][nt][half * 2 + 0];
                v.y = acc[mt][nt][half * 2 + 1];
                if (epi == 1) {
                    v.x = silu_f(v.x); v.y = silu_f(v.y);
                } else if (epi == 2) {
                    const float2 rr = *(const float2*)(R + crow_idx * Nl + col);
                    v.x += rr.x; v.y += rr.y;
                }
                *(float2*)(crow + col) = v;
            }
        }
    }
}

// ---------------- RMSNorm ----------------
__global__ void rmsnorm_k(const float* __restrict__ x, const float* __restrict__ w,
                          float* __restrict__ o)
{
    const int t = blockIdx.x;
    const int tid = threadIdx.x;
    const float* xr = x + (size_t)t * H_;
    float s = 0.f;
    for (int i = tid; i < H_; i += 256) { float v = xr[i]; s = __fmaf_rn(v, v, s); }
    for (int off = 16; off; off >>= 1) s += __shfl_down_sync(0xffffffffu, s, off);
    __shared__ float red[8];
    const int wid = tid >> 5, lane = tid & 31;
    if (!lane) red[wid] = s;
    __syncthreads();
    if (tid == 0) {
        float tot = 0.f;
        #pragma unroll
        for (int i = 0; i < 8; i++) tot += red[i];
        red[0] = rsqrtf(tot * (1.0f / H_) + 1e-6f);
    }
    __syncthreads();
    const float r = red[0];
    float* orow = o + (size_t)t * H_;
    for (int i = tid; i < H_; i += 256) orow[i] = w[i] * (xr[i] * r);
}

// ---------------- RoPE ----------------
__global__ void rope_k(float* __restrict__ q, float* __restrict__ k)
{
    const int idx = blockIdx.x * blockDim.x + threadIdx.x;
    const int half = idx & 31;
    const int rest = idx >> 5;
    const int head = rest % (NH_ + KVH_);
    const int t = rest / (NH_ + KVH_);
    const float inv_freq = __fdiv_rn(1.0f, acc_powf(10000.0f, (float)half * 0.03125f));
    const float ang = __fmul_rn((float)t, inv_freq);
    const float c = acc_cosf(ang);
    const float sn = acc_sinf(ang);
    float* base = (head < NH_) ? (q + (size_t)t * H_ + head * HD_)
                               : (k + (size_t)t * (KVH_ * HD_) + (head - NH_) * HD_);
    const float x1 = base[half];
    const float x2 = base[half + 32];
    base[half]      = __fadd_rn(__fmul_rn(x1, c), -__fmul_rn(x2, sn));
    base[half + 32] = __fadd_rn(__fmul_rn(x2, c),  __fmul_rn(x1, sn));
}

// ---- Attention: split-K two-pass MMA ----------------------------------------
#define AQ 128
#define AK 64
#define QSTR 68
#define SMEM_ATTN_A ((AQ*QSTR + 2*AK*QSTR + 512) * 4)
#define SMEM_ATTN_C ((2*AQ*QSTR + 2*AK*QSTR + 2*AQ) * 4)

__device__ __forceinline__ void attn_issue_tile(const float* gbase, float* sbuf, int tid) {
    #pragma unroll
    for (int s = 0; s < 4; s++) {
        const int i = tid + s * 256;
        const int j = i >> 4, d4 = (i & 15) * 4;
        cp16(s2u(&sbuf[j * QSTR + d4]), gbase + (size_t)j * (KVH_ * HD_) + d4);
    }
    cp_commit();
}

__device__ __forceinline__ void attn_mma_scores(
    const float* __restrict__ Qs, const float* __restrict__ KB,
    float accS[2][4][4], int lane, int wm, int wn)
{
    #pragma unroll
    for (int ks = 0; ks < 8; ks++) {
        const int kk = ks * 8 + (lane & 3);
        uint32_t a[2][4], b[4][2];
        #pragma unroll
        for (int mt = 0; mt < 2; mt++) {
            const int r = wm + mt * 16 + (lane >> 2);
            a[mt][0] = __float_as_uint(Qs[r * QSTR + kk]);
            a[mt][1] = __float_as_uint(Qs[(r + 8) * QSTR + kk]);
            a[mt][2] = __float_as_uint(Qs[r * QSTR + kk + 4]);
            a[mt][3] = __float_as_uint(Qs[(r + 8) * QSTR + kk + 4]);
        }
        #pragma unroll
        for (int nt = 0; nt < 4; nt++) {
            const int j = wn + nt * 8 + (lane >> 2);
            b[nt][0] = tf32u(KB[j * QSTR + kk]);
            b[nt][1] = tf32u(KB[j * QSTR + kk + 4]);
        }
        #pragma unroll
        for (int mt = 0; mt < 2; mt++)
            #pragma unroll
            for (int nt = 0; nt < 4; nt++)
                asm volatile(
                    "mma.sync.aligned.m16n8k8.row.col.f32.tf32.tf32.f32 "
                    "{%0,%1,%2,%3}, {%4,%5,%6,%7}, {%8,%9}, {%0,%1,%2,%3};"
                    : "+f"(accS[mt][nt][0]), "+f"(accS[mt][nt][1]),
                      "+f"(accS[mt][nt][2]), "+f"(accS[mt][nt][3])
                    : "r"(a[mt][0]), "r"(a[mt][1]), "r"(a[mt][2]), "r"(a[mt][3]),
                      "r"(b[nt][0]), "r"(b[nt][1]));
    }
}

// phase A: partial (m, l) for key-split s of q-tile qt
__global__ void __launch_bounds__(256, 2) attn_a_k(
    const float* __restrict__ q, const float* __restrict__ k,
    float* __restrict__ ml)
{
    extern __shared__ float sm[];
    float* Qs    = sm;
    float* KVa   = Qs + AQ * QSTR;
    float* KVb   = KVa + AK * QSTR;
    float* partM = KVb + AK * QSTR;   // [128][2]
    float* partL = partM + 256;

    const int h  = blockIdx.y;
    const int bx = blockIdx.x;            // 0..31, heavy qt first
    const int qt = 15 - (bx >> 1);
    const int sp = bx & 1;
    const int q0 = qt * AQ;
    const int tid = threadIdx.x;
    const int lane = tid & 31, wid = tid >> 5;
    const int kvh = h >> 2;
    const int halfT = qt + 1;
    const int ts = sp * halfT, te = ts + halfT;
    const int wm = (wid & 3) * 32, wn = (wid >> 2) * 32;

    const float* kb = k + kvh * HD_;
    attn_issue_tile(kb + (size_t)(ts * AK) * (KVH_ * HD_), KVa, tid);
    for (int i = tid; i < AQ * (HD_ / 4); i += 256) {
        const int qq = i >> 4, d4 = (i & 15) * 4;
        *(float4*)&Qs[qq * QSTR + d4] =
            tf32r4(*(const float4*)(q + (size_t)(q0 + qq) * H_ + h * HD_ + d4));
    }

    float m_old = -1e30f, l_old = 0.f;
    for (int t = ts; t < te; t++) {
        const int k0 = t * AK;
        float* bufX = ((t - ts) & 1) ? KVb : KVa;
        float* bufY = ((t - ts) & 1) ? KVa : KVb;
        if (t + 1 < te) { attn_issue_tile(kb + (size_t)(k0 + AK) * (KVH_ * HD_), bufY, tid); cp_wait1(); }
        else            { cp_wait0(); }
        __syncthreads();

        float accS[2][4][4] = {};
        attn_mma_scores(Qs, bufX, accS, lane, wm, wn);

        #pragma unroll
        for (int mt = 0; mt < 2; mt++)
            #pragma unroll
            for (int half = 0; half < 2; half++) {
                const int row = wm + mt * 16 + (lane >> 2) + half * 8;
                const int qi_r = q0 + row;
                float sv[8];
                float pm = -1e30f;
                #pragma unroll
                for (int nt = 0; nt < 4; nt++)
                    #pragma unroll
                    for (int e2 = 0; e2 < 2; e2++) {
                        const int col = wn + nt * 8 + (lane & 3) * 2 + e2;
                        const float s = accS[mt][nt][half * 2 + e2] * 0.125f;
                        sv[nt * 2 + e2] = (k0 + col <= qi_r) ? s : -1e30f;
                        pm = fmaxf(pm, sv[nt * 2 + e2]);
                    }
                float pl = 0.f;
                #pragma unroll
                for (int x = 0; x < 8; x++)
                    if (sv[x] > -1e29f) pl += acc_expf(sv[x] - pm);
                #pragma unroll
                for (int mm = 1; mm <= 2; mm <<= 1) {
                    const float om = __shfl_xor_sync(0xffffffffu, pm, mm);
                    const float ol = __shfl_xor_sync(0xffffffffu, pl, mm);
                    const float nm = fmaxf(pm, om);
                    pl = pl * acc_expf(pm - nm) + ol * acc_expf(om - nm);
                    pm = nm;
                }
                if ((lane & 3) == 0) {
                    partM[row * 2 + (wn >> 5)] = pm;
                    partL[row * 2 + (wn >> 5)] = pl;
                }
            }
        __syncthreads();
        if (tid < 128) {
            const float mA = partM[tid * 2], mB = partM[tid * 2 + 1];
            const float mt2 = fmaxf(mA, mB);
            const float lt = partL[tid * 2] * acc_expf(mA - mt2)
                           + partL[tid * 2 + 1] * acc_expf(mB - mt2);
            const float mn = fmaxf(m_old, mt2);
            l_old = l_old * acc_expf(m_old - mn) + lt * acc_expf(mt2 - mn);
            m_old = mn;
        }
    }
    if (tid < 128) {
        const int base = ((h * 16 + qt) * 2 + sp) * 256;
        ml[base + tid]       = m_old;
        ml[base + 128 + tid] = l_old;
    }
}

// phase C: merged (m,l) -> partial O for key-split s
__global__ void __launch_bounds__(256, 2) attn_c_k(
    const float* __restrict__ q, const float* __restrict__ k,
    const float* __restrict__ v, const float* __restrict__ ml,
    float* __restrict__ o0, float* __restrict__ o1)
{
    extern __shared__ float sm[];
    float* Qs   = sm;
    float* SP   = Qs + AQ * QSTR;
    float* KVa  = SP + AQ * QSTR;
    float* KVb  = KVa + AK * QSTR;
    float* mfin = KVb + AK * QSTR;
    float* lfin = mfin + AQ;

    const int h  = blockIdx.y;
    const int bx = blockIdx.x;
    const int qt = 15 - (bx >> 1);
    const int sp = bx & 1;
    const int q0 = qt * AQ;
    const int tid = threadIdx.x;
    const int lane = tid & 31, wid = tid >> 5;
    const int kvh = h >> 2;
    const int halfT = qt + 1;
    const int ts = sp * halfT, te = ts + halfT;
    const int wm = (wid & 3) * 32, wn = (wid >> 2) * 32;

    const float* kb = k + kvh * HD_;
    const float* vb = v + kvh * HD_;
    attn_issue_tile(kb + (size_t)(ts * AK) * (KVH_ * HD_), KVa, tid);

    // merge the two split partials (deterministic, fixed association)
    if (tid < 128) {
        const int b = (h * 16 + qt) * 2 * 256;
        const float mA = ml[b + tid],       lA = ml[b + 128 + tid];
        const float mB = ml[b + 256 + tid], lB = ml[b + 384 + tid];
        const float mq = fmaxf(mA, mB);
        mfin[tid] = mq;
        lfin[tid] = lA * acc_expf(mA - mq) + lB * acc_expf(mB - mq);
    }
    for (int i = tid; i < AQ * (HD_ / 4); i += 256) {
        const int qq = i >> 4, d4 = (i & 15) * 4;
        *(float4*)&Qs[qq * QSTR + d4] =
            tf32r4(*(const float4*)(q + (size_t)(q0 + qq) * H_ + h * HD_ + d4));
    }

    float accO[2][4][4] = {};
    for (int t = ts; t < te; t++) {
        const int k0 = t * AK;
        float* bufX = ((t - ts) & 1) ? KVb : KVa;
        float* bufY = ((t - ts) & 1) ? KVa : KVb;
        __syncthreads();                  // prev PV done; mfin/Qs ready at t=ts
        if (t + 1 < te) { attn_issue_tile(kb + (size_t)(k0 + AK) * (KVH_ * HD_), bufY, tid); cp_wait1(); }
        else            { cp_wait0(); }
        __syncthreads();                  // K_t visible

        float accS[2][4][4] = {};
        attn_mma_scores(Qs, bufX, accS, lane, wm, wn);
        __syncthreads();                  // all warps done reading K_t
        attn_issue_tile(vb + (size_t)k0 * (KVH_ * HD_), bufX, tid);  // V_t -> bufX (overlaps conv)

        #pragma unroll
        for (int mt = 0; mt < 2; mt++)
            #pragma unroll
            for (int half = 0; half < 2; half++) {
                const int row = wm + mt * 16 + (lane >> 2) + half * 8;
                const float mq = mfin[row];
                const float lq = lfin[row];
                #pragma unroll
                for (int nt = 0; nt < 4; nt++)
                    #pragma unroll
                    for (int e2 = 0; e2 < 2; e2++) {
                        const int col = wn + nt * 8 + (lane & 3) * 2 + e2;
                        float p = 0.f;
                        if (k0 + col <= q0 + row) {
                            const float s = accS[mt][nt][half * 2 + e2] * 0.125f;
                            p = tf32r(__fdiv_rn(acc_expf(s - mq), lq));
                        }
                        SP[row * QSTR + col] = p;
                    }
            }
        cp_wait0();
        __syncthreads();                  // SP + V_t visible

        #pragma unroll
        for (int ks = 0; ks < 8; ks++) {
            const int kk = ks * 8 + (lane & 3);
            uint32_t a[2][4], b[4][2];
            #pragma unroll
            for (int mt = 0; mt < 2; mt++) {
                const int r = wm + mt * 16 + (lane >> 2);
                a[mt][0] = __float_as_uint(SP[r * QSTR + kk]);
                a[mt][1] = __float_as_uint(SP[(r + 8) * QSTR + kk]);
                a[mt][2] = __float_as_uint(SP[r * QSTR + kk + 4]);
                a[mt][3] = __float_as_uint(SP[(r + 8) * QSTR + kk + 4]);
            }
            #pragma unroll
            for (int nt = 0; nt < 4; nt++) {
                const int d = wn + nt * 8 + (lane >> 2);
                b[nt][0] = tf32u(bufX[kk * QSTR + d]);
                b[nt][1] = tf32u(bufX[(kk + 4) * QSTR + d]);
            }
            #pragma unroll
            for (int mt = 0; mt < 2; mt++)
                #pragma unroll
                for (int nt = 0; nt < 4; nt++)
                    asm volatile(
                        "mma.sync.aligned.m16n8k8.row.col.f32.tf32.tf32.f32 "
                        "{%0,%1,%2,%3}, {%4,%5,%6,%7}, {%8,%9}, {%0,%1,%2,%3};"
                        : "+f"(accO[mt][nt][0]), "+f"(accO[mt][nt][1]),
                          "+f"(accO[mt][nt][2]), "+f"(accO[mt][nt][3])
                        : "r"(a[mt][0]), "r"(a[mt][1]), "r"(a[mt][2]), "r"(a[mt][3]),
                          "r"(b[nt][0]), "r"(b[nt][1]));
        }
    }

    float* od = sp ? o1 : o0;
    #pragma unroll
    for (int mt = 0; mt < 2; mt++)
        #pragma unroll
        for (int half = 0; half < 2; half++) {
            const int row = q0 + wm + mt * 16 + (lane >> 2) + half * 8;
            #pragma unroll
            for (int nt = 0; nt < 4; nt++) {
                const int col = wn + nt * 8 + (lane & 3) * 2;
                float2 r2;
                r2.x = accO[mt][nt][half * 2 + 0];
                r2.y = accO[mt][nt][half * 2 + 1];
                *(float2*)(od + (size_t)row * H_ + h * HD_ + col) = r2;
            }
        }
}

// att += attP  (2-term fp32 add, fixed order, deterministic)
__global__ void addO_k(float* __restrict__ a, const float* __restrict__ b)
{
    const size_t i = ((size_t)blockIdx.x * 256 + threadIdx.x) * 4;
    float4 x = *(float4*)(a + i);
    const float4 y = *(const float4*)(b + i);
    x.x += y.x; x.y += y.y; x.z += y.z; x.w += y.w;
    *(float4*)(a + i) = x;
}

// ---------------- router ----------------
__global__ void zero_k(int* __restrict__ c)
{
    if (threadIdx.x < E_) c[threadIdx.x] = 0;
}

__global__ void router_k(const float* __restrict__ x, const float* __restrict__ rw,
                         int* __restrict__ cnt, int* __restrict__ list,
                         float* __restrict__ wout)
{
    const int t = blockIdx.x;
    const int tid = threadIdx.x;
    const int e = tid >> 5, lane = tid & 31;
    const float* xr = x + (size_t)t * H_;
    float s = 0.f;
    for (int i = lane; i < H_; i += 32)
        s = __fmaf_rn(tf32r(xr[i]), tf32r(rw[i * E_ + e]), s);
    for (int off = 16; off; off >>= 1) s += __shfl_down_sync(0xffffffffu, s, off);
    __shared__ float logit[E_];
    if (!lane) logit[e] = s;
    __syncthreads();
    if (tid == 0) {
        float mx = logit[0];
        #pragma unroll
        for (int i = 1; i < E_; i++) mx = fmaxf(mx, logit[i]);
        float p[E_];
        #pragma unroll
        for (int i = 0; i < E_; i++) p[i] = acc_expf(logit[i] - mx);
        int i0 = 0;
        #pragma unroll
        for (int i = 1; i < E_; i++) if (p[i] > p[i0]) i0 = i;
        int i1 = (i0 == 0) ? 1 : 0;
        #pragma unroll
        for (int i = 0; i < E_; i++) if (i != i0 && p[i] > p[i1]) i1 = i;
        const float denom = p[i0] + p[i1];
        wout[2 * t + 0] = __fdiv_rn(p[i0], denom);
        wout[2 * t + 1] = __fdiv_rn(p[i1], denom);
        int pos = atomicAdd(&cnt[i0], 1);
        list[i0 * S_ + pos] = 2 * t;
        pos = atomicAdd(&cnt[i1], 1);
        list[i1 * S_ + pos] = 2 * t + 1;
    }
}

// ---------------- combine ----------------
__global__ void combine_k(float* __restrict__ out, const float* __restrict__ eo,
                          const float* __restrict__ w)
{
    const int t = blockIdx.x;
    const float w0 = w[2 * t], w1 = w[2 * t + 1];
    const float* e0 = eo + (size_t)(2 * t) * H_;
    const float* e1 = eo + (size_t)(2 * t + 1) * H_;
    float* orow = out + (size_t)t * H_;
    for (int i = threadIdx.x; i < H_; i += 256)
        orow[i] += __fmaf_rn(w0, e0[i], __fmul_rn(w1, e1[i]));
}

// ---------------- host launch --------------------------------------------------
extern "C" void kernel_launch(void* const* d_in, const int* in_sizes, int n_in,
                              void* d_out, int out_size)
{
    const float* hs  = (const float*)d_in[0];
    const float* ln1 = (const float*)d_in[1];
    const float* wq  = (const float*)d_in[2];
    const float* wk  = (const float*)d_in[3];
    const float* wv  = (const float*)d_in[4];
    const float* wo  = (const float*)d_in[5];
    const float* ln2 = (const float*)d_in[6];
    const float* sw1 = (const float*)d_in[7];
    const float* sw2 = (const float*)d_in[8];
    const float* ew1 = (const float*)d_in[9];
    const float* ew2 = (const float*)d_in[10];
    const float* rw  = (const float*)d_in[11];
    float* out = (float*)d_out;

    float *x1, *q, *k, *v, *att, *attP, *mlb, *hid, *x2, *hsv, *hcol, *eo, *wts;
    int *cnt, *list;
    cudaGetSymbolAddress((void**)&x1,   g_x1);
    cudaGetSymbolAddress((void**)&q,    g_q);
    cudaGetSymbolAddress((void**)&k,    g_k);
    cudaGetSymbolAddress((void**)&v,    g_v);
    cudaGetSymbolAddress((void**)&att,  g_att);
    cudaGetSymbolAddress((void**)&attP, g_attP);
    cudaGetSymbolAddress((void**)&mlb,  g_ml);
    cudaGetSymbolAddress((void**)&hid,  g_hidden);
    cudaGetSymbolAddress((void**)&x2,   g_x2);
    cudaGetSymbolAddress((void**)&hsv,  g_hs);
    cudaGetSymbolAddress((void**)&hcol, g_hcol);
    cudaGetSymbolAddress((void**)&eo,   g_eo);
    cudaGetSymbolAddress((void**)&wts,  g_wts);
    cudaGetSymbolAddress((void**)&cnt,  g_cnt);
    cudaGetSymbolAddress((void**)&list, g_list);

    cudaFuncSetAttribute(mma_gemm_k<0,0,0,1,0>, cudaFuncAttributeMaxDynamicSharedMemorySize, SMEM_GEMM);
    cudaFuncSetAttribute(mma_gemm_k<2,0,0,0,0>, cudaFuncAttributeMaxDynamicSharedMemorySize, SMEM_GEMM);
    cudaFuncSetAttribute(mma_gemm_k<1,2,1,0,1>, cudaFuncAttributeMaxDynamicSharedMemorySize, SMEM_GEMM);
    cudaFuncSetAttribute(mma_gemm_k<0,2,0,0,2>, cudaFuncAttributeMaxDynamicSharedMemorySize, SMEM_GEMM);
    cudaFuncSetAttribute(attn_a_k, cudaFuncAttributeMaxDynamicSharedMemorySize, SMEM_ATTN_A);
    cudaFuncSetAttribute(attn_c_k, cudaFuncAttributeMaxDynamicSharedMemorySize, SMEM_ATTN_C);

    // 1. rmsnorm1
    rmsnorm_k<<<S_, 256>>>(hs, ln1, x1);
    // 2. fused QKV projection
    mma_gemm_k<0,0,0,1,0><<<dim3(12, S_ / BM), 256, SMEM_GEMM>>>(
        x1, wq, q, nullptr, nullptr, nullptr, wk, wv, k, v, H_, H_);
    // 3. RoPE
    rope_k<<<(S_ * (NH_ + KVH_) * 32) / 256, 256>>>(q, k);
    // 4. attention: split-K two-pass
    attn_a_k<<<dim3(32, NH_), 256, SMEM_ATTN_A>>>(q, k, mlb);
    attn_c_k<<<dim3(32, NH_), 256, SMEM_ATTN_C>>>(q, k, v, mlb, att, attP);
    addO_k<<<(S_ * H_) / 1024, 256>>>(att, attP);
    // 5. O-proj + residual
    mma_gemm_k<2,0,0,0,0><<<dim3(H_ / BN, S_ / BM), 256, SMEM_GEMM>>>(
        att, wo, hid, hs, nullptr, nullptr, nullptr, nullptr, nullptr, nullptr, H_, H_);
    // 6. rmsnorm2
    rmsnorm_k<<<S_, 256>>>(hid, ln2, x2);
    // 7. router
    zero_k<<<1, 32>>>(cnt);
    router_k<<<S_, 256>>>(x2, rw, cnt, list, wts);
    // 8. fused shared-MLP-1 + expert-1
    mma_gemm_k<1,2,1,0,1><<<dim3(I_ / BN, S_ / BM, E_ + 1), 256, SMEM_GEMM>>>(
        x2, ew1, hcol, nullptr, list, cnt, sw1, x2, hsv, nullptr, I_, H_);
    // 9. fused shared-MLP-2 (+residual) + expert-2
    mma_gemm_k<0,2,0,0,2><<<dim3(H_ / BN, S_ / BM, E_ + 1), 256, SMEM_GEMM>>>(
        hcol, ew2, eo, hid, list, cnt, sw2, hsv, out, nullptr, H_, I_);
    // 10. combine
    combine_k<<<S_, 256>>>(out, eo, wts);
}

// round 12
// speedup vs baseline: 1.8795x; 1.0378x over previous
#include <cuda_runtime.h>
#include <cstdint>
#include <math.h>

#define S_   2048
#define H_   1024
#define NH_  16
#define KVH_ 4
#define HD_  64
#define E_   8
#define I_   4096

// ---------------- accurate math helpers ------------------
#ifdef __FAST_MATH__
__device__ __forceinline__ float acc_expf(float x) { return (float)exp((double)x); }
__device__ __forceinline__ float acc_cosf(float x) { return (float)cos((double)x); }
__device__ __forceinline__ float acc_sinf(float x) { return (float)sin((double)x); }
__device__ __forceinline__ float acc_powf(float a, float b) { return (float)pow((double)a, (double)b); }
#else
__device__ __forceinline__ float acc_expf(float x) { return expf(x); }
__device__ __forceinline__ float acc_cosf(float x) { return cosf(x); }
__device__ __forceinline__ float acc_sinf(float x) { return sinf(x); }
__device__ __forceinline__ float acc_powf(float a, float b) { return powf(a, b); }
#endif

__device__ __forceinline__ float tf32r(float x) {
    uint32_t u;
    asm("cvt.rna.tf32.f32 %0, %1;" : "=r"(u) : "f"(x));
    return __uint_as_float(u);
}
__device__ __forceinline__ uint32_t tf32u(float x) {
    uint32_t u;
    asm("cvt.rna.tf32.f32 %0, %1;" : "=r"(u) : "f"(x));
    return u;
}
__device__ __forceinline__ float4 tf32r4(float4 v) {
    v.x = tf32r(v.x); v.y = tf32r(v.y); v.z = tf32r(v.z); v.w = tf32r(v.w);
    return v;
}
__device__ __forceinline__ float silu_f(float v) {
    return __fdiv_rn(v, 1.0f + acc_expf(-v));
}

__device__ __forceinline__ uint32_t s2u(const void* p) {
    return (uint32_t)__cvta_generic_to_shared(p);
}
__device__ __forceinline__ void cp16(uint32_t dst, const float* src) {
    asm volatile("cp.async.ca.shared.global [%0], [%1], 16;\n" :: "r"(dst), "l"(src));
}
__device__ __forceinline__ void cp_commit() {
    asm volatile("cp.async.commit_group;\n" ::);
}
__device__ __forceinline__ void cp_wait1() {
    asm volatile("cp.async.wait_group 1;\n" ::);
}
__device__ __forceinline__ void cp_wait0() {
    asm volatile("cp.async.wait_group 0;\n" ::);
}

// ---------------- scratch ----------------
__device__ float g_x1[S_*H_];
__device__ float g_q[S_*H_];
__device__ float g_k[S_*KVH_*HD_];
__device__ float g_v[S_*KVH_*HD_];
__device__ float g_att[S_*H_];
__device__ float g_attP[S_*H_];
__device__ float g_ml[NH_*16*2*256];   // [h][qt][s][{m:0-127, l:128-255}]
__device__ float g_hidden[S_*H_];
__device__ float g_x2[S_*H_];
__device__ float g_hs[S_*I_];
__device__ float g_hcol[(S_*2)*I_];
__device__ float g_eo[(S_*2)*H_];
__device__ int   g_cnt[E_];
__device__ int   g_list[E_*S_];
__device__ float g_wts[S_*2];

// ---------------- TF32 tensor-core GEMM, 3-stage cp.async ----------------
// A operands are pre-rounded to tf32 by producer kernels -> raw fragment reads.
#define BM  128
#define BN  128
#define BKT 16
#define NST 3
#define ASTR 20
#define BSTR 136
#define SMEM_GEMM ((NST*BM*ASTR + NST*BKT*BSTR) * 4)

template<int EPI, int MODE, int SHIFT, int QKV, int EPI2>
__global__ void __launch_bounds__(256, 2) mma_gemm_k(
    const float* __restrict__ A, const float* __restrict__ B,
    float* __restrict__ C, const float* __restrict__ R,
    const int* __restrict__ list, const int* __restrict__ cnt,
    const float* __restrict__ B2, const float* __restrict__ B3,
    float* __restrict__ C2, float* __restrict__ C3,
    int N, int K)
{
    extern __shared__ float dsm[];
    float* As = dsm;
    float* Bs = dsm + NST * BM * ASTR;

    int n_rows = S_;
    const float* Az = A;
    const float* Bz = B;
    float* Cz = C;
    bool gat = (MODE == 1);
    int zoff = 0;
    int Nl = N;
    int n0 = blockIdx.x * BN;
    if (MODE == 1) {
        const int z = blockIdx.z;
        n_rows = cnt[z];
        if ((int)blockIdx.y * BM >= n_rows) return;
        zoff = z * S_;
        Bz = B + (size_t)z * K * N;
    }
    if (MODE == 2) {
        const int z = blockIdx.z;
        if (z == 0) {
            Az = B3; Bz = B2; Cz = C2; gat = false;
        } else {
            const int e = z - 1;
            n_rows = cnt[e];
            if ((int)blockIdx.y * BM >= n_rows) return;
            zoff = e * S_;
            Bz = B + (size_t)e * K * N;
            gat = true;
        }
    }
    if (QKV) {
        const int bx = blockIdx.x;
        if (bx < 8)       { Bz = B;  Cz = C;  Nl = 1024; n0 = bx * BN; }
        else if (bx < 10) { Bz = B2; Cz = C2; Nl = 256;  n0 = (bx - 8) * BN; }
        else              { Bz = B3; Cz = C3; Nl = 256;  n0 = (bx - 10) * BN; }
    }

    const int tid  = threadIdx.x;
    const int lane = tid & 31;
    const int wid  = tid >> 5;
    const int wm   = (wid & 1) * 64;
    const int wn   = (wid >> 1) * 32;
    const int m0   = blockIdx.y * BM;

    const int aIdx0 = tid, aIdx1 = tid + 256;
    const int r0 = m0 + (aIdx0 >> 2), r1 = m0 + (aIdx1 >> 2);
    int gar0 = r0, gar1 = r1;
    if (gat) {
        gar0 = (r0 < n_rows) ? (list[zoff + r0] >> SHIFT) : 0;
        gar1 = (r1 < n_rows) ? (list[zoff + r1] >> SHIFT) : 0;
    }
    const float* Ag0 = Az + (size_t)gar0 * K + (aIdx0 & 3) * 4;
    const float* Ag1 = Az + (size_t)gar1 * K + (aIdx1 & 3) * 4;
    const float* Bg0 = Bz + (size_t)(tid >> 5) * Nl + n0 + (tid & 31) * 4;
    const float* Bg1 = Bg0 + (size_t)8 * Nl;

    const uint32_t sa0 = s2u(&As[(size_t)(aIdx0 >> 2) * ASTR + (aIdx0 & 3) * 4]);
    const uint32_t sa1 = s2u(&As[(size_t)(aIdx1 >> 2) * ASTR + (aIdx1 & 3) * 4]);
    const uint32_t sb0 = s2u(&Bs[(size_t)(tid >> 5) * BSTR + (tid & 31) * 4]);
    const uint32_t sb1 = s2u(&Bs[(size_t)((tid >> 5) + 8) * BSTR + (tid & 31) * 4]);
    const uint32_t aStgB = BM * ASTR * 4;
    const uint32_t bStgB = BKT * BSTR * 4;

    float acc[4][4][4] = {};
    const int nk = K / BKT;

    auto load_stage = [&](int sbuf, int c) {
        const int k0 = c * BKT;
        cp16(sa0 + sbuf * aStgB, Ag0 + k0);
        cp16(sa1 + sbuf * aStgB, Ag1 + k0);
        cp16(sb0 + sbuf * bStgB, Bg0 + (size_t)k0 * Nl);
        cp16(sb1 + sbuf * bStgB, Bg1 + (size_t)k0 * Nl);
        cp_commit();
    };

    load_stage(0, 0);
    load_stage(1, 1);

    for (int c = 0; c < nk; c++) {
        cp_wait1();
        __syncthreads();
        const int buf = c % NST;
        if (c + NST - 1 < nk) load_stage((c + NST - 1) % NST, c + NST - 1);

        const float* Ab = As + (size_t)buf * BM * ASTR;
        const float* Bb = Bs + (size_t)buf * BKT * BSTR;
        #pragma unroll
        for (int ks = 0; ks < 2; ks++) {
            const int kk = ks * 8 + (lane & 3);
            uint32_t a[4][4], b[4][2];
            #pragma unroll
            for (int mt = 0; mt < 4; mt++) {
                const int m = wm + mt * 16 + (lane >> 2);
                a[mt][0] = __float_as_uint(Ab[(size_t)m * ASTR + kk]);
                a[mt][1] = __float_as_uint(Ab[(size_t)(m + 8) * ASTR + kk]);
                a[mt][2] = __float_as_uint(Ab[(size_t)m * ASTR + kk + 4]);
                a[mt][3] = __float_as_uint(Ab[(size_t)(m + 8) * ASTR + kk + 4]);
            }
            #pragma unroll
            for (int nt = 0; nt < 4; nt++) {
                const int nn = wn + nt * 8 + (lane >> 2);
                b[nt][0] = tf32u(Bb[(size_t)kk * BSTR + nn]);
                b[nt][1] = tf32u(Bb[(size_t)(kk + 4) * BSTR + nn]);
            }
            #pragma unroll
            for (int mt = 0; mt < 4; mt++)
                #pragma unroll
                for (int nt = 0; nt < 4; nt++)
                    asm volatile(
                        "mma.sync.aligned.m16n8k8.row.col.f32.tf32.tf32.f32 "
                        "{%0,%1,%2,%3}, {%4,%5,%6,%7}, {%8,%9}, {%0,%1,%2,%3};"
                        : "+f"(acc[mt][nt][0]), "+f"(acc[mt][nt][1]),
                          "+f"(acc[mt][nt][2]), "+f"(acc[mt][nt][3])
                        : "r"(a[mt][0]), "r"(a[mt][1]), "r"(a[mt][2]), "r"(a[mt][3]),
                          "r"(b[nt][0]), "r"(b[nt][1]));
        }
    }

    const bool sharedSide = (MODE == 2) && (blockIdx.z == 0);
    const bool rndSt = QKV && ((int)blockIdx.x >= 10);   // v output: pre-round (idempotent)
    #pragma unroll
    for (int mt = 0; mt < 4; mt++) {
        #pragma unroll
        for (int half = 0; half < 2; half++) {
            const int r = m0 + wm + mt * 16 + (lane >> 2) + half * 8;
            if (gat && r >= n_rows) continue;
            size_t crow_idx = r;
            if (gat) crow_idx = (size_t)list[zoff + r];
            float* crow = Cz + crow_idx * Nl;
            const int epi = sharedSide ? EPI2 : EPI;
            #pragma unroll
            for (int nt = 0; nt < 4; nt++) {
                const int col = n0 + wn + nt * 8 + (lane & 3) * 2;
                float2 v;
                v.x = acc[mt][nt][half * 2 + 0];
                v.y = acc[mt][nt][half * 2 + 1];
                if (epi == 1) {
                    v.x = tf32r(silu_f(v.x)); v.y = tf32r(silu_f(v.y));
                } else if (epi == 2) {
                    const float2 rr = *(const float2*)(R + crow_idx * Nl + col);
                    v.x += rr.x; v.y += rr.y;
                } else if (rndSt) {
                    v.x = tf32r(v.x); v.y = tf32r(v.y);
                }
                *(float2*)(crow + col) = v;
            }
        }
    }
}

// ---------------- RMSNorm (stores tf32-rounded; consumers are MMA-A/router) --
__global__ void rmsnorm_k(const float* __restrict__ x, const float* __restrict__ w,
                          float* __restrict__ o)
{
    const int t = blockIdx.x;
    const int tid = threadIdx.x;
    const float* xr = x + (size_t)t * H_;
    float s = 0.f;
    for (int i = tid; i < H_; i += 256) { float v = xr[i]; s = __fmaf_rn(v, v, s); }
    for (int off = 16; off; off >>= 1) s += __shfl_down_sync(0xffffffffu, s, off);
    __shared__ float red[8];
    const int wid = tid >> 5, lane = tid & 31;
    if (!lane) red[wid] = s;
    __syncthreads();
    if (tid == 0) {
        float tot = 0.f;
        #pragma unroll
        for (int i = 0; i < 8; i++) tot += red[i];
        red[0] = rsqrtf(tot * (1.0f / H_) + 1e-6f);
    }
    __syncthreads();
    const float r = red[0];
    float* orow = o + (size_t)t * H_;
    for (int i = tid; i < H_; i += 256) orow[i] = tf32r(w[i] * (xr[i] * r));
}

// ---------------- RoPE (stores tf32-rounded rotated q/k) ----------------------
__global__ void rope_k(float* __restrict__ q, float* __restrict__ k)
{
    const int idx = blockIdx.x * blockDim.x + threadIdx.x;
    const int half = idx & 31;
    const int rest = idx >> 5;
    const int head = rest % (NH_ + KVH_);
    const int t = rest / (NH_ + KVH_);
    const float inv_freq = __fdiv_rn(1.0f, acc_powf(10000.0f, (float)half * 0.03125f));
    const float ang = __fmul_rn((float)t, inv_freq);
    const float c = acc_cosf(ang);
    const float sn = acc_sinf(ang);
    float* base = (head < NH_) ? (q + (size_t)t * H_ + head * HD_)
                               : (k + (size_t)t * (KVH_ * HD_) + (head - NH_) * HD_);
    const float x1 = base[half];
    const float x2 = base[half + 32];
    base[half]      = tf32r(__fadd_rn(__fmul_rn(x1, c), -__fmul_rn(x2, sn)));
    base[half + 32] = tf32r(__fadd_rn(__fmul_rn(x2, c),  __fmul_rn(x1, sn)));
}

// ---- Attention: split-K two-pass MMA (q/k/v pre-rounded -> raw loads) --------
#define AQ 128
#define AK 64
#define QSTR 68
#define SMEM_ATTN_A ((AQ*QSTR + 2*AK*QSTR + 512) * 4)
#define SMEM_ATTN_C ((2*AQ*QSTR + 2*AK*QSTR + 2*AQ) * 4)

__device__ __forceinline__ void attn_issue_tile(const float* gbase, float* sbuf, int tid) {
    #pragma unroll
    for (int s = 0; s < 4; s++) {
        const int i = tid + s * 256;
        const int j = i >> 4, d4 = (i & 15) * 4;
        cp16(s2u(&sbuf[j * QSTR + d4]), gbase + (size_t)j * (KVH_ * HD_) + d4);
    }
    cp_commit();
}

__device__ __forceinline__ void attn_mma_scores(
    const float* __restrict__ Qs, const float* __restrict__ KB,
    float accS[2][4][4], int lane, int wm, int wn)
{
    #pragma unroll
    for (int ks = 0; ks < 8; ks++) {
        const int kk = ks * 8 + (lane & 3);
        uint32_t a[2][4], b[4][2];
        #pragma unroll
        for (int mt = 0; mt < 2; mt++) {
            const int r = wm + mt * 16 + (lane >> 2);
            a[mt][0] = __float_as_uint(Qs[r * QSTR + kk]);
            a[mt][1] = __float_as_uint(Qs[(r + 8) * QSTR + kk]);
            a[mt][2] = __float_as_uint(Qs[r * QSTR + kk + 4]);
            a[mt][3] = __float_as_uint(Qs[(r + 8) * QSTR + kk + 4]);
        }
        #pragma unroll
        for (int nt = 0; nt < 4; nt++) {
            const int j = wn + nt * 8 + (lane >> 2);
            b[nt][0] = __float_as_uint(KB[j * QSTR + kk]);
            b[nt][1] = __float_as_uint(KB[j * QSTR + kk + 4]);
        }
        #pragma unroll
        for (int mt = 0; mt < 2; mt++)
            #pragma unroll
            for (int nt = 0; nt < 4; nt++)
                asm volatile(
                    "mma.sync.aligned.m16n8k8.row.col.f32.tf32.tf32.f32 "
                    "{%0,%1,%2,%3}, {%4,%5,%6,%7}, {%8,%9}, {%0,%1,%2,%3};"
                    : "+f"(accS[mt][nt][0]), "+f"(accS[mt][nt][1]),
                      "+f"(accS[mt][nt][2]), "+f"(accS[mt][nt][3])
                    : "r"(a[mt][0]), "r"(a[mt][1]), "r"(a[mt][2]), "r"(a[mt][3]),
                      "r"(b[nt][0]), "r"(b[nt][1]));
    }
}

// phase A: partial (m, l) for key-split s of q-tile qt
__global__ void __launch_bounds__(256, 2) attn_a_k(
    const float* __restrict__ q, const float* __restrict__ k,
    float* __restrict__ ml)
{
    extern __shared__ float sm[];
    float* Qs    = sm;
    float* KVa   = Qs + AQ * QSTR;
    float* KVb   = KVa + AK * QSTR;
    float* partM = KVb + AK * QSTR;   // [128][2]
    float* partL = partM + 256;

    const int h  = blockIdx.y;
    const int bx = blockIdx.x;            // 0..31, heavy qt first
    const int qt = 15 - (bx >> 1);
    const int sp = bx & 1;
    const int q0 = qt * AQ;
    const int tid = threadIdx.x;
    const int lane = tid & 31, wid = tid >> 5;
    const int kvh = h >> 2;
    const int halfT = qt + 1;
    const int ts = sp * halfT, te = ts + halfT;
    const int wm = (wid & 3) * 32, wn = (wid >> 2) * 32;

    const float* kb = k + kvh * HD_;
    attn_issue_tile(kb + (size_t)(ts * AK) * (KVH_ * HD_), KVa, tid);
    for (int i = tid; i < AQ * (HD_ / 4); i += 256) {
        const int qq = i >> 4, d4 = (i & 15) * 4;
        *(float4*)&Qs[qq * QSTR + d4] =
            *(const float4*)(q + (size_t)(q0 + qq) * H_ + h * HD_ + d4);
    }

    float m_old = -1e30f, l_old = 0.f;
    for (int t = ts; t < te; t++) {
        const int k0 = t * AK;
        float* bufX = ((t - ts) & 1) ? KVb : KVa;
        float* bufY = ((t - ts) & 1) ? KVa : KVb;
        if (t + 1 < te) { attn_issue_tile(kb + (size_t)(k0 + AK) * (KVH_ * HD_), bufY, tid); cp_wait1(); }
        else            { cp_wait0(); }
        __syncthreads();

        float accS[2][4][4] = {};
        attn_mma_scores(Qs, bufX, accS, lane, wm, wn);

        #pragma unroll
        for (int mt = 0; mt < 2; mt++)
            #pragma unroll
            for (int half = 0; half < 2; half++) {
                const int row = wm + mt * 16 + (lane >> 2) + half * 8;
                const int qi_r = q0 + row;
                float sv[8];
                float pm = -1e30f;
                #pragma unroll
                for (int nt = 0; nt < 4; nt++)
                    #pragma unroll
                    for (int e2 = 0; e2 < 2; e2++) {
                        const int col = wn + nt * 8 + (lane & 3) * 2 + e2;
                        const float s = accS[mt][nt][half * 2 + e2] * 0.125f;
                        sv[nt * 2 + e2] = (k0 + col <= qi_r) ? s : -1e30f;
                        pm = fmaxf(pm, sv[nt * 2 + e2]);
                    }
                float pl = 0.f;
                #pragma unroll
                for (int x = 0; x < 8; x++)
                    if (sv[x] > -1e29f) pl += acc_expf(sv[x] - pm);
                #pragma unroll
                for (int mm = 1; mm <= 2; mm <<= 1) {
                    const float om = __shfl_xor_sync(0xffffffffu, pm, mm);
                    const float ol = __shfl_xor_sync(0xffffffffu, pl, mm);
                    const float nm = fmaxf(pm, om);
                    pl = pl * acc_expf(pm - nm) + ol * acc_expf(om - nm);
                    pm = nm;
                }
                if ((lane & 3) == 0) {
                    partM[row * 2 + (wn >> 5)] = pm;
                    partL[row * 2 + (wn >> 5)] = pl;
                }
            }
        __syncthreads();
        if (tid < 128) {
            const float mA = partM[tid * 2], mB = partM[tid * 2 + 1];
            const float mt2 = fmaxf(mA, mB);
            const float lt = partL[tid * 2] * acc_expf(mA - mt2)
                           + partL[tid * 2 + 1] * acc_expf(mB - mt2);
            const float mn = fmaxf(m_old, mt2);
            l_old = l_old * acc_expf(m_old - mn) + lt * acc_expf(mt2 - mn);
            m_old = mn;
        }
    }
    if (tid < 128) {
        const int base = ((h * 16 + qt) * 2 + sp) * 256;
        ml[base + tid]       = m_old;
        ml[base + 128 + tid] = l_old;
    }
}

// phase C: merged (m,l) -> partial O for key-split s
__global__ void __launch_bounds__(256, 2) attn_c_k(
    const float* __restrict__ q, const float* __restrict__ k,
    const float* __restrict__ v, const float* __restrict__ ml,
    float* __restrict__ o0, float* __restrict__ o1)
{
    extern __shared__ float sm[];
    float* Qs   = sm;
    float* SP   = Qs + AQ * QSTR;
    float* KVa  = SP + AQ * QSTR;
    float* KVb  = KVa + AK * QSTR;
    float* mfin = KVb + AK * QSTR;
    float* lfin = mfin + AQ;

    const int h  = blockIdx.y;
    const int bx = blockIdx.x;
    const int qt = 15 - (bx >> 1);
    const int sp = bx & 1;
    const int q0 = qt * AQ;
    const int tid = threadIdx.x;
    const int lane = tid & 31, wid = tid >> 5;
    const int kvh = h >> 2;
    const int halfT = qt + 1;
    const int ts = sp * halfT, te = ts + halfT;
    const int wm = (wid & 3) * 32, wn = (wid >> 2) * 32;

    const float* kb = k + kvh * HD_;
    const float* vb = v + kvh * HD_;
    attn_issue_tile(kb + (size_t)(ts * AK) * (KVH_ * HD_), KVa, tid);

    // merge the two split partials (deterministic, fixed association)
    if (tid < 128) {
        const int b = (h * 16 + qt) * 2 * 256;
        const float mA = ml[b + tid],       lA = ml[b + 128 + tid];
        const float mB = ml[b + 256 + tid], lB = ml[b + 384 + tid];
        const float mq = fmaxf(mA, mB);
        mfin[tid] = mq;
        lfin[tid] = lA * acc_expf(mA - mq) + lB * acc_expf(mB - mq);
    }
    for (int i = tid; i < AQ * (HD_ / 4); i += 256) {
        const int qq = i >> 4, d4 = (i & 15) * 4;
        *(float4*)&Qs[qq * QSTR + d4] =
            *(const float4*)(q + (size_t)(q0 + qq) * H_ + h * HD_ + d4);
    }

    float accO[2][4][4] = {};
    for (int t = ts; t < te; t++) {
        const int k0 = t * AK;
        float* bufX = ((t - ts) & 1) ? KVb : KVa;
        float* bufY = ((t - ts) & 1) ? KVa : KVb;
        __syncthreads();                  // prev PV done; mfin/Qs ready at t=ts
        if (t + 1 < te) { attn_issue_tile(kb + (size_t)(k0 + AK) * (KVH_ * HD_), bufY, tid); cp_wait1(); }
        else            { cp_wait0(); }
        __syncthreads();                  // K_t visible

        float accS[2][4][4] = {};
        attn_mma_scores(Qs, bufX, accS, lane, wm, wn);
        __syncthreads();                  // all warps done reading K_t
        attn_issue_tile(vb + (size_t)k0 * (KVH_ * HD_), bufX, tid);  // V_t -> bufX (overlaps conv)

        #pragma unroll
        for (int mt = 0; mt < 2; mt++)
            #pragma unroll
            for (int half = 0; half < 2; half++) {
                const int row = wm + mt * 16 + (lane >> 2) + half * 8;
                const float mq = mfin[row];
                const float lq = lfin[row];
                #pragma unroll
                for (int nt = 0; nt < 4; nt++)
                    #pragma unroll
                    for (int e2 = 0; e2 < 2; e2++) {
                        const int col = wn + nt * 8 + (lane & 3) * 2 + e2;
                        float p = 0.f;
                        if (k0 + col <= q0 + row) {
                            const float s = accS[mt][nt][half * 2 + e2] * 0.125f;
                            p = tf32r(__fdiv_rn(acc_expf(s - mq), lq));
                        }
                        SP[row * QSTR + col] = p;
                    }
            }
        cp_wait0();
        __syncthreads();                  // SP + V_t visible

        #pragma unroll
        for (int ks = 0; ks < 8; ks++) {
            const int kk = ks * 8 + (lane & 3);
            uint32_t a[2][4], b[4][2];
            #pragma unroll
            for (int mt = 0; mt < 2; mt++) {
                const int r = wm + mt * 16 + (lane >> 2);
                a[mt][0] = __float_as_uint(SP[r * QSTR + kk]);
                a[mt][1] = __float_as_uint(SP[(r + 8) * QSTR + kk]);
                a[mt][2] = __float_as_uint(SP[r * QSTR + kk + 4]);
                a[mt][3] = __float_as_uint(SP[(r + 8) * QSTR + kk + 4]);
            }
            #pragma unroll
            for (int nt = 0; nt < 4; nt++) {
                const int d = wn + nt * 8 + (lane >> 2);
                b[nt][0] = __float_as_uint(bufX[kk * QSTR + d]);
                b[nt][1] = __float_as_uint(bufX[(kk + 4) * QSTR + d]);
            }
            #pragma unroll
            for (int mt = 0; mt < 2; mt++)
                #pragma unroll
                for (int nt = 0; nt < 4; nt++)
                    asm volatile(
                        "mma.sync.aligned.m16n8k8.row.col.f32.tf32.tf32.f32 "
                        "{%0,%1,%2,%3}, {%4,%5,%6,%7}, {%8,%9}, {%0,%1,%2,%3};"
                        : "+f"(accO[mt][nt][0]), "+f"(accO[mt][nt][1]),
                          "+f"(accO[mt][nt][2]), "+f"(accO[mt][nt][3])
                        : "r"(a[mt][0]), "r"(a[mt][1]), "r"(a[mt][2]), "r"(a[mt][3]),
                          "r"(b[nt][0]), "r"(b[nt][1]));
        }
    }

    float* od = sp ? o1 : o0;
    #pragma unroll
    for (int mt = 0; mt < 2; mt++)
        #pragma unroll
        for (int half = 0; half < 2; half++) {
            const int row = q0 + wm + mt * 16 + (lane >> 2) + half * 8;
            #pragma unroll
            for (int nt = 0; nt < 4; nt++) {
                const int col = wn + nt * 8 + (lane & 3) * 2;
                float2 r2;
                r2.x = accO[mt][nt][half * 2 + 0];
                r2.y = accO[mt][nt][half * 2 + 1];
                *(float2*)(od + (size_t)row * H_ + h * HD_ + col) = r2;
            }
        }
}

// att = tf32r(att + attP)  (pre-rounds O-proj's A operand; idempotent w/ read)
__global__ void addO_k(float* __restrict__ a, const float* __restrict__ b)
{
    const size_t i = ((size_t)blockIdx.x * 256 + threadIdx.x) * 4;
    float4 x = *(float4*)(a + i);
    const float4 y = *(const float4*)(b + i);
    x.x = tf32r(x.x + y.x); x.y = tf32r(x.y + y.y);
    x.z = tf32r(x.z + y.z); x.w = tf32r(x.w + y.w);
    *(float4*)(a + i) = x;
}

// ---------------- router ----------------
__global__ void zero_k(int* __restrict__ c)
{
    if (threadIdx.x < E_) c[threadIdx.x] = 0;
}

__global__ void router_k(const float* __restrict__ x, const float* __restrict__ rw,
                         int* __restrict__ cnt, int* __restrict__ list,
                         float* __restrict__ wout)
{
    const int t = blockIdx.x;
    const int tid = threadIdx.x;
    const int e = tid >> 5, lane = tid & 31;
    const float* xr = x + (size_t)t * H_;
    float s = 0.f;
    for (int i = lane; i < H_; i += 32)
        s = __fmaf_rn(tf32r(xr[i]), tf32r(rw[i * E_ + e]), s);
    for (int off = 16; off; off >>= 1) s += __shfl_down_sync(0xffffffffu, s, off);
    __shared__ float logit[E_];
    if (!lane) logit[e] = s;
    __syncthreads();
    if (tid == 0) {
        float mx = logit[0];
        #pragma unroll
        for (int i = 1; i < E_; i++) mx = fmaxf(mx, logit[i]);
        float p[E_];
        #pragma unroll
        for (int i = 0; i < E_; i++) p[i] = acc_expf(logit[i] - mx);
        int i0 = 0;
        #pragma unroll
        for (int i = 1; i < E_; i++) if (p[i] > p[i0]) i0 = i;
        int i1 = (i0 == 0) ? 1 : 0;
        #pragma unroll
        for (int i = 0; i < E_; i++) if (i != i0 && p[i] > p[i1]) i1 = i;
        const float denom = p[i0] + p[i1];
        wout[2 * t + 0] = __fdiv_rn(p[i0], denom);
        wout[2 * t + 1] = __fdiv_rn(p[i1], denom);
        int pos = atomicAdd(&cnt[i0], 1);
        list[i0 * S_ + pos] = 2 * t;
        pos = atomicAdd(&cnt[i1], 1);
        list[i1 * S_ + pos] = 2 * t + 1;
    }
}

// ---------------- combine ----------------
__global__ void combine_k(float* __restrict__ out, const float* __restrict__ eo,
                          const float* __restrict__ w)
{
    const int t = blockIdx.x;
    const float w0 = w[2 * t], w1 = w[2 * t + 1];
    const float* e0 = eo + (size_t)(2 * t) * H_;
    const float* e1 = eo + (size_t)(2 * t + 1) * H_;
    float* orow = out + (size_t)t * H_;
    for (int i = threadIdx.x; i < H_; i += 256)
        orow[i] += __fmaf_rn(w0, e0[i], __fmul_rn(w1, e1[i]));
}

// ---------------- host launch --------------------------------------------------
extern "C" void kernel_launch(void* const* d_in, const int* in_sizes, int n_in,
                              void* d_out, int out_size)
{
    const float* hs  = (const float*)d_in[0];
    const float* ln1 = (const float*)d_in[1];
    const float* wq  = (const float*)d_in[2];
    const float* wk  = (const float*)d_in[3];
    const float* wv  = (const float*)d_in[4];
    const float* wo  = (const float*)d_in[5];
    const float* ln2 = (const float*)d_in[6];
    const float* sw1 = (const float*)d_in[7];
    const float* sw2 = (const float*)d_in[8];
    const float* ew1 = (const float*)d_in[9];
    const float* ew2 = (const float*)d_in[10];
    const float* rw  = (const float*)d_in[11];
    float* out = (float*)d_out;

    float *x1, *q, *k, *v, *att, *attP, *mlb, *hid, *x2, *hsv, *hcol, *eo, *wts;
    int *cnt, *list;
    cudaGetSymbolAddress((void**)&x1,   g_x1);
    cudaGetSymbolAddress((void**)&q,    g_q);
    cudaGetSymbolAddress((void**)&k,    g_k);
    cudaGetSymbolAddress((void**)&v,    g_v);
    cudaGetSymbolAddress((void**)&att,  g_att);
    cudaGetSymbolAddress((void**)&attP, g_attP);
    cudaGetSymbolAddress((void**)&mlb,  g_ml);
    cudaGetSymbolAddress((void**)&hid,  g_hidden);
    cudaGetSymbolAddress((void**)&x2,   g_x2);
    cudaGetSymbolAddress((void**)&hsv,  g_hs);
    cudaGetSymbolAddress((void**)&hcol, g_hcol);
    cudaGetSymbolAddress((void**)&eo,   g_eo);
    cudaGetSymbolAddress((void**)&wts,  g_wts);
    cudaGetSymbolAddress((void**)&cnt,  g_cnt);
    cudaGetSymbolAddress((void**)&list, g_list);

    cudaFuncSetAttribute(mma_gemm_k<0,0,0,1,0>, cudaFuncAttributeMaxDynamicSharedMemorySize, SMEM_GEMM);
    cudaFuncSetAttribute(mma_gemm_k<2,0,0,0,0>, cudaFuncAttributeMaxDynamicSharedMemorySize, SMEM_GEMM);
    cudaFuncSetAttribute(mma_gemm_k<1,2,1,0,1>, cudaFuncAttributeMaxDynamicSharedMemorySize, SMEM_GEMM);
    cudaFuncSetAttribute(mma_gemm_k<0,2,0,0,2>, cudaFuncAttributeMaxDynamicSharedMemorySize, SMEM_GEMM);
    cudaFuncSetAttribute(attn_a_k, cudaFuncAttributeMaxDynamicSharedMemorySize, SMEM_ATTN_A);
    cudaFuncSetAttribute(attn_c_k, cudaFuncAttributeMaxDynamicSharedMemorySize, SMEM_ATTN_C);

    // 1. rmsnorm1 (tf32-rounded output)
    rmsnorm_k<<<S_, 256>>>(hs, ln1, x1);
    // 2. fused QKV projection (v output pre-rounded)
    mma_gemm_k<0,0,0,1,0><<<dim3(12, S_ / BM), 256, SMEM_GEMM>>>(
        x1, wq, q, nullptr, nullptr, nullptr, wk, wv, k, v, H_, H_);
    // 3. RoPE (tf32-rounded q/k)
    rope_k<<<(S_ * (NH_ + KVH_) * 32) / 256, 256>>>(q, k);
    // 4. attention: split-K two-pass
    attn_a_k<<<dim3(32, NH_), 256, SMEM_ATTN_A>>>(q, k, mlb);
    attn_c_k<<<dim3(32, NH_), 256, SMEM_ATTN_C>>>(q, k, v, mlb, att, attP);
    addO_k<<<(S_ * H_) / 1024, 256>>>(att, attP);
    // 5. O-proj + residual
    mma_gemm_k<2,0,0,0,0><<<dim3(H_ / BN, S_ / BM), 256, SMEM_GEMM>>>(
        att, wo, hid, hs, nullptr, nullptr, nullptr, nullptr, nullptr, nullptr, H_, H_);
    // 6. rmsnorm2 (tf32-rounded output)
    rmsnorm_k<<<S_, 256>>>(hid, ln2, x2);
    // 7. router
    zero_k<<<1, 32>>>(cnt);
    router_k<<<S_, 256>>>(x2, rw, cnt, list, wts);
    // 8. fused shared-MLP-1 + expert-1 (silu outputs tf32-rounded)
    mma_gemm_k<1,2,1,0,1><<<dim3(I_ / BN, S_ / BM, E_ + 1), 256, SMEM_GEMM>>>(
        x2, ew1, hcol, nullptr, list, cnt, sw1, x2, hsv, nullptr, I_, H_);
    // 9. fused shared-MLP-2 (+residual) + expert-2
    mma_gemm_k<0,2,0,0,2><<<dim3(H_ / BN, S_ / BM, E_ + 1), 256, SMEM_GEMM>>>(
        hcol, ew2, eo, hid, list, cnt, sw2, hsv, out, nullptr, H_, I_);
    // 10. combine
    combine_k<<<S_, 256>>>(out, eo, wts);
}

// round 13
// speedup vs baseline: 1.8821x; 1.0014x over previous
#include <cuda_runtime.h>
#include <cstdint>
#include <math.h>

#define S_   2048
#define H_   1024
#define NH_  16
#define KVH_ 4
#define HD_  64
#define E_   8
#define I_   4096

// ---------------- accurate math helpers ------------------
#ifdef __FAST_MATH__
__device__ __forceinline__ float acc_expf(float x) { return (float)exp((double)x); }
__device__ __forceinline__ float acc_cosf(float x) { return (float)cos((double)x); }
__device__ __forceinline__ float acc_sinf(float x) { return (float)sin((double)x); }
__device__ __forceinline__ float acc_powf(float a, float b) { return (float)pow((double)a, (double)b); }
#else
__device__ __forceinline__ float acc_expf(float x) { return expf(x); }
__device__ __forceinline__ float acc_cosf(float x) { return cosf(x); }
__device__ __forceinline__ float acc_sinf(float x) { return sinf(x); }
__device__ __forceinline__ float acc_powf(float a, float b) { return powf(a, b); }
#endif

__device__ __forceinline__ float tf32r(float x) {
    uint32_t u;
    asm("cvt.rna.tf32.f32 %0, %1;" : "=r"(u) : "f"(x));
    return __uint_as_float(u);
}
__device__ __forceinline__ uint32_t tf32u(float x) {
    uint32_t u;
    asm("cvt.rna.tf32.f32 %0, %1;" : "=r"(u) : "f"(x));
    return u;
}
__device__ __forceinline__ float4 tf32r4(float4 v) {
    v.x = tf32r(v.x); v.y = tf32r(v.y); v.z = tf32r(v.z); v.w = tf32r(v.w);
    return v;
}
__device__ __forceinline__ float silu_f(float v) {
    return __fdiv_rn(v, 1.0f + acc_expf(-v));
}

__device__ __forceinline__ uint32_t s2u(const void* p) {
    return (uint32_t)__cvta_generic_to_shared(p);
}
__device__ __forceinline__ void cp16(uint32_t dst, const float* src) {
    asm volatile("cp.async.ca.shared.global [%0], [%1], 16;\n" :: "r"(dst), "l"(src));
}
__device__ __forceinline__ void cp_commit() {
    asm volatile("cp.async.commit_group;\n" ::);
}
__device__ __forceinline__ void cp_wait1() {
    asm volatile("cp.async.wait_group 1;\n" ::);
}
__device__ __forceinline__ void cp_wait0() {
    asm volatile("cp.async.wait_group 0;\n" ::);
}

// ---------------- scratch ----------------
__device__ float g_x1[S_*H_];            // rmsnorm1 out; later O-proj partial 0
__device__ float g_q[S_*H_];
__device__ float g_k[S_*KVH_*HD_];
__device__ float g_v[S_*KVH_*HD_];
__device__ float g_att[S_*H_];
__device__ float g_attP[S_*H_];          // attn partial; later O-proj partial 1
__device__ float g_ml[NH_*16*2*256];
__device__ float g_hidden[S_*H_];
__device__ float g_x2[S_*H_];
__device__ float g_hs[S_*I_];
__device__ float g_hcol[(S_*2)*I_];
__device__ float g_eoP[2*(S_*2)*H_];     // expert-out partials, split-stride 2S*H
__device__ float g_spP[2*S_*H_];         // shared-MLP2 partials, split-stride S*H
__device__ int   g_cnt[E_];
__device__ int   g_list[E_*S_];
__device__ float g_wts[S_*2];

// ---------------- TF32 tensor-core GEMM, BKT=32, 3-stage cp.async ------------
// A operands pre-rounded tf32 by producers -> raw fragment reads; B (weights) cvt.
#define BM  128
#define BN  128
#define BKT 32
#define NST 3
#define ASTR 36
#define BSTR 136
#define SMEM_GEMM ((NST*BM*ASTR + NST*BKT*BSTR) * 4)

// MODE: 0 plain, 2 fused (zi==0 shared via B2/B3/C2, zi>0 gather expert via list)
// KSPLIT: 2-way K split; outputs offset by ksp*stride (MODE2) or C/C2 (MODE0)
template<int EPI, int MODE, int SHIFT, int QKV, int EPI2, int KSPLIT>
__global__ void __launch_bounds__(256, 2) mma_gemm_k(
    const float* __restrict__ A, const float* __restrict__ B,
    float* __restrict__ C, const float* __restrict__ R,
    const int* __restrict__ list, const int* __restrict__ cnt,
    const float* __restrict__ B2, const float* __restrict__ B3,
    float* __restrict__ C2, float* __restrict__ C3,
    int N, int K)
{
    extern __shared__ float dsm[];
    float* As = dsm;                    // [NST][BM][ASTR]
    float* Bs = dsm + NST * BM * ASTR;  // [NST][BKT][BSTR]

    int n_rows = S_;
    const float* Az = A;
    const float* Bz = B;
    float* Cz = C;
    bool gat = false;
    int zoff = 0;
    int Nl = N;
    int n0 = blockIdx.x * BN;

    int ksp = 0, zi = blockIdx.z;
    if (KSPLIT) {
        if (MODE == 2) { ksp = blockIdx.z / (E_ + 1); zi = blockIdx.z % (E_ + 1); }
        else           { ksp = blockIdx.z; zi = 0; if (ksp) Cz = C2; }
    }
    bool sharedSide = false;
    if (MODE == 2) {
        if (zi == 0) {
            Az = B3; Bz = B2; sharedSide = true;
            Cz = C2 + (KSPLIT ? (size_t)ksp * S_ * N : 0);
        } else {
            const int e = zi - 1;
            n_rows = cnt[e];
            if ((int)blockIdx.y * BM >= n_rows) return;
            zoff = e * S_;
            Bz = B + (size_t)e * K * N;
            gat = true;
            Cz = C + (KSPLIT ? (size_t)ksp * (2 * S_) * N : 0);
        }
    }
    if (QKV) {
        const int bx = blockIdx.x;
        if (bx < 8)       { Bz = B;  Cz = C;  Nl = 1024; n0 = bx * BN; }
        else if (bx < 10) { Bz = B2; Cz = C2; Nl = 256;  n0 = (bx - 8) * BN; }
        else              { Bz = B3; Cz = C3; Nl = 256;  n0 = (bx - 10) * BN; }
    }

    const int Keff = KSPLIT ? (K >> 1) : K;
    const int koff = KSPLIT ? ksp * Keff : 0;

    const int tid  = threadIdx.x;
    const int lane = tid & 31;
    const int wid  = tid >> 5;
    const int wm   = (wid & 1) * 64;
    const int wn   = (wid >> 1) * 32;
    const int m0   = blockIdx.y * BM;

    // loaders: 4 A-float4 + 4 B-float4 per thread per stage (BKT=32)
    const float* AgR[4];
    #pragma unroll
    for (int s = 0; s < 4; s++) {
        const int ia = tid + s * 256;
        const int ar = ia >> 3;
        int grow = m0 + ar;
        if (gat) grow = (grow < n_rows) ? (list[zoff + grow] >> SHIFT) : 0;
        AgR[s] = Az + (size_t)grow * K + koff + (ia & 7) * 4;
    }
    const uint32_t sao0 = s2u(&As[(tid >> 3) * ASTR + (tid & 7) * 4]);
    const uint32_t sbo0 = s2u(&Bs[(tid >> 5) * BSTR + (tid & 31) * 4]);
    const float* Bg0 = Bz + (size_t)(koff + (tid >> 5)) * Nl + n0 + (tid & 31) * 4;
    const uint32_t aStgB = BM * ASTR * 4;
    const uint32_t bStgB = BKT * BSTR * 4;

    float acc[4][4][4] = {};
    const int nk = Keff / BKT;

    auto load_stage = [&](int sbuf, int c) {
        const int k0 = c * BKT;
        #pragma unroll
        for (int s = 0; s < 4; s++)
            cp16(sao0 + sbuf * aStgB + s * (32 * ASTR * 4), AgR[s] + k0);
        #pragma unroll
        for (int s = 0; s < 4; s++)
            cp16(sbo0 + sbuf * bStgB + s * (8 * BSTR * 4),
                 Bg0 + (size_t)(k0 + s * 8) * Nl);
        cp_commit();
    };

    load_stage(0, 0);
    load_stage(1, 1);

    for (int c = 0; c < nk; c++) {
        cp_wait1();
        __syncthreads();
        const int buf = c % NST;
        if (c + NST - 1 < nk) load_stage((c + NST - 1) % NST, c + NST - 1);

        const float* Ab = As + (size_t)buf * BM * ASTR;
        const float* Bb = Bs + (size_t)buf * BKT * BSTR;
        #pragma unroll
        for (int ks = 0; ks < 4; ks++) {
            const int kk = ks * 8 + (lane & 3);
            uint32_t a[4][4], b[4][2];
            #pragma unroll
            for (int mt = 0; mt < 4; mt++) {
                const int m = wm + mt * 16 + (lane >> 2);
                a[mt][0] = __float_as_uint(Ab[(size_t)m * ASTR + kk]);
                a[mt][1] = __float_as_uint(Ab[(size_t)(m + 8) * ASTR + kk]);
                a[mt][2] = __float_as_uint(Ab[(size_t)m * ASTR + kk + 4]);
                a[mt][3] = __float_as_uint(Ab[(size_t)(m + 8) * ASTR + kk + 4]);
            }
            #pragma unroll
            for (int nt = 0; nt < 4; nt++) {
                const int nn = wn + nt * 8 + (lane >> 2);
                b[nt][0] = tf32u(Bb[(size_t)kk * BSTR + nn]);
                b[nt][1] = tf32u(Bb[(size_t)(kk + 4) * BSTR + nn]);
            }
            #pragma unroll
            for (int mt = 0; mt < 4; mt++)
                #pragma unroll
                for (int nt = 0; nt < 4; nt++)
                    asm volatile(
                        "mma.sync.aligned.m16n8k8.row.col.f32.tf32.tf32.f32 "
                        "{%0,%1,%2,%3}, {%4,%5,%6,%7}, {%8,%9}, {%0,%1,%2,%3};"
                        : "+f"(acc[mt][nt][0]), "+f"(acc[mt][nt][1]),
                          "+f"(acc[mt][nt][2]), "+f"(acc[mt][nt][3])
                        : "r"(a[mt][0]), "r"(a[mt][1]), "r"(a[mt][2]), "r"(a[mt][3]),
                          "r"(b[nt][0]), "r"(b[nt][1]));
        }
    }

    const bool rndSt = QKV && ((int)blockIdx.x >= 10);   // v output pre-rounded
    #pragma unroll
    for (int mt = 0; mt < 4; mt++) {
        #pragma unroll
        for (int half = 0; half < 2; half++) {
            const int r = m0 + wm + mt * 16 + (lane >> 2) + half * 8;
            if (gat && r >= n_rows) continue;
            size_t crow_idx = r;
            if (gat) crow_idx = (size_t)list[zoff + r];
            float* crow = Cz + crow_idx * Nl;
            const int epi = sharedSide ? EPI2 : EPI;
            #pragma unroll
            for (int nt = 0; nt < 4; nt++) {
                const int col = n0 + wn + nt * 8 + (lane & 3) * 2;
                float2 v;
                v.x = acc[mt][nt][half * 2 + 0];
                v.y = acc[mt][nt][half * 2 + 1];
                if (epi == 1) {
                    v.x = tf32r(silu_f(v.x)); v.y = tf32r(silu_f(v.y));
                } else if (rndSt) {
                    v.x = tf32r(v.x); v.y = tf32r(v.y);
                }
                *(float2*)(crow + col) = v;
            }
        }
    }
}

// ---------------- RMSNorm (tf32-rounded output) ----------------
__global__ void rmsnorm_k(const float* __restrict__ x, const float* __restrict__ w,
                          float* __restrict__ o)
{
    const int t = blockIdx.x;
    const int tid = threadIdx.x;
    const float* xr = x + (size_t)t * H_;
    float s = 0.f;
    for (int i = tid; i < H_; i += 256) { float v = xr[i]; s = __fmaf_rn(v, v, s); }
    for (int off = 16; off; off >>= 1) s += __shfl_down_sync(0xffffffffu, s, off);
    __shared__ float red[8];
    const int wid = tid >> 5, lane = tid & 31;
    if (!lane) red[wid] = s;
    __syncthreads();
    if (tid == 0) {
        float tot = 0.f;
        #pragma unroll
        for (int i = 0; i < 8; i++) tot += red[i];
        red[0] = rsqrtf(tot * (1.0f / H_) + 1e-6f);
    }
    __syncthreads();
    const float r = red[0];
    float* orow = o + (size_t)t * H_;
    for (int i = tid; i < H_; i += 256) orow[i] = tf32r(w[i] * (xr[i] * r));
}

// ---- RMSNorm2 fused: hid = hs + (p1+p2); x2 = tf32(w*hid*rsqrt) -------------
__global__ void rmsnorm_add_k(const float* __restrict__ hs,
                              const float* __restrict__ p1,
                              const float* __restrict__ p2,
                              const float* __restrict__ w,
                              float* __restrict__ hid, float* __restrict__ o)
{
    const int t = blockIdx.x;
    const int tid = threadIdx.x;
    const size_t base = (size_t)t * H_;
    float s = 0.f;
    for (int i = tid; i < H_; i += 256) {
        const float v = __fadd_rn(hs[base + i], __fadd_rn(p1[base + i], p2[base + i]));
        hid[base + i] = v;
        s = __fmaf_rn(v, v, s);
    }
    for (int off = 16; off; off >>= 1) s += __shfl_down_sync(0xffffffffu, s, off);
    __shared__ float red[8];
    const int wid = tid >> 5, lane = tid & 31;
    if (!lane) red[wid] = s;
    __syncthreads();
    if (tid == 0) {
        float tot = 0.f;
        #pragma unroll
        for (int i = 0; i < 8; i++) tot += red[i];
        red[0] = rsqrtf(tot * (1.0f / H_) + 1e-6f);
    }
    __syncthreads();
    const float r = red[0];
    for (int i = tid; i < H_; i += 256)
        o[base + i] = tf32r(w[i] * (hid[base + i] * r));
}

// ---------------- RoPE (tf32-rounded; also zeroes expert counters) -----------
__global__ void rope_k(float* __restrict__ q, float* __restrict__ k,
                       int* __restrict__ cnt)
{
    if (blockIdx.x == 0 && threadIdx.x < E_) cnt[threadIdx.x] = 0;
    const int idx = blockIdx.x * blockDim.x + threadIdx.x;
    const int half = idx & 31;
    const int rest = idx >> 5;
    const int head = rest % (NH_ + KVH_);
    const int t = rest / (NH_ + KVH_);
    const float inv_freq = __fdiv_rn(1.0f, acc_powf(10000.0f, (float)half * 0.03125f));
    const float ang = __fmul_rn((float)t, inv_freq);
    const float c = acc_cosf(ang);
    const float sn = acc_sinf(ang);
    float* base = (head < NH_) ? (q + (size_t)t * H_ + head * HD_)
                               : (k + (size_t)t * (KVH_ * HD_) + (head - NH_) * HD_);
    const float x1 = base[half];
    const float x2 = base[half + 32];
    base[half]      = tf32r(__fadd_rn(__fmul_rn(x1, c), -__fmul_rn(x2, sn)));
    base[half + 32] = tf32r(__fadd_rn(__fmul_rn(x2, c),  __fmul_rn(x1, sn)));
}

// ---- Attention: split-K two-pass MMA (unchanged from R12) -------------------
#define AQ 128
#define AK 64
#define QSTR 68
#define SMEM_ATTN_A ((AQ*QSTR + 2*AK*QSTR + 512) * 4)
#define SMEM_ATTN_C ((2*AQ*QSTR + 2*AK*QSTR + 2*AQ) * 4)

__device__ __forceinline__ void attn_issue_tile(const float* gbase, float* sbuf, int tid) {
    #pragma unroll
    for (int s = 0; s < 4; s++) {
        const int i = tid + s * 256;
        const int j = i >> 4, d4 = (i & 15) * 4;
        cp16(s2u(&sbuf[j * QSTR + d4]), gbase + (size_t)j * (KVH_ * HD_) + d4);
    }
    cp_commit();
}

__device__ __forceinline__ void attn_mma_scores(
    const float* __restrict__ Qs, const float* __restrict__ KB,
    float accS[2][4][4], int lane, int wm, int wn)
{
    #pragma unroll
    for (int ks = 0; ks < 8; ks++) {
        const int kk = ks * 8 + (lane & 3);
        uint32_t a[2][4], b[4][2];
        #pragma unroll
        for (int mt = 0; mt < 2; mt++) {
            const int r = wm + mt * 16 + (lane >> 2);
            a[mt][0] = __float_as_uint(Qs[r * QSTR + kk]);
            a[mt][1] = __float_as_uint(Qs[(r + 8) * QSTR + kk]);
            a[mt][2] = __float_as_uint(Qs[r * QSTR + kk + 4]);
            a[mt][3] = __float_as_uint(Qs[(r + 8) * QSTR + kk + 4]);
        }
        #pragma unroll
        for (int nt = 0; nt < 4; nt++) {
            const int j = wn + nt * 8 + (lane >> 2);
            b[nt][0] = __float_as_uint(KB[j * QSTR + kk]);
            b[nt][1] = __float_as_uint(KB[j * QSTR + kk + 4]);
        }
        #pragma unroll
        for (int mt = 0; mt < 2; mt++)
            #pragma unroll
            for (int nt = 0; nt < 4; nt++)
                asm volatile(
                    "mma.sync.aligned.m16n8k8.row.col.f32.tf32.tf32.f32 "
                    "{%0,%1,%2,%3}, {%4,%5,%6,%7}, {%8,%9}, {%0,%1,%2,%3};"
                    : "+f"(accS[mt][nt][0]), "+f"(accS[mt][nt][1]),
                      "+f"(accS[mt][nt][2]), "+f"(accS[mt][nt][3])
                    : "r"(a[mt][0]), "r"(a[mt][1]), "r"(a[mt][2]), "r"(a[mt][3]),
                      "r"(b[nt][0]), "r"(b[nt][1]));
    }
}

__global__ void __launch_bounds__(256, 2) attn_a_k(
    const float* __restrict__ q, const float* __restrict__ k,
    float* __restrict__ ml)
{
    extern __shared__ float sm[];
    float* Qs    = sm;
    float* KVa   = Qs + AQ * QSTR;
    float* KVb   = KVa + AK * QSTR;
    float* partM = KVb + AK * QSTR;
    float* partL = partM + 256;

    const int h  = blockIdx.y;
    const int bx = blockIdx.x;
    const int qt = 15 - (bx >> 1);
    const int sp = bx & 1;
    const int q0 = qt * AQ;
    const int tid = threadIdx.x;
    const int lane = tid & 31, wid = tid >> 5;
    const int kvh = h >> 2;
    const int halfT = qt + 1;
    const int ts = sp * halfT, te = ts + halfT;
    const int wm = (wid & 3) * 32, wn = (wid >> 2) * 32;

    const float* kb = k + kvh * HD_;
    attn_issue_tile(kb + (size_t)(ts * AK) * (KVH_ * HD_), KVa, tid);
    for (int i = tid; i < AQ * (HD_ / 4); i += 256) {
        const int qq = i >> 4, d4 = (i & 15) * 4;
        *(float4*)&Qs[qq * QSTR + d4] =
            *(const float4*)(q + (size_t)(q0 + qq) * H_ + h * HD_ + d4);
    }

    float m_old = -1e30f, l_old = 0.f;
    for (int t = ts; t < te; t++) {
        const int k0 = t * AK;
        float* bufX = ((t - ts) & 1) ? KVb : KVa;
        float* bufY = ((t - ts) & 1) ? KVa : KVb;
        if (t + 1 < te) { attn_issue_tile(kb + (size_t)(k0 + AK) * (KVH_ * HD_), bufY, tid); cp_wait1(); }
        else            { cp_wait0(); }
        __syncthreads();

        float accS[2][4][4] = {};
        attn_mma_scores(Qs, bufX, accS, lane, wm, wn);

        #pragma unroll
        for (int mt = 0; mt < 2; mt++)
            #pragma unroll
            for (int half = 0; half < 2; half++) {
                const int row = wm + mt * 16 + (lane >> 2) + half * 8;
                const int qi_r = q0 + row;
                float sv[8];
                float pm = -1e30f;
                #pragma unroll
                for (int nt = 0; nt < 4; nt++)
                    #pragma unroll
                    for (int e2 = 0; e2 < 2; e2++) {
                        const int col = wn + nt * 8 + (lane & 3) * 2 + e2;
                        const float s = accS[mt][nt][half * 2 + e2] * 0.125f;
                        sv[nt * 2 + e2] = (k0 + col <= qi_r) ? s : -1e30f;
                        pm = fmaxf(pm, sv[nt * 2 + e2]);
                    }
                float pl = 0.f;
                #pragma unroll
                for (int x = 0; x < 8; x++)
                    if (sv[x] > -1e29f) pl += acc_expf(sv[x] - pm);
                #pragma unroll
                for (int mm = 1; mm <= 2; mm <<= 1) {
                    const float om = __shfl_xor_sync(0xffffffffu, pm, mm);
                    const float ol = __shfl_xor_sync(0xffffffffu, pl, mm);
                    const float nm = fmaxf(pm, om);
                    pl = pl * acc_expf(pm - nm) + ol * acc_expf(om - nm);
                    pm = nm;
                }
                if ((lane & 3) == 0) {
                    partM[row * 2 + (wn >> 5)] = pm;
                    partL[row * 2 + (wn >> 5)] = pl;
                }
            }
        __syncthreads();
        if (tid < 128) {
            const float mA = partM[tid * 2], mB = partM[tid * 2 + 1];
            const float mt2 = fmaxf(mA, mB);
            const float lt = partL[tid * 2] * acc_expf(mA - mt2)
                           + partL[tid * 2 + 1] * acc_expf(mB - mt2);
            const float mn = fmaxf(m_old, mt2);
            l_old = l_old * acc_expf(m_old - mn) + lt * acc_expf(mt2 - mn);
            m_old = mn;
        }
    }
    if (tid < 128) {
        const int base = ((h * 16 + qt) * 2 + sp) * 256;
        ml[base + tid]       = m_old;
        ml[base + 128 + tid] = l_old;
    }
}

__global__ void __launch_bounds__(256, 2) attn_c_k(
    const float* __restrict__ q, const float* __restrict__ k,
    const float* __restrict__ v, const float* __restrict__ ml,
    float* __restrict__ o0, float* __restrict__ o1)
{
    extern __shared__ float sm[];
    float* Qs   = sm;
    float* SP   = Qs + AQ * QSTR;
    float* KVa  = SP + AQ * QSTR;
    float* KVb  = KVa + AK * QSTR;
    float* mfin = KVb + AK * QSTR;
    float* lfin = mfin + AQ;

    const int h  = blockIdx.y;
    const int bx = blockIdx.x;
    const int qt = 15 - (bx >> 1);
    const int sp = bx & 1;
    const int q0 = qt * AQ;
    const int tid = threadIdx.x;
    const int lane = tid & 31, wid = tid >> 5;
    const int kvh = h >> 2;
    const int halfT = qt + 1;
    const int ts = sp * halfT, te = ts + halfT;
    const int wm = (wid & 3) * 32, wn = (wid >> 2) * 32;

    const float* kb = k + kvh * HD_;
    const float* vb = v + kvh * HD_;
    attn_issue_tile(kb + (size_t)(ts * AK) * (KVH_ * HD_), KVa, tid);

    if (tid < 128) {
        const int b = (h * 16 + qt) * 2 * 256;
        const float mA = ml[b + tid],       lA = ml[b + 128 + tid];
        const float mB = ml[b + 256 + tid], lB = ml[b + 384 + tid];
        const float mq = fmaxf(mA, mB);
        mfin[tid] = mq;
        lfin[tid] = lA * acc_expf(mA - mq) + lB * acc_expf(mB - mq);
    }
    for (int i = tid; i < AQ * (HD_ / 4); i += 256) {
        const int qq = i >> 4, d4 = (i & 15) * 4;
        *(float4*)&Qs[qq * QSTR + d4] =
            *(const float4*)(q + (size_t)(q0 + qq) * H_ + h * HD_ + d4);
    }

    float accO[2][4][4] = {};
    for (int t = ts; t < te; t++) {
        const int k0 = t * AK;
        float* bufX = ((t - ts) & 1) ? KVb : KVa;
        float* bufY = ((t - ts) & 1) ? KVa : KVb;
        __syncthreads();
        if (t + 1 < te) { attn_issue_tile(kb + (size_t)(k0 + AK) * (KVH_ * HD_), bufY, tid); cp_wait1(); }
        else            { cp_wait0(); }
        __syncthreads();

        float accS[2][4][4] = {};
        attn_mma_scores(Qs, bufX, accS, lane, wm, wn);
        __syncthreads();
        attn_issue_tile(vb + (size_t)k0 * (KVH_ * HD_), bufX, tid);

        #pragma unroll
        for (int mt = 0; mt < 2; mt++)
            #pragma unroll
            for (int half = 0; half < 2; half++) {
                const int row = wm + mt * 16 + (lane >> 2) + half * 8;
                const float mq = mfin[row];
                const float lq = lfin[row];
                #pragma unroll
                for (int nt = 0; nt < 4; nt++)
                    #pragma unroll
                    for (int e2 = 0; e2 < 2; e2++) {
                        const int col = wn + nt * 8 + (lane & 3) * 2 + e2;
                        float p = 0.f;
                        if (k0 + col <= q0 + row) {
                            const float s = accS[mt][nt][half * 2 + e2] * 0.125f;
                            p = tf32r(__fdiv_rn(acc_expf(s - mq), lq));
                        }
                        SP[row * QSTR + col] = p;
                    }
            }
        cp_wait0();
        __syncthreads();

        #pragma unroll
        for (int ks = 0; ks < 8; ks++) {
            const int kk = ks * 8 + (lane & 3);
            uint32_t a[2][4], b[4][2];
            #pragma unroll
            for (int mt = 0; mt < 2; mt++) {
                const int r = wm + mt * 16 + (lane >> 2);
                a[mt][0] = __float_as_uint(SP[r * QSTR + kk]);
                a[mt][1] = __float_as_uint(SP[(r + 8) * QSTR + kk]);
                a[mt][2] = __float_as_uint(SP[r * QSTR + kk + 4]);
                a[mt][3] = __float_as_uint(SP[(r + 8) * QSTR + kk + 4]);
            }
            #pragma unroll
            for (int nt = 0; nt < 4; nt++) {
                const int d = wn + nt * 8 + (lane >> 2);
                b[nt][0] = __float_as_uint(bufX[kk * QSTR + d]);
                b[nt][1] = __float_as_uint(bufX[(kk + 4) * QSTR + d]);
            }
            #pragma unroll
            for (int mt = 0; mt < 2; mt++)
                #pragma unroll
                for (int nt = 0; nt < 4; nt++)
                    asm volatile(
                        "mma.sync.aligned.m16n8k8.row.col.f32.tf32.tf32.f32 "
                        "{%0,%1,%2,%3}, {%4,%5,%6,%7}, {%8,%9}, {%0,%1,%2,%3};"
                        : "+f"(accO[mt][nt][0]), "+f"(accO[mt][nt][1]),
                          "+f"(accO[mt][nt][2]), "+f"(accO[mt][nt][3])
                        : "r"(a[mt][0]), "r"(a[mt][1]), "r"(a[mt][2]), "r"(a[mt][3]),
                          "r"(b[nt][0]), "r"(b[nt][1]));
        }
    }

    float* od = sp ? o1 : o0;
    #pragma unroll
    for (int mt = 0; mt < 2; mt++)
        #pragma unroll
        for (int half = 0; half < 2; half++) {
            const int row = q0 + wm + mt * 16 + (lane >> 2) + half * 8;
            #pragma unroll
            for (int nt = 0; nt < 4; nt++) {
                const int col = wn + nt * 8 + (lane & 3) * 2;
                float2 r2;
                r2.x = accO[mt][nt][half * 2 + 0];
                r2.y = accO[mt][nt][half * 2 + 1];
                *(float2*)(od + (size_t)row * H_ + h * HD_ + col) = r2;
            }
        }
}

// att = tf32r(att + attP)
__global__ void addO_k(float* __restrict__ a, const float* __restrict__ b)
{
    const size_t i = ((size_t)blockIdx.x * 256 + threadIdx.x) * 4;
    float4 x = *(float4*)(a + i);
    const float4 y = *(const float4*)(b + i);
    x.x = tf32r(x.x + y.x); x.y = tf32r(x.y + y.y);
    x.z = tf32r(x.z + y.z); x.w = tf32r(x.w + y.w);
    *(float4*)(a + i) = x;
}

// ---------------- router ----------------
__global__ void router_k(const float* __restrict__ x, const float* __restrict__ rw,
                         int* __restrict__ cnt, int* __restrict__ list,
                         float* __restrict__ wout)
{
    const int t = blockIdx.x;
    const int tid = threadIdx.x;
    const int e = tid >> 5, lane = tid & 31;
    const float* xr = x + (size_t)t * H_;
    float s = 0.f;
    for (int i = lane; i < H_; i += 32)
        s = __fmaf_rn(tf32r(xr[i]), tf32r(rw[i * E_ + e]), s);
    for (int off = 16; off; off >>= 1) s += __shfl_down_sync(0xffffffffu, s, off);
    __shared__ float logit[E_];
    if (!lane) logit[e] = s;
    __syncthreads();
    if (tid == 0) {
        float mx = logit[0];
        #pragma unroll
        for (int i = 1; i < E_; i++) mx = fmaxf(mx, logit[i]);
        float p[E_];
        #pragma unroll
        for (int i = 0; i < E_; i++) p[i] = acc_expf(logit[i] - mx);
        int i0 = 0;
        #pragma unroll
        for (int i = 1; i < E_; i++) if (p[i] > p[i0]) i0 = i;
        int i1 = (i0 == 0) ? 1 : 0;
        #pragma unroll
        for (int i = 0; i < E_; i++) if (i != i0 && p[i] > p[i1]) i1 = i;
        const float denom = p[i0] + p[i1];
        wout[2 * t + 0] = __fdiv_rn(p[i0], denom);
        wout[2 * t + 1] = __fdiv_rn(p[i1], denom);
        int pos = atomicAdd(&cnt[i0], 1);
        list[i0 * S_ + pos] = 2 * t;
        pos = atomicAdd(&cnt[i1], 1);
        list[i1 * S_ + pos] = 2 * t + 1;
    }
}

// -- final combine: out = (hid + (sp1+sp2)) + (w0*(e0a+e0b) + w1*(e1a+e1b)) ----
__global__ void combine_k(float* __restrict__ out, const float* __restrict__ hid,
                          const float* __restrict__ eoP, const float* __restrict__ spP,
                          const float* __restrict__ w)
{
    const int t = blockIdx.x;
    const float w0 = w[2 * t], w1 = w[2 * t + 1];
    const size_t eoStride = (size_t)(2 * S_) * H_;
    const size_t spStride = (size_t)S_ * H_;
    const float* e0a = eoP + (size_t)(2 * t) * H_;
    const float* e1a = eoP + (size_t)(2 * t + 1) * H_;
    const float* sp1 = spP + (size_t)t * H_;
    for (int i = threadIdx.x; i < H_; i += 256) {
        const float shared2 = __fadd_rn(sp1[i], sp1[spStride + i]);
        const float r0 = __fadd_rn(e0a[i], e0a[eoStride + i]);
        const float r1 = __fadd_rn(e1a[i], e1a[eoStride + i]);
        const float routed = __fmaf_rn(w0, r0, __fmul_rn(w1, r1));
        out[(size_t)t * H_ + i] =
            __fadd_rn(__fadd_rn(hid[(size_t)t * H_ + i], shared2), routed);
    }
}

// ---------------- host launch --------------------------------------------------
extern "C" void kernel_launch(void* const* d_in, const int* in_sizes, int n_in,
                              void* d_out, int out_size)
{
    const float* hs  = (const float*)d_in[0];
    const float* ln1 = (const float*)d_in[1];
    const float* wq  = (const float*)d_in[2];
    const float* wk  = (const float*)d_in[3];
    const float* wv  = (const float*)d_in[4];
    const float* wo  = (const float*)d_in[5];
    const float* ln2 = (const float*)d_in[6];
    const float* sw1 = (const float*)d_in[7];
    const float* sw2 = (const float*)d_in[8];
    const float* ew1 = (const float*)d_in[9];
    const float* ew2 = (const float*)d_in[10];
    const float* rw  = (const float*)d_in[11];
    float* out = (float*)d_out;

    float *x1, *q, *k, *v, *att, *attP, *mlb, *hid, *x2, *hsv, *hcol, *eoP, *spP, *wts;
    int *cnt, *list;
    cudaGetSymbolAddress((void**)&x1,   g_x1);
    cudaGetSymbolAddress((void**)&q,    g_q);
    cudaGetSymbolAddress((void**)&k,    g_k);
    cudaGetSymbolAddress((void**)&v,    g_v);
    cudaGetSymbolAddress((void**)&att,  g_att);
    cudaGetSymbolAddress((void**)&attP, g_attP);
    cudaGetSymbolAddress((void**)&mlb,  g_ml);
    cudaGetSymbolAddress((void**)&hid,  g_hidden);
    cudaGetSymbolAddress((void**)&x2,   g_x2);
    cudaGetSymbolAddress((void**)&hsv,  g_hs);
    cudaGetSymbolAddress((void**)&hcol, g_hcol);
    cudaGetSymbolAddress((void**)&eoP,  g_eoP);
    cudaGetSymbolAddress((void**)&spP,  g_spP);
    cudaGetSymbolAddress((void**)&wts,  g_wts);
    cudaGetSymbolAddress((void**)&cnt,  g_cnt);
    cudaGetSymbolAddress((void**)&list, g_list);

    cudaFuncSetAttribute(mma_gemm_k<0,0,0,1,0,0>, cudaFuncAttributeMaxDynamicSharedMemorySize, SMEM_GEMM);
    cudaFuncSetAttribute(mma_gemm_k<0,0,0,0,0,1>, cudaFuncAttributeMaxDynamicSharedMemorySize, SMEM_GEMM);
    cudaFuncSetAttribute(mma_gemm_k<1,2,1,0,1,0>, cudaFuncAttributeMaxDynamicSharedMemorySize, SMEM_GEMM);
    cudaFuncSetAttribute(mma_gemm_k<0,2,0,0,0,1>, cudaFuncAttributeMaxDynamicSharedMemorySize, SMEM_GEMM);
    cudaFuncSetAttribute(attn_a_k, cudaFuncAttributeMaxDynamicSharedMemorySize, SMEM_ATTN_A);
    cudaFuncSetAttribute(attn_c_k, cudaFuncAttributeMaxDynamicSharedMemorySize, SMEM_ATTN_C);

    // 1. rmsnorm1
    rmsnorm_k<<<S_, 256>>>(hs, ln1, x1);
    // 2. fused QKV projection
    mma_gemm_k<0,0,0,1,0,0><<<dim3(12, S_ / BM), 256, SMEM_GEMM>>>(
        x1, wq, q, nullptr, nullptr, nullptr, wk, wv, k, v, H_, H_);
    // 3. RoPE (+ zero expert counters)
    rope_k<<<(S_ * (NH_ + KVH_) * 32) / 256, 256>>>(q, k, cnt);
    // 4. attention: split-K two-pass
    attn_a_k<<<dim3(32, NH_), 256, SMEM_ATTN_A>>>(q, k, mlb);
    attn_c_k<<<dim3(32, NH_), 256, SMEM_ATTN_C>>>(q, k, v, mlb, att, attP);
    addO_k<<<(S_ * H_) / 1024, 256>>>(att, attP);
    // 5. O-proj, 2-way K split into partials p1=x1, p2=attP (both free now)
    mma_gemm_k<0,0,0,0,0,1><<<dim3(H_ / BN, S_ / BM, 2), 256, SMEM_GEMM>>>(
        att, wo, x1, nullptr, nullptr, nullptr, nullptr, nullptr, attP, nullptr, H_, H_);
    // 6. rmsnorm2 fused with residual+partial sum
    rmsnorm_add_k<<<S_, 256>>>(hs, x1, attP, ln2, hid, x2);
    // 7. router
    router_k<<<S_, 256>>>(x2, rw, cnt, list, wts);
    // 8. fused shared-MLP-1 + expert-1
    mma_gemm_k<1,2,1,0,1,0><<<dim3(I_ / BN, S_ / BM, E_ + 1), 256, SMEM_GEMM>>>(
        x2, ew1, hcol, nullptr, list, cnt, sw1, x2, hsv, nullptr, I_, H_);
    // 9. fused shared-MLP-2 + expert-2, 2-way K split into partial buffers
    mma_gemm_k<0,2,0,0,0,1><<<dim3(H_ / BN, S_ / BM, 2 * (E_ + 1)), 256, SMEM_GEMM>>>(
        hcol, ew2, eoP, nullptr, list, cnt, sw2, hsv, spP, nullptr, H_, I_);
    // 10. combine everything into out
    combine_k<<<S_, 256>>>(out, hid, eoP, spP, wts);
}

// round 17
// speedup vs baseline: 1.8971x; 1.0080x over previous
#include <cuda_runtime.h>
#include <cstdint>
#include <math.h>

#define S_   2048
#define H_   1024
#define NH_  16
#define KVH_ 4
#define HD_  64
#define E_   8
#define I_   4096

// ---------------- accurate math helpers ------------------
#ifdef __FAST_MATH__
__device__ __forceinline__ float acc_expf(float x) { return (float)exp((double)x); }
__device__ __forceinline__ float acc_cosf(float x) { return (float)cos((double)x); }
__device__ __forceinline__ float acc_sinf(float x) { return (float)sin((double)x); }
__device__ __forceinline__ float acc_powf(float a, float b) { return (float)pow((double)a, (double)b); }
#else
__device__ __forceinline__ float acc_expf(float x) { return expf(x); }
__device__ __forceinline__ float acc_cosf(float x) { return cosf(x); }
__device__ __forceinline__ float acc_sinf(float x) { return sinf(x); }
__device__ __forceinline__ float acc_powf(float a, float b) { return powf(a, b); }
#endif

__device__ __forceinline__ float tf32r(float x) {
    uint32_t u;
    asm("cvt.rna.tf32.f32 %0, %1;" : "=r"(u) : "f"(x));
    return __uint_as_float(u);
}
__device__ __forceinline__ uint32_t tf32u(float x) {
    uint32_t u;
    asm("cvt.rna.tf32.f32 %0, %1;" : "=r"(u) : "f"(x));
    return u;
}
__device__ __forceinline__ float4 tf32r4(float4 v) {
    v.x = tf32r(v.x); v.y = tf32r(v.y); v.z = tf32r(v.z); v.w = tf32r(v.w);
    return v;
}
__device__ __forceinline__ float silu_f(float v) {
    return __fdiv_rn(v, 1.0f + acc_expf(-v));
}

__device__ __forceinline__ uint32_t s2u(const void* p) {
    return (uint32_t)__cvta_generic_to_shared(p);
}
__device__ __forceinline__ void cp16(uint32_t dst, const float* src) {
    asm volatile("cp.async.ca.shared.global [%0], [%1], 16;\n" :: "r"(dst), "l"(src));
}
__device__ __forceinline__ void cp_commit() {
    asm volatile("cp.async.commit_group;\n" ::);
}
__device__ __forceinline__ void cp_wait1() {
    asm volatile("cp.async.wait_group 1;\n" ::);
}
__device__ __forceinline__ void cp_wait0() {
    asm volatile("cp.async.wait_group 0;\n" ::);
}

// ---------------- scratch ----------------
__device__ float g_x1[S_*H_];            // rmsnorm1 out; later O-proj partial 0
__device__ float g_q[S_*H_];
__device__ float g_k[S_*KVH_*HD_];
__device__ float g_v[S_*KVH_*HD_];
__device__ float g_att[S_*H_];
__device__ float g_attP[S_*H_];          // attn partial; later O-proj partial 1
__device__ float g_ml[NH_*16*2*256];
__device__ float g_hidden[S_*H_];
__device__ float g_x2[S_*H_];
__device__ float g_hs[S_*I_];
__device__ float g_hcol[(S_*2)*I_];
__device__ float g_eoP[2*(S_*2)*H_];     // expert-out partials, split-stride 2S*H
__device__ float g_spP[2*S_*H_];         // shared-MLP2 partials, split-stride S*H
__device__ int   g_cnt[E_];
__device__ int   g_list[E_*S_];
__device__ float g_wts[S_*2];

// ---------------- TF32 tensor-core GEMM, BKT=16, 3-stage cp.async ------------
// A operands pre-rounded tf32 by producers -> raw fragment reads; B (weights) cvt.
#define BM  128
#define BN  128
#define BKT 16
#define NST 3
#define ASTR 20
#define BSTR 136
#define SMEM_GEMM ((NST*BM*ASTR + NST*BKT*BSTR) * 4)

// MODE: 0 plain, 2 fused (zi==0 shared via B2/B3/C2, zi>0 gather expert via list)
// KSPLIT: 2-way K split; outputs offset by ksp*stride (MODE2) or C/C2 (MODE0)
template<int EPI, int MODE, int SHIFT, int QKV, int EPI2, int KSPLIT>
__global__ void __launch_bounds__(256, 2) mma_gemm_k(
    const float* __restrict__ A, const float* __restrict__ B,
    float* __restrict__ C, const float* __restrict__ R,
    const int* __restrict__ list, const int* __restrict__ cnt,
    const float* __restrict__ B2, const float* __restrict__ B3,
    float* __restrict__ C2, float* __restrict__ C3,
    int N, int K)
{
    extern __shared__ float dsm[];
    float* As = dsm;                    // [NST][BM][ASTR]
    float* Bs = dsm + NST * BM * ASTR;  // [NST][BKT][BSTR]

    int n_rows = S_;
    const float* Az = A;
    const float* Bz = B;
    float* Cz = C;
    bool gat = false;
    int zoff = 0;
    int Nl = N;
    int n0 = blockIdx.x * BN;

    int ksp = 0, zi = blockIdx.z;
    if (KSPLIT) {
        if (MODE == 2) { ksp = blockIdx.z / (E_ + 1); zi = blockIdx.z % (E_ + 1); }
        else           { ksp = blockIdx.z; zi = 0; if (ksp) Cz = C2; }
    }
    bool sharedSide = false;
    if (MODE == 2) {
        if (zi == 0) {
            Az = B3; Bz = B2; sharedSide = true;
            Cz = C2 + (KSPLIT ? (size_t)ksp * S_ * N : 0);
        } else {
            const int e = zi - 1;
            n_rows = cnt[e];
            if ((int)blockIdx.y * BM >= n_rows) return;
            zoff = e * S_;
            Bz = B + (size_t)e * K * N;
            gat = true;
            Cz = C + (KSPLIT ? (size_t)ksp * (2 * S_) * N : 0);
        }
    }
    if (QKV) {
        const int bx = blockIdx.x;
        if (bx < 8)       { Bz = B;  Cz = C;  Nl = 1024; n0 = bx * BN; }
        else if (bx < 10) { Bz = B2; Cz = C2; Nl = 256;  n0 = (bx - 8) * BN; }
        else              { Bz = B3; Cz = C3; Nl = 256;  n0 = (bx - 10) * BN; }
    }

    const int Keff = KSPLIT ? (K >> 1) : K;
    const int koff = KSPLIT ? ksp * Keff : 0;

    const int tid  = threadIdx.x;
    const int lane = tid & 31;
    const int wid  = tid >> 5;
    const int wm   = (wid & 1) * 64;
    const int wn   = (wid >> 1) * 32;
    const int m0   = blockIdx.y * BM;

    // loaders: 2 A-float4 + 2 B-float4 per thread per stage (BKT=16)
    const int aIdx0 = tid, aIdx1 = tid + 256;
    const int r0 = m0 + (aIdx0 >> 2), r1 = m0 + (aIdx1 >> 2);
    int gar0 = r0, gar1 = r1;
    if (gat) {
        gar0 = (r0 < n_rows) ? (list[zoff + r0] >> SHIFT) : 0;
        gar1 = (r1 < n_rows) ? (list[zoff + r1] >> SHIFT) : 0;
    }
    const float* Ag0 = Az + (size_t)gar0 * K + koff + (aIdx0 & 3) * 4;
    const float* Ag1 = Az + (size_t)gar1 * K + koff + (aIdx1 & 3) * 4;
    const float* Bg0 = Bz + (size_t)(koff + (tid >> 5)) * Nl + n0 + (tid & 31) * 4;
    const float* Bg1 = Bg0 + (size_t)8 * Nl;

    const uint32_t sa0 = s2u(&As[(size_t)(aIdx0 >> 2) * ASTR + (aIdx0 & 3) * 4]);
    const uint32_t sa1 = s2u(&As[(size_t)(aIdx1 >> 2) * ASTR + (aIdx1 & 3) * 4]);
    const uint32_t sb0 = s2u(&Bs[(size_t)(tid >> 5) * BSTR + (tid & 31) * 4]);
    const uint32_t sb1 = s2u(&Bs[(size_t)((tid >> 5) + 8) * BSTR + (tid & 31) * 4]);
    const uint32_t aStgB = BM * ASTR * 4;
    const uint32_t bStgB = BKT * BSTR * 4;

    float acc[4][4][4] = {};
    const int nk = Keff / BKT;

    auto load_stage = [&](int sbuf, int c) {
        const int k0 = c * BKT;
        cp16(sa0 + sbuf * aStgB, Ag0 + k0);
        cp16(sa1 + sbuf * aStgB, Ag1 + k0);
        cp16(sb0 + sbuf * bStgB, Bg0 + (size_t)k0 * Nl);
        cp16(sb1 + sbuf * bStgB, Bg1 + (size_t)k0 * Nl);
        cp_commit();
    };

    load_stage(0, 0);
    load_stage(1, 1);

    for (int c = 0; c < nk; c++) {
        cp_wait1();
        __syncthreads();
        const int buf = c % NST;
        if (c + NST - 1 < nk) load_stage((c + NST - 1) % NST, c + NST - 1);

        const float* Ab = As + (size_t)buf * BM * ASTR;
        const float* Bb = Bs + (size_t)buf * BKT * BSTR;
        #pragma unroll
        for (int ks = 0; ks < 2; ks++) {
            const int kk = ks * 8 + (lane & 3);
            uint32_t a[4][4], b[4][2];
            #pragma unroll
            for (int mt = 0; mt < 4; mt++) {
                const int m = wm + mt * 16 + (lane >> 2);
                a[mt][0] = __float_as_uint(Ab[(size_t)m * ASTR + kk]);
                a[mt][1] = __float_as_uint(Ab[(size_t)(m + 8) * ASTR + kk]);
                a[mt][2] = __float_as_uint(Ab[(size_t)m * ASTR + kk + 4]);
                a[mt][3] = __float_as_uint(Ab[(size_t)(m + 8) * ASTR + kk + 4]);
            }
            #pragma unroll
            for (int nt = 0; nt < 4; nt++) {
                const int nn = wn + nt * 8 + (lane >> 2);
                b[nt][0] = tf32u(Bb[(size_t)kk * BSTR + nn]);
                b[nt][1] = tf32u(Bb[(size_t)(kk + 4) * BSTR + nn]);
            }
            #pragma unroll
            for (int mt = 0; mt < 4; mt++)
                #pragma unroll
                for (int nt = 0; nt < 4; nt++)
                    asm volatile(
                        "mma.sync.aligned.m16n8k8.row.col.f32.tf32.tf32.f32 "
                        "{%0,%1,%2,%3}, {%4,%5,%6,%7}, {%8,%9}, {%0,%1,%2,%3};"
                        : "+f"(acc[mt][nt][0]), "+f"(acc[mt][nt][1]),
                          "+f"(acc[mt][nt][2]), "+f"(acc[mt][nt][3])
                        : "r"(a[mt][0]), "r"(a[mt][1]), "r"(a[mt][2]), "r"(a[mt][3]),
                          "r"(b[nt][0]), "r"(b[nt][1]));
        }
    }

    const bool rndSt = QKV && ((int)blockIdx.x >= 10);   // v output pre-rounded
    #pragma unroll
    for (int mt = 0; mt < 4; mt++) {
        #pragma unroll
        for (int half = 0; half < 2; half++) {
            const int r = m0 + wm + mt * 16 + (lane >> 2) + half * 8;
            if (gat && r >= n_rows) continue;
            size_t crow_idx = r;
            if (gat) crow_idx = (size_t)list[zoff + r];
            float* crow = Cz + crow_idx * Nl;
            const int epi = sharedSide ? EPI2 : EPI;
            #pragma unroll
            for (int nt = 0; nt < 4; nt++) {
                const int col = n0 + wn + nt * 8 + (lane & 3) * 2;
                float2 v;
                v.x = acc[mt][nt][half * 2 + 0];
                v.y = acc[mt][nt][half * 2 + 1];
                if (epi == 1) {
                    v.x = tf32r(silu_f(v.x)); v.y = tf32r(silu_f(v.y));
                } else if (rndSt) {
                    v.x = tf32r(v.x); v.y = tf32r(v.y);
                }
                *(float2*)(crow + col) = v;
            }
        }
    }
}

// ---------------- RMSNorm (tf32-rounded output) ----------------
__global__ void rmsnorm_k(const float* __restrict__ x, const float* __restrict__ w,
                          float* __restrict__ o)
{
    const int t = blockIdx.x;
    const int tid = threadIdx.x;
    const float* xr = x + (size_t)t * H_;
    float s = 0.f;
    for (int i = tid; i < H_; i += 256) { float v = xr[i]; s = __fmaf_rn(v, v, s); }
    for (int off = 16; off; off >>= 1) s += __shfl_down_sync(0xffffffffu, s, off);
    __shared__ float red[8];
    const int wid = tid >> 5, lane = tid & 31;
    if (!lane) red[wid] = s;
    __syncthreads();
    if (tid == 0) {
        float tot = 0.f;
        #pragma unroll
        for (int i = 0; i < 8; i++) tot += red[i];
        red[0] = rsqrtf(tot * (1.0f / H_) + 1e-6f);
    }
    __syncthreads();
    const float r = red[0];
    float* orow = o + (size_t)t * H_;
    for (int i = tid; i < H_; i += 256) orow[i] = tf32r(w[i] * (xr[i] * r));
}

// ---- RMSNorm2 fused: hid = hs + (p1+p2); x2 = tf32(w*hid*rsqrt) -------------
__global__ void rmsnorm_add_k(const float* __restrict__ hs,
                              const float* __restrict__ p1,
                              const float* __restrict__ p2,
                              const float* __restrict__ w,
                              float* __restrict__ hid, float* __restrict__ o)
{
    const int t = blockIdx.x;
    const int tid = threadIdx.x;
    const size_t base = (size_t)t * H_;
    float s = 0.f;
    for (int i = tid; i < H_; i += 256) {
        const float v = __fadd_rn(hs[base + i], __fadd_rn(p1[base + i], p2[base + i]));
        hid[base + i] = v;
        s = __fmaf_rn(v, v, s);
    }
    for (int off = 16; off; off >>= 1) s += __shfl_down_sync(0xffffffffu, s, off);
    __shared__ float red[8];
    const int wid = tid >> 5, lane = tid & 31;
    if (!lane) red[wid] = s;
    __syncthreads();
    if (tid == 0) {
        float tot = 0.f;
        #pragma unroll
        for (int i = 0; i < 8; i++) tot += red[i];
        red[0] = rsqrtf(tot * (1.0f / H_) + 1e-6f);
    }
    __syncthreads();
    const float r = red[0];
    for (int i = tid; i < H_; i += 256)
        o[base + i] = tf32r(w[i] * (hid[base + i] * r));
}

// ---------------- RoPE (tf32-rounded; also zeroes expert counters) -----------
__global__ void rope_k(float* __restrict__ q, float* __restrict__ k,
                       int* __restrict__ cnt)
{
    if (blockIdx.x == 0 && threadIdx.x < E_) cnt[threadIdx.x] = 0;
    const int idx = blockIdx.x * blockDim.x + threadIdx.x;
    const int half = idx & 31;
    const int rest = idx >> 5;
    const int head = rest % (NH_ + KVH_);
    const int t = rest / (NH_ + KVH_);
    const float inv_freq = __fdiv_rn(1.0f, acc_powf(10000.0f, (float)half * 0.03125f));
    const float ang = __fmul_rn((float)t, inv_freq);
    const float c = acc_cosf(ang);
    const float sn = acc_sinf(ang);
    float* base = (head < NH_) ? (q + (size_t)t * H_ + head * HD_)
                               : (k + (size_t)t * (KVH_ * HD_) + (head - NH_) * HD_);
    const float x1 = base[half];
    const float x2 = base[half + 32];
    base[half]      = tf32r(__fadd_rn(__fmul_rn(x1, c), -__fmul_rn(x2, sn)));
    base[half + 32] = tf32r(__fadd_rn(__fmul_rn(x2, c),  __fmul_rn(x1, sn)));
}

// ---- Attention: split-K two-pass MMA (unchanged) ----------------------------
#define AQ 128
#define AK 64
#define QSTR 68
#define SMEM_ATTN_A ((AQ*QSTR + 2*AK*QSTR + 512) * 4)
#define SMEM_ATTN_C ((2*AQ*QSTR + 2*AK*QSTR + 2*AQ) * 4)

__device__ __forceinline__ void attn_issue_tile(const float* gbase, float* sbuf, int tid) {
    #pragma unroll
    for (int s = 0; s < 4; s++) {
        const int i = tid + s * 256;
        const int j = i >> 4, d4 = (i & 15) * 4;
        cp16(s2u(&sbuf[j * QSTR + d4]), gbase + (size_t)j * (KVH_ * HD_) + d4);
    }
    cp_commit();
}

__device__ __forceinline__ void attn_mma_scores(
    const float* __restrict__ Qs, const float* __restrict__ KB,
    float accS[2][4][4], int lane, int wm, int wn)
{
    #pragma unroll
    for (int ks = 0; ks < 8; ks++) {
        const int kk = ks * 8 + (lane & 3);
        uint32_t a[2][4], b[4][2];
        #pragma unroll
        for (int mt = 0; mt < 2; mt++) {
            const int r = wm + mt * 16 + (lane >> 2);
            a[mt][0] = __float_as_uint(Qs[r * QSTR + kk]);
            a[mt][1] = __float_as_uint(Qs[(r + 8) * QSTR + kk]);
            a[mt][2] = __float_as_uint(Qs[r * QSTR + kk + 4]);
            a[mt][3] = __float_as_uint(Qs[(r + 8) * QSTR + kk + 4]);
        }
        #pragma unroll
        for (int nt = 0; nt < 4; nt++) {
            const int j = wn + nt * 8 + (lane >> 2);
            b[nt][0] = __float_as_uint(KB[j * QSTR + kk]);
            b[nt][1] = __float_as_uint(KB[j * QSTR + kk + 4]);
        }
        #pragma unroll
        for (int mt = 0; mt < 2; mt++)
            #pragma unroll
            for (int nt = 0; nt < 4; nt++)
                asm volatile(
                    "mma.sync.aligned.m16n8k8.row.col.f32.tf32.tf32.f32 "
                    "{%0,%1,%2,%3}, {%4,%5,%6,%7}, {%8,%9}, {%0,%1,%2,%3};"
                    : "+f"(accS[mt][nt][0]), "+f"(accS[mt][nt][1]),
                      "+f"(accS[mt][nt][2]), "+f"(accS[mt][nt][3])
                    : "r"(a[mt][0]), "r"(a[mt][1]), "r"(a[mt][2]), "r"(a[mt][3]),
                      "r"(b[nt][0]), "r"(b[nt][1]));
    }
}

__global__ void __launch_bounds__(256, 2) attn_a_k(
    const float* __restrict__ q, const float* __restrict__ k,
    float* __restrict__ ml)
{
    extern __shared__ float sm[];
    float* Qs    = sm;
    float* KVa   = Qs + AQ * QSTR;
    float* KVb   = KVa + AK * QSTR;
    float* partM = KVb + AK * QSTR;
    float* partL = partM + 256;

    const int h  = blockIdx.y;
    const int bx = blockIdx.x;
    const int qt = 15 - (bx >> 1);
    const int sp = bx & 1;
    const int q0 = qt * AQ;
    const int tid = threadIdx.x;
    const int lane = tid & 31, wid = tid >> 5;
    const int kvh = h >> 2;
    const int halfT = qt + 1;
    const int ts = sp * halfT, te = ts + halfT;
    const int wm = (wid & 3) * 32, wn = (wid >> 2) * 32;

    const float* kb = k + kvh * HD_;
    attn_issue_tile(kb + (size_t)(ts * AK) * (KVH_ * HD_), KVa, tid);
    for (int i = tid; i < AQ * (HD_ / 4); i += 256) {
        const int qq = i >> 4, d4 = (i & 15) * 4;
        *(float4*)&Qs[qq * QSTR + d4] =
            *(const float4*)(q + (size_t)(q0 + qq) * H_ + h * HD_ + d4);
    }

    float m_old = -1e30f, l_old = 0.f;
    for (int t = ts; t < te; t++) {
        const int k0 = t * AK;
        float* bufX = ((t - ts) & 1) ? KVb : KVa;
        float* bufY = ((t - ts) & 1) ? KVa : KVb;
        if (t + 1 < te) { attn_issue_tile(kb + (size_t)(k0 + AK) * (KVH_ * HD_), bufY, tid); cp_wait1(); }
        else            { cp_wait0(); }
        __syncthreads();

        float accS[2][4][4] = {};
        attn_mma_scores(Qs, bufX, accS, lane, wm, wn);

        #pragma unroll
        for (int mt = 0; mt < 2; mt++)
            #pragma unroll
            for (int half = 0; half < 2; half++) {
                const int row = wm + mt * 16 + (lane >> 2) + half * 8;
                const int qi_r = q0 + row;
                float sv[8];
                float pm = -1e30f;
                #pragma unroll
                for (int nt = 0; nt < 4; nt++)
                    #pragma unroll
                    for (int e2 = 0; e2 < 2; e2++) {
                        const int col = wn + nt * 8 + (lane & 3) * 2 + e2;
                        const float s = accS[mt][nt][half * 2 + e2] * 0.125f;
                        sv[nt * 2 + e2] = (k0 + col <= qi_r) ? s : -1e30f;
                        pm = fmaxf(pm, sv[nt * 2 + e2]);
                    }
                float pl = 0.f;
                #pragma unroll
                for (int x = 0; x < 8; x++)
                    if (sv[x] > -1e29f) pl += acc_expf(sv[x] - pm);
                #pragma unroll
                for (int mm = 1; mm <= 2; mm <<= 1) {
                    const float om = __shfl_xor_sync(0xffffffffu, pm, mm);
                    const float ol = __shfl_xor_sync(0xffffffffu, pl, mm);
                    const float nm = fmaxf(pm, om);
                    pl = pl * acc_expf(pm - nm) + ol * acc_expf(om - nm);
                    pm = nm;
                }
                if ((lane & 3) == 0) {
                    partM[row * 2 + (wn >> 5)] = pm;
                    partL[row * 2 + (wn >> 5)] = pl;
                }
            }
        __syncthreads();
        if (tid < 128) {
            const float mA = partM[tid * 2], mB = partM[tid * 2 + 1];
            const float mt2 = fmaxf(mA, mB);
            const float lt = partL[tid * 2] * acc_expf(mA - mt2)
                           + partL[tid * 2 + 1] * acc_expf(mB - mt2);
            const float mn = fmaxf(m_old, mt2);
            l_old = l_old * acc_expf(m_old - mn) + lt * acc_expf(mt2 - mn);
            m_old = mn;
        }
    }
    if (tid < 128) {
        const int base = ((h * 16 + qt) * 2 + sp) * 256;
        ml[base + tid]       = m_old;
        ml[base + 128 + tid] = l_old;
    }
}

__global__ void __launch_bounds__(256, 2) attn_c_k(
    const float* __restrict__ q, const float* __restrict__ k,
    const float* __restrict__ v, const float* __restrict__ ml,
    float* __restrict__ o0, float* __restrict__ o1)
{
    extern __shared__ float sm[];
    float* Qs   = sm;
    float* SP   = Qs + AQ * QSTR;
    float* KVa  = SP + AQ * QSTR;
    float* KVb  = KVa + AK * QSTR;
    float* mfin = KVb + AK * QSTR;
    float* lfin = mfin + AQ;

    const int h  = blockIdx.y;
    const int bx = blockIdx.x;
    const int qt = 15 - (bx >> 1);
    const int sp = bx & 1;
    const int q0 = qt * AQ;
    const int tid = threadIdx.x;
    const int lane = tid & 31, wid = tid >> 5;
    const int kvh = h >> 2;
    const int halfT = qt + 1;
    const int ts = sp * halfT, te = ts + halfT;
    const int wm = (wid & 3) * 32, wn = (wid >> 2) * 32;

    const float* kb = k + kvh * HD_;
    const float* vb = v + kvh * HD_;
    attn_issue_tile(kb + (size_t)(ts * AK) * (KVH_ * HD_), KVa, tid);

    if (tid < 128) {
        const int b = (h * 16 + qt) * 2 * 256;
        const float mA = ml[b + tid],       lA = ml[b + 128 + tid];
        const float mB = ml[b + 256 + tid], lB = ml[b + 384 + tid];
        const float mq = fmaxf(mA, mB);
        mfin[tid] = mq;
        lfin[tid] = lA * acc_expf(mA - mq) + lB * acc_expf(mB - mq);
    }
    for (int i = tid; i < AQ * (HD_ / 4); i += 256) {
        const int qq = i >> 4, d4 = (i & 15) * 4;
        *(float4*)&Qs[qq * QSTR + d4] =
            *(const float4*)(q + (size_t)(q0 + qq) * H_ + h * HD_ + d4);
    }

    float accO[2][4][4] = {};
    for (int t = ts; t < te; t++) {
        const int k0 = t * AK;
        float* bufX = ((t - ts) & 1) ? KVb : KVa;
        float* bufY = ((t - ts) & 1) ? KVa : KVb;
        __syncthreads();
        if (t + 1 < te) { attn_issue_tile(kb + (size_t)(k0 + AK) * (KVH_ * HD_), bufY, tid); cp_wait1(); }
        else            { cp_wait0(); }
        __syncthreads();

        float accS[2][4][4] = {};
        attn_mma_scores(Qs, bufX, accS, lane, wm, wn);
        __syncthreads();
        attn_issue_tile(vb + (size_t)k0 * (KVH_ * HD_), bufX, tid);

        #pragma unroll
        for (int mt = 0; mt < 2; mt++)
            #pragma unroll
            for (int half = 0; half < 2; half++) {
                const int row = wm + mt * 16 + (lane >> 2) + half * 8;
                const float mq = mfin[row];
                const float lq = lfin[row];
                #pragma unroll
                for (int nt = 0; nt < 4; nt++)
                    #pragma unroll
                    for (int e2 = 0; e2 < 2; e2++) {
                        const int col = wn + nt * 8 + (lane & 3) * 2 + e2;
                        float p = 0.f;
                        if (k0 + col <= q0 + row) {
                            const float s = accS[mt][nt][half * 2 + e2] * 0.125f;
                            p = tf32r(__fdiv_rn(acc_expf(s - mq), lq));
                        }
                        SP[row * QSTR + col] = p;
                    }
            }
        cp_wait0();
        __syncthreads();

        #pragma unroll
        for (int ks = 0; ks < 8; ks++) {
            const int kk = ks * 8 + (lane & 3);
            uint32_t a[2][4], b[4][2];
            #pragma unroll
            for (int mt = 0; mt < 2; mt++) {
                const int r = wm + mt * 16 + (lane >> 2);
                a[mt][0] = __float_as_uint(SP[r * QSTR + kk]);
                a[mt][1] = __float_as_uint(SP[(r + 8) * QSTR + kk]);
                a[mt][2] = __float_as_uint(SP[r * QSTR + kk + 4]);
                a[mt][3] = __float_as_uint(SP[(r + 8) * QSTR + kk + 4]);
            }
            #pragma unroll
            for (int nt = 0; nt < 4; nt++) {
                const int d = wn + nt * 8 + (lane >> 2);
                b[nt][0] = __float_as_uint(bufX[kk * QSTR + d]);
                b[nt][1] = __float_as_uint(bufX[(kk + 4) * QSTR + d]);
            }
            #pragma unroll
            for (int mt = 0; mt < 2; mt++)
                #pragma unroll
                for (int nt = 0; nt < 4; nt++)
                    asm volatile(
                        "mma.sync.aligned.m16n8k8.row.col.f32.tf32.tf32.f32 "
                        "{%0,%1,%2,%3}, {%4,%5,%6,%7}, {%8,%9}, {%0,%1,%2,%3};"
                        : "+f"(accO[mt][nt][0]), "+f"(accO[mt][nt][1]),
                          "+f"(accO[mt][nt][2]), "+f"(accO[mt][nt][3])
                        : "r"(a[mt][0]), "r"(a[mt][1]), "r"(a[mt][2]), "r"(a[mt][3]),
                          "r"(b[nt][0]), "r"(b[nt][1]));
        }
    }

    float* od = sp ? o1 : o0;
    #pragma unroll
    for (int mt = 0; mt < 2; mt++)
        #pragma unroll
        for (int half = 0; half < 2; half++) {
            const int row = q0 + wm + mt * 16 + (lane >> 2) + half * 8;
            #pragma unroll
            for (int nt = 0; nt < 4; nt++) {
                const int col = wn + nt * 8 + (lane & 3) * 2;
                float2 r2;
                r2.x = accO[mt][nt][half * 2 + 0];
                r2.y = accO[mt][nt][half * 2 + 1];
                *(float2*)(od + (size_t)row * H_ + h * HD_ + col) = r2;
            }
        }
}

// att = tf32r(att + attP)
__global__ void addO_k(float* __restrict__ a, const float* __restrict__ b)
{
    const size_t i = ((size_t)blockIdx.x * 256 + threadIdx.x) * 4;
    float4 x = *(float4*)(a + i);
    const float4 y = *(const float4*)(b + i);
    x.x = tf32r(x.x + y.x); x.y = tf32r(x.y + y.y);
    x.z = tf32r(x.z + y.z); x.w = tf32r(x.w + y.w);
    *(float4*)(a + i) = x;
}

// ---------------- router ----------------
__global__ void router_k(const float* __restrict__ x, const float* __restrict__ rw,
                         int* __restrict__ cnt, int* __restrict__ list,
                         float* __restrict__ wout)
{
    const int t = blockIdx.x;
    const int tid = threadIdx.x;
    const int e = tid >> 5, lane = tid & 31;
    const float* xr = x + (size_t)t * H_;
    float s = 0.f;
    for (int i = lane; i < H_; i += 32)
        s = __fmaf_rn(tf32r(xr[i]), tf32r(rw[i * E_ + e]), s);
    for (int off = 16; off; off >>= 1) s += __shfl_down_sync(0xffffffffu, s, off);
    __shared__ float logit[E_];
    if (!lane) logit[e] = s;
    __syncthreads();
    if (tid == 0) {
        float mx = logit[0];
        #pragma unroll
        for (int i = 1; i < E_; i++) mx = fmaxf(mx, logit[i]);
        float p[E_];
        #pragma unroll
        for (int i = 0; i < E_; i++) p[i] = acc_expf(logit[i] - mx);
        int i0 = 0;
        #pragma unroll
        for (int i = 1; i < E_; i++) if (p[i] > p[i0]) i0 = i;
        int i1 = (i0 == 0) ? 1 : 0;
        #pragma unroll
        for (int i = 0; i < E_; i++) if (i != i0 && p[i] > p[i1]) i1 = i;
        const float denom = p[i0] + p[i1];
        wout[2 * t + 0] = __fdiv_rn(p[i0], denom);
        wout[2 * t + 1] = __fdiv_rn(p[i1], denom);
        int pos = atomicAdd(&cnt[i0], 1);
        list[i0 * S_ + pos] = 2 * t;
        pos = atomicAdd(&cnt[i1], 1);
        list[i1 * S_ + pos] = 2 * t + 1;
    }
}

// -- final combine: out = (hid + (sp1+sp2)) + (w0*(e0a+e0b) + w1*(e1a+e1b)) ----
__global__ void combine_k(float* __restrict__ out, const float* __restrict__ hid,
                          const float* __restrict__ eoP, const float* __restrict__ spP,
                          const float* __restrict__ w)
{
    const int t = blockIdx.x;
    const float w0 = w[2 * t], w1 = w[2 * t + 1];
    const size_t eoStride = (size_t)(2 * S_) * H_;
    const size_t spStride = (size_t)S_ * H_;
    const float* e0a = eoP + (size_t)(2 * t) * H_;
    const float* e1a = eoP + (size_t)(2 * t + 1) * H_;
    const float* sp1 = spP + (size_t)t * H_;
    for (int i = threadIdx.x; i < H_; i += 256) {
        const float shared2 = __fadd_rn(sp1[i], sp1[spStride + i]);
        const float r0 = __fadd_rn(e0a[i], e0a[eoStride + i]);
        const float r1 = __fadd_rn(e1a[i], e1a[eoStride + i]);
        const float routed = __fmaf_rn(w0, r0, __fmul_rn(w1, r1));
        out[(size_t)t * H_ + i] =
            __fadd_rn(__fadd_rn(hid[(size_t)t * H_ + i], shared2), routed);
    }
}

// ---------------- host launch --------------------------------------------------
extern "C" void kernel_launch(void* const* d_in, const int* in_sizes, int n_in,
                              void* d_out, int out_size)
{
    const float* hs  = (const float*)d_in[0];
    const float* ln1 = (const float*)d_in[1];
    const float* wq  = (const float*)d_in[2];
    const float* wk  = (const float*)d_in[3];
    const float* wv  = (const float*)d_in[4];
    const float* wo  = (const float*)d_in[5];
    const float* ln2 = (const float*)d_in[6];
    const float* sw1 = (const float*)d_in[7];
    const float* sw2 = (const float*)d_in[8];
    const float* ew1 = (const float*)d_in[9];
    const float* ew2 = (const float*)d_in[10];
    const float* rw  = (const float*)d_in[11];
    float* out = (float*)d_out;

    float *x1, *q, *k, *v, *att, *attP, *mlb, *hid, *x2, *hsv, *hcol, *eoP, *spP, *wts;
    int *cnt, *list;
    cudaGetSymbolAddress((void**)&x1,   g_x1);
    cudaGetSymbolAddress((void**)&q,    g_q);
    cudaGetSymbolAddress((void**)&k,    g_k);
    cudaGetSymbolAddress((void**)&v,    g_v);
    cudaGetSymbolAddress((void**)&att,  g_att);
    cudaGetSymbolAddress((void**)&attP, g_attP);
    cudaGetSymbolAddress((void**)&mlb,  g_ml);
    cudaGetSymbolAddress((void**)&hid,  g_hidden);
    cudaGetSymbolAddress((void**)&x2,   g_x2);
    cudaGetSymbolAddress((void**)&hsv,  g_hs);
    cudaGetSymbolAddress((void**)&hcol, g_hcol);
    cudaGetSymbolAddress((void**)&eoP,  g_eoP);
    cudaGetSymbolAddress((void**)&spP,  g_spP);
    cudaGetSymbolAddress((void**)&wts,  g_wts);
    cudaGetSymbolAddress((void**)&cnt,  g_cnt);
    cudaGetSymbolAddress((void**)&list, g_list);

    cudaFuncSetAttribute(mma_gemm_k<0,0,0,1,0,0>, cudaFuncAttributeMaxDynamicSharedMemorySize, SMEM_GEMM);
    cudaFuncSetAttribute(mma_gemm_k<0,0,0,0,0,1>, cudaFuncAttributeMaxDynamicSharedMemorySize, SMEM_GEMM);
    cudaFuncSetAttribute(mma_gemm_k<1,2,1,0,1,0>, cudaFuncAttributeMaxDynamicSharedMemorySize, SMEM_GEMM);
    cudaFuncSetAttribute(mma_gemm_k<0,2,0,0,0,1>, cudaFuncAttributeMaxDynamicSharedMemorySize, SMEM_GEMM);
    cudaFuncSetAttribute(attn_a_k, cudaFuncAttributeMaxDynamicSharedMemorySize, SMEM_ATTN_A);
    cudaFuncSetAttribute(attn_c_k, cudaFuncAttributeMaxDynamicSharedMemorySize, SMEM_ATTN_C);

    // 1. rmsnorm1
    rmsnorm_k<<<S_, 256>>>(hs, ln1, x1);
    // 2. fused QKV projection
    mma_gemm_k<0,0,0,1,0,0><<<dim3(12, S_ / BM), 256, SMEM_GEMM>>>(
        x1, wq, q, nullptr, nullptr, nullptr, wk, wv, k, v, H_, H_);
    // 3. RoPE (+ zero expert counters)
    rope_k<<<(S_ * (NH_ + KVH_) * 32) / 256, 256>>>(q, k, cnt);
    // 4. attention: split-K two-pass
    attn_a_k<<<dim3(32, NH_), 256, SMEM_ATTN_A>>>(q, k, mlb);
    attn_c_k<<<dim3(32, NH_), 256, SMEM_ATTN_C>>>(q, k, v, mlb, att, attP);
    addO_k<<<(S_ * H_) / 1024, 256>>>(att, attP);
    // 5. O-proj, 2-way K split into partials p1=x1, p2=attP
    mma_gemm_k<0,0,0,0,0,1><<<dim3(H_ / BN, S_ / BM, 2), 256, SMEM_GEMM>>>(
        att, wo, x1, nullptr, nullptr, nullptr, nullptr, nullptr, attP, nullptr, H_, H_);
    // 6. rmsnorm2 fused with residual+partial sum
    rmsnorm_add_k<<<S_, 256>>>(hs, x1, attP, ln2, hid, x2);
    // 7. router
    router_k<<<S_, 256>>>(x2, rw, cnt, list, wts);
    // 8. fused shared-MLP-1 + expert-1
    mma_gemm_k<1,2,1,0,1,0><<<dim3(I_ / BN, S_ / BM, E_ + 1), 256, SMEM_GEMM>>>(
        x2, ew1, hcol, nullptr, list, cnt, sw1, x2, hsv, nullptr, I_, H_);
    // 9. fused shared-MLP-2 + expert-2, 2-way K split into partial buffers
    mma_gemm_k<0,2,0,0,0,1><<<dim3(H_ / BN, S_ / BM, 2 * (E_ + 1)), 256, SMEM_GEMM>>>(
        hcol, ew2, eoP, nullptr, list, cnt, sw2, hsv, spP, nullptr, H_, I_);
    // 10. combine everything into out
    combine_k<<<S_, 256>>>(out, hid, eoP, spP, wts);
}